// round 4
// baseline (speedup 1.0000x reference)
#include <cuda_runtime.h>
#include <math.h>
#include <cstdint>
#include <cstddef>

// Problem constants
static constexpr int NN   = 32000;     // nodes
static constexpr int NB   = 16;        // graphs
static constexpr int NPG  = 2000;      // nodes per graph
static constexpr int KK   = 1600;      // clusters total
static constexpr int KPG  = 100;       // clusters per graph
static constexpr int DD   = 128;       // feature dim
static constexpr int EE   = 512000;    // edges
static constexpr int ADJ_ELEMS = KK * KK;

// ---------------- scratch (__device__ globals) ------------------------------
__device__ float g_x[(size_t)NN * DD];
__device__ float g_t1[(size_t)NN * DD];
__device__ float g_feat[(size_t)NN * DD];
__device__ float g_x2[(size_t)NN * KK];
__device__ float g_logits[(size_t)NN * KPG];
__device__ float g_assign[(size_t)NN * KPG];
__device__ float g_tmp[(size_t)NN * KPG];
__device__ int   g_degi[NN];
__device__ int   g_base[NN];
__device__ int   g_cursor[NN];
__device__ int   g_nbr[EE];

// ---------------- packed f32x2 helpers --------------------------------------
__device__ __forceinline__ unsigned long long bcast2(float a) {
    unsigned long long r;
    asm("mov.b64 %0, {%1, %1};" : "=l"(r) : "r"(__float_as_uint(a)));
    return r;
}
__device__ __forceinline__ void fma2(unsigned long long& acc,
                                     unsigned long long a, unsigned long long b) {
    asm("fma.rn.f32x2 %0, %1, %2, %0;" : "+l"(acc) : "l"(a), "l"(b));
}
__device__ __forceinline__ void unpack2(unsigned long long v, float& lo, float& hi) {
    uint32_t l, h;
    asm("mov.b64 {%0, %1}, %2;" : "=r"(l), "=r"(h) : "l"(v));
    lo = __uint_as_float(l);
    hi = __uint_as_float(h);
}

// ---------------- zero helpers ----------------------------------------------
__global__ void zero_f(float* __restrict__ p, size_t n) {
    size_t i = (size_t)blockIdx.x * blockDim.x + threadIdx.x;
    size_t st = (size_t)gridDim.x * blockDim.x;
    for (; i < n; i += st) p[i] = 0.f;
}
__global__ void zero_i(int* __restrict__ p, size_t n) {
    size_t i = (size_t)blockIdx.x * blockDim.x + threadIdx.x;
    size_t st = (size_t)gridDim.x * blockDim.x;
    for (; i < n; i += st) p[i] = 0;
}

// ---------------- CSR build --------------------------------------------------
__global__ void count_deg_kernel(const int* __restrict__ dst) {
    int e = blockIdx.x * blockDim.x + threadIdx.x;
    if (e < EE) atomicAdd(&g_degi[dst[e]], 1);
}

// one-pass block scan: 1024 threads, 32 contiguous nodes each
__global__ void scan_kernel() {
    __shared__ int warpsum[32];
    const int t = threadIdx.x;
    const int lane = t & 31, w = t >> 5;
    const int base = t * 32;
    int sum = 0;
    for (int i = 0; i < 32; i++) {
        int idx = base + i;
        if (idx < NN) sum += g_degi[idx];
    }
    int v = sum;
#pragma unroll
    for (int off = 1; off < 32; off <<= 1) {
        int n = __shfl_up_sync(0xFFFFFFFFu, v, off);
        if (lane >= off) v += n;
    }
    if (lane == 31) warpsum[w] = v;
    __syncthreads();
    if (w == 0) {
        int x = warpsum[lane];
        int y = x;
#pragma unroll
        for (int off = 1; off < 32; off <<= 1) {
            int n = __shfl_up_sync(0xFFFFFFFFu, y, off);
            if (lane >= off) y += n;
        }
        warpsum[lane] = y - x;   // exclusive
    }
    __syncthreads();
    int run = v - sum + warpsum[w];
    for (int i = 0; i < 32; i++) {
        int idx = base + i;
        if (idx < NN) {
            g_base[idx]   = run;
            g_cursor[idx] = run;
            run += g_degi[idx];
        }
    }
}

__global__ void fill_csr_kernel(const int* __restrict__ src,
                                const int* __restrict__ dst) {
    int e = blockIdx.x * blockDim.x + threadIdx.x;
    if (e >= EE) return;
    int p = atomicAdd(&g_cursor[dst[e]], 1);
    g_nbr[p] = src[e];
}

// ---------------- gather: x = h + mean_{s in N(n)} h[s] ---------------------
__global__ void gather_x_kernel(const float* __restrict__ h) {
    int n = (blockIdx.x * blockDim.x + threadIdx.x) >> 5;
    int lane = threadIdx.x & 31;
    if (n >= NN) return;
    int b = g_base[n];
    int dg = g_degi[n];
    float a0 = 0.f, a1 = 0.f, a2 = 0.f, a3 = 0.f;
    for (int j = 0; j < dg; j++) {
        const float* hr = h + (size_t)g_nbr[b + j] * DD;
        a0 += hr[lane];
        a1 += hr[lane + 32];
        a2 += hr[lane + 64];
        a3 += hr[lane + 96];
    }
    float inv = 1.f / fmaxf((float)dg, 1.f);
    const float* hn = h + (size_t)n * DD;
    float* xo = g_x + (size_t)n * DD;
    xo[lane]      = hn[lane]      + a0 * inv;
    xo[lane + 32] = hn[lane + 32] + a1 * inv;
    xo[lane + 64] = hn[lane + 64] + a2 * inv;
    xo[lane + 96] = hn[lane + 96] + a3 * inv;
}

// ---------------- gather: tmp[n] = sum_{s in N(n)} assign[s] ----------------
__global__ void gather_tmp_kernel() {
    int n = (blockIdx.x * blockDim.x + threadIdx.x) >> 5;
    int lane = threadIdx.x & 31;
    if (n >= NN) return;
    int b = g_base[n];
    int dg = g_degi[n];
    float a0 = 0.f, a1 = 0.f, a2 = 0.f, a3 = 0.f;
    for (int j = 0; j < dg; j++) {
        const float* ar = g_assign + (size_t)g_nbr[b + j] * KPG;
        a0 += ar[lane];
        a1 += ar[lane + 32];
        a2 += ar[lane + 64];
        if (lane < 4) a3 += ar[lane + 96];
    }
    float* tp = g_tmp + (size_t)n * KPG;
    tp[lane]      = a0;
    tp[lane + 32] = a1;
    tp[lane + 64] = a2;
    if (lane < 4) tp[lane + 96] = a3;
}

// ---------------- SGEMM: C = relu(A@B + bias), packed f32x2 math ------------
// 128x128 tile, BK=8, 128 threads, 16x8 per thread, double-buffered smem.
// Inner product uses fma.rn.f32x2 (2 fp32 FMA per instruction).
__global__ __launch_bounds__(128)
void sgemm_kernel(const float* __restrict__ A, const float* __restrict__ B,
                  const float* __restrict__ bias, float* __restrict__ C,
                  int M, int N, int K, int lda, int ldb, int ldc,
                  long zsA, long zsB, long zsC, long zsBias) {
    A    += (size_t)blockIdx.z * zsA;
    B    += (size_t)blockIdx.z * zsB;
    C    += (size_t)blockIdx.z * zsC;
    bias += (size_t)blockIdx.z * zsBias;

    __shared__ float As[2][8][128];
    __shared__ float Bs[2][8][128];

    const int tid = threadIdx.x;
    const int bm = blockIdx.x * 128;
    const int bn = blockIdx.y * 128;
    const int rowBase = (tid >> 4) * 16;
    const int colBase = (tid & 15) * 8;

    const int aRow  = bm + tid;          // one A row per thread
    const int bRow  = tid >> 4;          // 0..7
    const int bColL = (tid & 15) * 8;    // 0..120
    const int bCol  = bn + bColL;
    const float* Aptr = A + (size_t)aRow * lda;
    const bool aOk = (aRow < M);
    const bool bOk0 = (bCol + 3 < N);
    const bool bOk1 = (bCol + 7 < N);

    float4 pa0, pa1, pb0, pb1;
    const float4 z4 = make_float4(0.f, 0.f, 0.f, 0.f);

    // prefetch tile 0
    {
        pa0 = aOk ? *(const float4*)(Aptr + 0) : z4;
        pa1 = aOk ? *(const float4*)(Aptr + 4) : z4;
        const float* bp = B + (size_t)bRow * ldb + bCol;
        pb0 = bOk0 ? *(const float4*)(bp) : z4;
        pb1 = bOk1 ? *(const float4*)(bp + 4) : z4;
    }
    As[0][0][tid] = pa0.x; As[0][1][tid] = pa0.y; As[0][2][tid] = pa0.z; As[0][3][tid] = pa0.w;
    As[0][4][tid] = pa1.x; As[0][5][tid] = pa1.y; As[0][6][tid] = pa1.z; As[0][7][tid] = pa1.w;
    *(float4*)&Bs[0][bRow][bColL]     = pb0;
    *(float4*)&Bs[0][bRow][bColL + 4] = pb1;
    __syncthreads();

    unsigned long long acc[16][4];
#pragma unroll
    for (int i = 0; i < 16; i++)
#pragma unroll
        for (int j = 0; j < 4; j++) acc[i][j] = 0ull;

    const int nT = K >> 3;
    for (int t = 0; t < nT; t++) {
        const int cur = t & 1;
        if (t + 1 < nT) {
            const int k0 = (t + 1) * 8;
            pa0 = aOk ? *(const float4*)(Aptr + k0)     : z4;
            pa1 = aOk ? *(const float4*)(Aptr + k0 + 4) : z4;
            const float* bp = B + (size_t)(k0 + bRow) * ldb + bCol;
            pb0 = bOk0 ? *(const float4*)(bp)     : z4;
            pb1 = bOk1 ? *(const float4*)(bp + 4) : z4;
        }
#pragma unroll
        for (int k = 0; k < 8; k++) {
            float a[16];
            *(float4*)&a[0]  = *(const float4*)&As[cur][k][rowBase];
            *(float4*)&a[4]  = *(const float4*)&As[cur][k][rowBase + 4];
            *(float4*)&a[8]  = *(const float4*)&As[cur][k][rowBase + 8];
            *(float4*)&a[12] = *(const float4*)&As[cur][k][rowBase + 12];
            unsigned long long b2[4];
            {
                const ulonglong2 t0 = *(const ulonglong2*)&Bs[cur][k][colBase];
                const ulonglong2 t1 = *(const ulonglong2*)&Bs[cur][k][colBase + 4];
                b2[0] = t0.x; b2[1] = t0.y; b2[2] = t1.x; b2[3] = t1.y;
            }
#pragma unroll
            for (int i = 0; i < 16; i++) {
                const unsigned long long ap = bcast2(a[i]);
#pragma unroll
                for (int j = 0; j < 4; j++) fma2(acc[i][j], ap, b2[j]);
            }
        }
        if (t + 1 < nT) {
            const int nxt = (t + 1) & 1;
            As[nxt][0][tid] = pa0.x; As[nxt][1][tid] = pa0.y; As[nxt][2][tid] = pa0.z; As[nxt][3][tid] = pa0.w;
            As[nxt][4][tid] = pa1.x; As[nxt][5][tid] = pa1.y; As[nxt][6][tid] = pa1.z; As[nxt][7][tid] = pa1.w;
            *(float4*)&Bs[nxt][bRow][bColL]     = pb0;
            *(float4*)&Bs[nxt][bRow][bColL + 4] = pb1;
        }
        __syncthreads();
    }

#pragma unroll
    for (int i = 0; i < 16; i++) {
        int r = bm + rowBase + i;
        if (r >= M) continue;
        float* cp = C + (size_t)r * ldc + bn + colBase;
#pragma unroll
        for (int j = 0; j < 4; j++) {
            float lo, hi;
            unpack2(acc[i][j], lo, hi);
            int c0 = bn + colBase + 2 * j;
            if (c0 < N)     cp[2 * j]     = fmaxf(lo + bias[c0], 0.f);
            if (c0 + 1 < N) cp[2 * j + 1] = fmaxf(hi + bias[c0 + 1], 0.f);
        }
    }
}

// ---------------- per-node softmax over 100 compact logits ------------------
__global__ void softmax_kernel() {
    int node = (blockIdx.x * blockDim.x + threadIdx.x) >> 5;
    int lane = threadIdx.x & 31;
    if (node >= NN) return;
    const float* lp = g_logits + (size_t)node * KPG;
    float v[4];
    float mx = -1e30f;
#pragma unroll
    for (int i = 0; i < 4; i++) {
        int c = lane + 32 * i;
        v[i] = (c < KPG) ? lp[c] : -1e30f;
        mx = fmaxf(mx, v[i]);
    }
#pragma unroll
    for (int o = 16; o; o >>= 1) mx = fmaxf(mx, __shfl_xor_sync(0xFFFFFFFFu, mx, o));
    float sum = 0.f;
#pragma unroll
    for (int i = 0; i < 4; i++) {
        int c = lane + 32 * i;
        v[i] = (c < KPG) ? expf(v[i] - mx) : 0.f;
        sum += v[i];
    }
#pragma unroll
    for (int o = 16; o; o >>= 1) sum += __shfl_xor_sync(0xFFFFFFFFu, sum, o);
    float inv = 1.f / sum;
    float* ap = g_assign + (size_t)node * KPG;
#pragma unroll
    for (int i = 0; i < 4; i++) {
        int c = lane + 32 * i;
        if (c < KPG) ap[c] = v[i] * inv;
    }
}

// ---------------- h_pool: per graph, assign_b^T [2000x100] @ feat_b [2000x128]
__global__ __launch_bounds__(256)
void hpool_kernel(float* __restrict__ out) {   // out = d_out + ADJ_ELEMS
    const int g = blockIdx.y;
    const int split = blockIdx.x;      // 8 splits
    const int kbeg = split * (NPG / 8);
    const int kend = kbeg + (NPG / 8);
    const float* A = g_assign + (size_t)g * NPG * KPG;
    const float* F = g_feat + (size_t)g * NPG * DD;

    __shared__ float As[8][KPG];
    __shared__ float Fs[8][DD];
    const int tx = threadIdx.x & 15;
    const int ty = threadIdx.x >> 4;

    float acc[7][8];
#pragma unroll
    for (int i = 0; i < 7; i++)
#pragma unroll
        for (int j = 0; j < 8; j++) acc[i][j] = 0.f;

    for (int k0 = kbeg; k0 < kend; k0 += 8) {
        int kc = min(8, kend - k0);
        for (int idx = threadIdx.x; idx < 8 * KPG; idx += 256) {
            int r = idx / KPG, c = idx % KPG;
            As[r][c] = (r < kc) ? A[(size_t)(k0 + r) * KPG + c] : 0.f;
        }
        for (int idx = threadIdx.x; idx < 8 * DD; idx += 256) {
            int r = idx >> 7, c = idx & 127;
            Fs[r][c] = (r < kc) ? F[(size_t)(k0 + r) * DD + c] : 0.f;
        }
        __syncthreads();
#pragma unroll
        for (int k = 0; k < 8; k++) {
            float a[7], f[8];
#pragma unroll
            for (int i = 0; i < 7; i++) {
                int c = ty + 16 * i;
                a[i] = (c < KPG) ? As[k][c] : 0.f;
            }
#pragma unroll
            for (int j = 0; j < 8; j++) f[j] = Fs[k][tx + 16 * j];
#pragma unroll
            for (int i = 0; i < 7; i++)
#pragma unroll
                for (int j = 0; j < 8; j++) acc[i][j] += a[i] * f[j];
        }
        __syncthreads();
    }
#pragma unroll
    for (int i = 0; i < 7; i++) {
        int c = ty + 16 * i;
        if (c >= KPG) continue;
#pragma unroll
        for (int j = 0; j < 8; j++) {
            int d = tx + 16 * j;
            atomicAdd(&out[(size_t)(g * KPG + c) * DD + d], acc[i][j]);
        }
    }
}

// ---------------- adj: per graph, assign_b^T [2000x100] @ tmp_b [2000x100] --
__global__ __launch_bounds__(256)
void adj_kernel(float* __restrict__ out) {   // adj part of d_out (pre-zeroed)
    const int g = blockIdx.y;
    const int split = blockIdx.x;      // 8 splits
    const int kbeg = split * (NPG / 8);
    const int kend = kbeg + (NPG / 8);
    const float* A = g_assign + (size_t)g * NPG * KPG;
    const float* T = g_tmp + (size_t)g * NPG * KPG;

    __shared__ float As[8][KPG];
    __shared__ float Ts[8][KPG];
    const int tx = threadIdx.x & 15;
    const int ty = threadIdx.x >> 4;

    float acc[7][7];
#pragma unroll
    for (int i = 0; i < 7; i++)
#pragma unroll
        for (int j = 0; j < 7; j++) acc[i][j] = 0.f;

    for (int k0 = kbeg; k0 < kend; k0 += 8) {
        int kc = min(8, kend - k0);
        for (int idx = threadIdx.x; idx < 8 * KPG; idx += 256) {
            int r = idx / KPG, c = idx % KPG;
            As[r][c] = (r < kc) ? A[(size_t)(k0 + r) * KPG + c] : 0.f;
            Ts[r][c] = (r < kc) ? T[(size_t)(k0 + r) * KPG + c] : 0.f;
        }
        __syncthreads();
#pragma unroll
        for (int k = 0; k < 8; k++) {
            float a[7], b[7];
#pragma unroll
            for (int i = 0; i < 7; i++) {
                int c = ty + 16 * i;
                a[i] = (c < KPG) ? As[k][c] : 0.f;
            }
#pragma unroll
            for (int j = 0; j < 7; j++) {
                int c = tx + 16 * j;
                b[j] = (c < KPG) ? Ts[k][c] : 0.f;
            }
#pragma unroll
            for (int i = 0; i < 7; i++)
#pragma unroll
                for (int j = 0; j < 7; j++) acc[i][j] += a[i] * b[j];
        }
        __syncthreads();
    }
#pragma unroll
    for (int i = 0; i < 7; i++) {
        int c1 = ty + 16 * i;
        if (c1 >= KPG) continue;
#pragma unroll
        for (int j = 0; j < 7; j++) {
            int c2 = tx + 16 * j;
            if (c2 >= KPG) continue;
            atomicAdd(&out[(size_t)(g * KPG + c1) * KK + (g * KPG + c2)], acc[i][j]);
        }
    }
}

// ---------------- launch ----------------------------------------------------
extern "C" void kernel_launch(void* const* d_in, const int* in_sizes, int n_in,
                              void* d_out, int out_size) {
    const float* h   = (const float*)d_in[0];
    const int*   src = (const int*)d_in[1];
    const int*   dst = (const int*)d_in[2];
    const float* W1f = (const float*)d_in[3];
    const float* b1f = (const float*)d_in[4];
    const float* W2f = (const float*)d_in[5];
    const float* b2f = (const float*)d_in[6];
    const float* W1p = (const float*)d_in[7];
    const float* b1p = (const float*)d_in[8];
    const float* W2p = (const float*)d_in[9];
    const float* b2p = (const float*)d_in[10];
    float* out = (float*)d_out;

    float *x, *t1, *feat, *x2, *logits;
    int* degi;
    cudaGetSymbolAddress((void**)&x,      g_x);
    cudaGetSymbolAddress((void**)&t1,     g_t1);
    cudaGetSymbolAddress((void**)&feat,   g_feat);
    cudaGetSymbolAddress((void**)&x2,     g_x2);
    cudaGetSymbolAddress((void**)&logits, g_logits);
    cudaGetSymbolAddress((void**)&degi,   g_degi);

    // zero output + degree counters
    zero_f<<<1024, 256>>>(out, (size_t)out_size);
    zero_i<<<128, 256>>>(degi, (size_t)NN);

    // CSR build (dst-indexed neighbor lists)
    count_deg_kernel<<<(EE + 255) / 256, 256>>>(dst);
    scan_kernel<<<1, 1024>>>();
    fill_csr_kernel<<<(EE + 255) / 256, 256>>>(src, dst);

    // x = h + mean-aggregated neighbors (shared by both GIN branches)
    gather_x_kernel<<<(NN * 32 + 255) / 256, 256>>>(h);

    // feat branch: two 32000x128x128 GEMMs
    sgemm_kernel<<<dim3(250, 1, 1), 128>>>(x, W1f, b1f, t1,
                                           NN, DD, DD, DD, DD, DD, 0, 0, 0, 0);
    sgemm_kernel<<<dim3(250, 1, 1), 128>>>(t1, W2f, b2f, feat,
                                           NN, DD, DD, DD, DD, DD, 0, 0, 0, 0);

    // pool branch layer 1: 32000 x 1600 x 128
    sgemm_kernel<<<dim3(250, 13, 1), 128>>>(x, W1p, b1p, x2,
                                            NN, KK, DD, DD, KK, KK, 0, 0, 0, 0);

    // pool branch layer 2: per graph [2000,1600] @ [1600,100] -> compact logits
    sgemm_kernel<<<dim3(16, 1, NB), 128>>>(x2, W2p, b2p, logits,
                                           NPG, KPG, KK, KK, KK, KPG,
                                           (long)NPG * KK, (long)KPG,
                                           (long)NPG * KPG, (long)KPG);

    // masked softmax (compact in-block)
    softmax_kernel<<<(NN * 32 + 255) / 256, 256>>>();

    // tmp = gather-sum of assign over incoming edges (no atomics)
    gather_tmp_kernel<<<(NN * 32 + 255) / 256, 256>>>();

    // h_pool and adj (block-diagonal), atomic split-K into pre-zeroed d_out
    hpool_kernel<<<dim3(8, NB), 256>>>(out + ADJ_ELEMS);
    adj_kernel<<<dim3(8, NB), 256>>>(out);
}

// round 5
// speedup vs baseline: 1.1425x; 1.1425x over previous
#include <cuda_runtime.h>
#include <math.h>
#include <cstdint>
#include <cstddef>

// Problem constants
static constexpr int NN   = 32000;     // nodes
static constexpr int NB   = 16;        // graphs
static constexpr int NPG  = 2000;      // nodes per graph
static constexpr int KK   = 1600;      // clusters total
static constexpr int KPG  = 100;       // clusters per graph
static constexpr int DD   = 128;       // feature dim
static constexpr int EE   = 512000;    // edges
static constexpr int ADJ_ELEMS = KK * KK;
static constexpr int CAP  = 96;        // neighbor bucket capacity

// ---------------- scratch (__device__ globals) ------------------------------
__device__ float g_x[(size_t)NN * DD];
__device__ float g_t1[(size_t)NN * DD];
__device__ float g_feat[(size_t)NN * DD];
__device__ float g_x2[(size_t)NN * KK];
__device__ float g_logits[(size_t)NN * KPG];
__device__ float g_assign[(size_t)NN * KPG];
__device__ float g_tmp[(size_t)NN * KPG];
__device__ int   g_degi[NN];
__device__ int   g_nbr[(size_t)NN * CAP];

// ---------------- helpers ----------------------------------------------------
__device__ __forceinline__ float tf32_rna(float a) {
    uint32_t r;
    asm("cvt.rna.tf32.f32 %0, %1;" : "=r"(r) : "f"(a));
    return __uint_as_float(r);
}
__device__ __forceinline__ void mma_tf32(float* c, const uint32_t* a,
                                         uint32_t b0, uint32_t b1) {
    asm volatile(
        "mma.sync.aligned.m16n8k8.row.col.f32.tf32.tf32.f32 "
        "{%0,%1,%2,%3}, {%4,%5,%6,%7}, {%8,%9}, {%0,%1,%2,%3};"
        : "+f"(c[0]), "+f"(c[1]), "+f"(c[2]), "+f"(c[3])
        : "r"(a[0]), "r"(a[1]), "r"(a[2]), "r"(a[3]), "r"(b0), "r"(b1));
}

// ---------------- zero helpers ----------------------------------------------
__global__ void zero_f(float* __restrict__ p, size_t n) {
    size_t i = (size_t)blockIdx.x * blockDim.x + threadIdx.x;
    size_t st = (size_t)gridDim.x * blockDim.x;
    for (; i < n; i += st) p[i] = 0.f;
}
__global__ void zero_i(int* __restrict__ p, size_t n) {
    size_t i = (size_t)blockIdx.x * blockDim.x + threadIdx.x;
    size_t st = (size_t)gridDim.x * blockDim.x;
    for (; i < n; i += st) p[i] = 0;
}

// ---------------- bucket fill: per-dst neighbor lists ------------------------
__global__ void fill_bucket_kernel(const int* __restrict__ src,
                                   const int* __restrict__ dst) {
    int e = blockIdx.x * blockDim.x + threadIdx.x;
    if (e >= EE) return;
    int d = dst[e];
    int p = atomicAdd(&g_degi[d], 1);
    if (p < CAP) g_nbr[(size_t)d * CAP + p] = src[e];
}

// ---------------- gather: x = h + mean_{s in N(n)} h[s] ---------------------
__global__ void gather_x_kernel(const float* __restrict__ h) {
    int n = (blockIdx.x * blockDim.x + threadIdx.x) >> 5;
    int lane = threadIdx.x & 31;
    if (n >= NN) return;
    int dg = min(g_degi[n], CAP);
    const int* nb = g_nbr + (size_t)n * CAP;
    float a0 = 0.f, a1 = 0.f, a2 = 0.f, a3 = 0.f;
    for (int j = 0; j < dg; j++) {
        const float* hr = h + (size_t)nb[j] * DD;
        a0 += hr[lane];
        a1 += hr[lane + 32];
        a2 += hr[lane + 64];
        a3 += hr[lane + 96];
    }
    float inv = 1.f / fmaxf((float)dg, 1.f);
    const float* hn = h + (size_t)n * DD;
    float* xo = g_x + (size_t)n * DD;
    xo[lane]      = hn[lane]      + a0 * inv;
    xo[lane + 32] = hn[lane + 32] + a1 * inv;
    xo[lane + 64] = hn[lane + 64] + a2 * inv;
    xo[lane + 96] = hn[lane + 96] + a3 * inv;
}

// ---------------- gather: tmp[n] = sum_{s in N(n)} assign[s] ----------------
__global__ void gather_tmp_kernel() {
    int n = (blockIdx.x * blockDim.x + threadIdx.x) >> 5;
    int lane = threadIdx.x & 31;
    if (n >= NN) return;
    int dg = min(g_degi[n], CAP);
    const int* nb = g_nbr + (size_t)n * CAP;
    float a0 = 0.f, a1 = 0.f, a2 = 0.f, a3 = 0.f;
    for (int j = 0; j < dg; j++) {
        const float* ar = g_assign + (size_t)nb[j] * KPG;
        a0 += ar[lane];
        a1 += ar[lane + 32];
        a2 += ar[lane + 64];
        if (lane < 4) a3 += ar[lane + 96];
    }
    float* tp = g_tmp + (size_t)n * KPG;
    tp[lane]      = a0;
    tp[lane + 32] = a1;
    tp[lane + 64] = a2;
    if (lane < 4) tp[lane + 96] = a3;
}

// ---------------- tensor-core tf32 split GEMM: C = relu(A@B + bias) ---------
// A [M,K] (lda), B [K,N] (ldb), C [M,N] (ldc). 128x128 CTA tile, BK=32,
// 256 threads = 8 warps (4 in M x 2 in N), warp tile 32x64, mma m16n8k8.
// 2-term tf32 split: hi*hi + hi*lo + lo*hi (fp32 accumulate).
static constexpr int TCK = 32;                 // BK
static constexpr int TCS = 132;                // smem row stride (floats)
static constexpr int TC_SMEM_BYTES = 4 * TCK * TCS * 4;   // 67584

__global__ __launch_bounds__(256, 2)
void mma_gemm(const float* __restrict__ A, const float* __restrict__ B,
              const float* __restrict__ bias, float* __restrict__ C,
              int M, int N, int K, int lda, int ldb, int ldc,
              long zsA, long zsB, long zsC, long zsBias) {
    extern __shared__ float sm[];
    float* Ah = sm;
    float* Al = Ah + TCK * TCS;
    float* Bh = Al + TCK * TCS;
    float* Bl = Bh + TCK * TCS;

    A    += (size_t)blockIdx.z * zsA;
    B    += (size_t)blockIdx.z * zsB;
    C    += (size_t)blockIdx.z * zsC;
    bias += (size_t)blockIdx.z * zsBias;

    const int tid  = threadIdx.x;
    const int wid  = tid >> 5;
    const int lane = tid & 31;
    const int wm   = wid & 3;          // warp row (M)
    const int wn   = wid >> 2;         // warp col (N)
    const int g    = lane >> 2;        // groupID 0..7
    const int tig  = lane & 3;         // thread-in-group
    const int bm   = blockIdx.x * 128;
    const int bn   = blockIdx.y * 128;

    // A loader: thread -> (row, 16-wide k chunk)
    const int am   = tid >> 1;             // 0..127
    const int akq  = (tid & 1) * 16;       // 0 or 16
    const int arow = min(bm + am, M - 1);
    const float* Aptr = A + (size_t)arow * lda + akq;
    // B loader: thread -> (k row, 16-wide n chunk)
    const int bk   = tid >> 3;             // 0..31
    const int bnq  = (tid & 7) * 16;

    float c[2][8][4];
#pragma unroll
    for (int mt = 0; mt < 2; mt++)
#pragma unroll
        for (int nt = 0; nt < 8; nt++)
#pragma unroll
            for (int q = 0; q < 4; q++) c[mt][nt][q] = 0.f;

    for (int k0 = 0; k0 < K; k0 += TCK) {
        // ---- A tile: As[k][m], split hi/lo
#pragma unroll
        for (int v = 0; v < 4; v++) {
            float4 va = *(const float4*)(Aptr + k0 + v * 4);
#pragma unroll
            for (int e = 0; e < 4; e++) {
                float f = (&va.x)[e];
                float hi = tf32_rna(f);
                float lo = tf32_rna(f - hi);
                int kk = akq + v * 4 + e;
                Ah[kk * TCS + am] = hi;
                Al[kk * TCS + am] = lo;
            }
        }
        // ---- B tile: Bs[k][n], split hi/lo (column-clamped for N<128)
        {
            const float* Bp = B + (size_t)(k0 + bk) * ldb;
            if (bn + bnq + 15 < N) {
#pragma unroll
                for (int v = 0; v < 4; v++) {
                    float4 vb = *(const float4*)(Bp + bn + bnq + v * 4);
#pragma unroll
                    for (int e = 0; e < 4; e++) {
                        float f = (&vb.x)[e];
                        float hi = tf32_rna(f);
                        float lo = tf32_rna(f - hi);
                        int nn = bnq + v * 4 + e;
                        Bh[bk * TCS + nn] = hi;
                        Bl[bk * TCS + nn] = lo;
                    }
                }
            } else {
#pragma unroll
                for (int i = 0; i < 16; i++) {
                    int col = bn + bnq + i;
                    float f = Bp[min(col, N - 1)];
                    if (col >= N) f = 0.f;
                    float hi = tf32_rna(f);
                    float lo = tf32_rna(f - hi);
                    Bh[bk * TCS + bnq + i] = hi;
                    Bl[bk * TCS + bnq + i] = lo;
                }
            }
        }
        __syncthreads();

#pragma unroll
        for (int ks = 0; ks < 4; ks++) {
            const int kb = ks * 8 + tig;
            uint32_t ah[2][4], al[2][4];
#pragma unroll
            for (int mt = 0; mt < 2; mt++) {
                const int mr = wm * 32 + mt * 16 + g;
                ah[mt][0] = __float_as_uint(Ah[kb * TCS + mr]);
                ah[mt][1] = __float_as_uint(Ah[kb * TCS + mr + 8]);
                ah[mt][2] = __float_as_uint(Ah[(kb + 4) * TCS + mr]);
                ah[mt][3] = __float_as_uint(Ah[(kb + 4) * TCS + mr + 8]);
                al[mt][0] = __float_as_uint(Al[kb * TCS + mr]);
                al[mt][1] = __float_as_uint(Al[kb * TCS + mr + 8]);
                al[mt][2] = __float_as_uint(Al[(kb + 4) * TCS + mr]);
                al[mt][3] = __float_as_uint(Al[(kb + 4) * TCS + mr + 8]);
            }
#pragma unroll
            for (int nt = 0; nt < 8; nt++) {
                const int nc = wn * 64 + nt * 8 + g;
                uint32_t bh0 = __float_as_uint(Bh[kb * TCS + nc]);
                uint32_t bh1 = __float_as_uint(Bh[(kb + 4) * TCS + nc]);
                uint32_t bl0 = __float_as_uint(Bl[kb * TCS + nc]);
                uint32_t bl1 = __float_as_uint(Bl[(kb + 4) * TCS + nc]);
#pragma unroll
                for (int mt = 0; mt < 2; mt++) {
                    mma_tf32(c[mt][nt], ah[mt], bh0, bh1);
                    mma_tf32(c[mt][nt], ah[mt], bl0, bl1);
                    mma_tf32(c[mt][nt], al[mt], bh0, bh1);
                }
            }
        }
        __syncthreads();
    }

    // ---- epilogue: bias + relu
#pragma unroll
    for (int mt = 0; mt < 2; mt++) {
        const int r0 = bm + wm * 32 + mt * 16 + g;
        const int r1 = r0 + 8;
#pragma unroll
        for (int nt = 0; nt < 8; nt++) {
            const int col = bn + wn * 64 + nt * 8 + 2 * tig;
            if (col >= N) continue;
            const bool pair = (col + 1 < N);
            const float b0 = bias[col];
            const float b1 = pair ? bias[col + 1] : 0.f;
            if (r0 < M) {
                float v0 = fmaxf(c[mt][nt][0] + b0, 0.f);
                float v1 = fmaxf(c[mt][nt][1] + b1, 0.f);
                if (pair) *(float2*)(C + (size_t)r0 * ldc + col) = make_float2(v0, v1);
                else      C[(size_t)r0 * ldc + col] = v0;
            }
            if (r1 < M) {
                float v2 = fmaxf(c[mt][nt][2] + b0, 0.f);
                float v3 = fmaxf(c[mt][nt][3] + b1, 0.f);
                if (pair) *(float2*)(C + (size_t)r1 * ldc + col) = make_float2(v2, v3);
                else      C[(size_t)r1 * ldc + col] = v2;
            }
        }
    }
}

// ---------------- per-node softmax over 100 compact logits ------------------
__global__ void softmax_kernel() {
    int node = (blockIdx.x * blockDim.x + threadIdx.x) >> 5;
    int lane = threadIdx.x & 31;
    if (node >= NN) return;
    const float* lp = g_logits + (size_t)node * KPG;
    float v[4];
    float mx = -1e30f;
#pragma unroll
    for (int i = 0; i < 4; i++) {
        int c = lane + 32 * i;
        v[i] = (c < KPG) ? lp[c] : -1e30f;
        mx = fmaxf(mx, v[i]);
    }
#pragma unroll
    for (int o = 16; o; o >>= 1) mx = fmaxf(mx, __shfl_xor_sync(0xFFFFFFFFu, mx, o));
    float sum = 0.f;
#pragma unroll
    for (int i = 0; i < 4; i++) {
        int c = lane + 32 * i;
        v[i] = (c < KPG) ? expf(v[i] - mx) : 0.f;
        sum += v[i];
    }
#pragma unroll
    for (int o = 16; o; o >>= 1) sum += __shfl_xor_sync(0xFFFFFFFFu, sum, o);
    float inv = 1.f / sum;
    float* ap = g_assign + (size_t)node * KPG;
#pragma unroll
    for (int i = 0; i < 4; i++) {
        int c = lane + 32 * i;
        if (c < KPG) ap[c] = v[i] * inv;
    }
}

// ---------------- h_pool: per graph, assign_b^T [2000x100] @ feat_b [2000x128]
__global__ __launch_bounds__(256)
void hpool_kernel(float* __restrict__ out) {   // out = d_out + ADJ_ELEMS
    const int g = blockIdx.y;
    const int split = blockIdx.x;      // 8 splits
    const int kbeg = split * (NPG / 8);
    const int kend = kbeg + (NPG / 8);
    const float* A = g_assign + (size_t)g * NPG * KPG;
    const float* F = g_feat + (size_t)g * NPG * DD;

    __shared__ float As[8][KPG];
    __shared__ float Fs[8][DD];
    const int tx = threadIdx.x & 15;
    const int ty = threadIdx.x >> 4;

    float acc[7][8];
#pragma unroll
    for (int i = 0; i < 7; i++)
#pragma unroll
        for (int j = 0; j < 8; j++) acc[i][j] = 0.f;

    for (int k0 = kbeg; k0 < kend; k0 += 8) {
        int kc = min(8, kend - k0);
        for (int idx = threadIdx.x; idx < 8 * KPG; idx += 256) {
            int r = idx / KPG, c = idx % KPG;
            As[r][c] = (r < kc) ? A[(size_t)(k0 + r) * KPG + c] : 0.f;
        }
        for (int idx = threadIdx.x; idx < 8 * DD; idx += 256) {
            int r = idx >> 7, c = idx & 127;
            Fs[r][c] = (r < kc) ? F[(size_t)(k0 + r) * DD + c] : 0.f;
        }
        __syncthreads();
#pragma unroll
        for (int k = 0; k < 8; k++) {
            float a[7], f[8];
#pragma unroll
            for (int i = 0; i < 7; i++) {
                int c = ty + 16 * i;
                a[i] = (c < KPG) ? As[k][c] : 0.f;
            }
#pragma unroll
            for (int j = 0; j < 8; j++) f[j] = Fs[k][tx + 16 * j];
#pragma unroll
            for (int i = 0; i < 7; i++)
#pragma unroll
                for (int j = 0; j < 8; j++) acc[i][j] += a[i] * f[j];
        }
        __syncthreads();
    }
#pragma unroll
    for (int i = 0; i < 7; i++) {
        int c = ty + 16 * i;
        if (c >= KPG) continue;
#pragma unroll
        for (int j = 0; j < 8; j++) {
            int d = tx + 16 * j;
            atomicAdd(&out[(size_t)(g * KPG + c) * DD + d], acc[i][j]);
        }
    }
}

// ---------------- adj: per graph, assign_b^T [2000x100] @ tmp_b [2000x100] --
__global__ __launch_bounds__(256)
void adj_kernel(float* __restrict__ out) {   // adj part of d_out (pre-zeroed)
    const int g = blockIdx.y;
    const int split = blockIdx.x;      // 8 splits
    const int kbeg = split * (NPG / 8);
    const int kend = kbeg + (NPG / 8);
    const float* A = g_assign + (size_t)g * NPG * KPG;
    const float* T = g_tmp + (size_t)g * NPG * KPG;

    __shared__ float As[8][KPG];
    __shared__ float Ts[8][KPG];
    const int tx = threadIdx.x & 15;
    const int ty = threadIdx.x >> 4;

    float acc[7][7];
#pragma unroll
    for (int i = 0; i < 7; i++)
#pragma unroll
        for (int j = 0; j < 7; j++) acc[i][j] = 0.f;

    for (int k0 = kbeg; k0 < kend; k0 += 8) {
        int kc = min(8, kend - k0);
        for (int idx = threadIdx.x; idx < 8 * KPG; idx += 256) {
            int r = idx / KPG, c = idx % KPG;
            As[r][c] = (r < kc) ? A[(size_t)(k0 + r) * KPG + c] : 0.f;
            Ts[r][c] = (r < kc) ? T[(size_t)(k0 + r) * KPG + c] : 0.f;
        }
        __syncthreads();
#pragma unroll
        for (int k = 0; k < 8; k++) {
            float a[7], b[7];
#pragma unroll
            for (int i = 0; i < 7; i++) {
                int c = ty + 16 * i;
                a[i] = (c < KPG) ? As[k][c] : 0.f;
            }
#pragma unroll
            for (int j = 0; j < 7; j++) {
                int c = tx + 16 * j;
                b[j] = (c < KPG) ? Ts[k][c] : 0.f;
            }
#pragma unroll
            for (int i = 0; i < 7; i++)
#pragma unroll
                for (int j = 0; j < 7; j++) acc[i][j] += a[i] * b[j];
        }
        __syncthreads();
    }
#pragma unroll
    for (int i = 0; i < 7; i++) {
        int c1 = ty + 16 * i;
        if (c1 >= KPG) continue;
#pragma unroll
        for (int j = 0; j < 7; j++) {
            int c2 = tx + 16 * j;
            if (c2 >= KPG) continue;
            atomicAdd(&out[(size_t)(g * KPG + c1) * KK + (g * KPG + c2)], acc[i][j]);
        }
    }
}

// ---------------- launch ----------------------------------------------------
extern "C" void kernel_launch(void* const* d_in, const int* in_sizes, int n_in,
                              void* d_out, int out_size) {
    const float* h   = (const float*)d_in[0];
    const int*   src = (const int*)d_in[1];
    const int*   dst = (const int*)d_in[2];
    const float* W1f = (const float*)d_in[3];
    const float* b1f = (const float*)d_in[4];
    const float* W2f = (const float*)d_in[5];
    const float* b2f = (const float*)d_in[6];
    const float* W1p = (const float*)d_in[7];
    const float* b1p = (const float*)d_in[8];
    const float* W2p = (const float*)d_in[9];
    const float* b2p = (const float*)d_in[10];
    float* out = (float*)d_out;

    float *x, *t1, *feat, *x2, *logits;
    int* degi;
    cudaGetSymbolAddress((void**)&x,      g_x);
    cudaGetSymbolAddress((void**)&t1,     g_t1);
    cudaGetSymbolAddress((void**)&feat,   g_feat);
    cudaGetSymbolAddress((void**)&x2,     g_x2);
    cudaGetSymbolAddress((void**)&logits, g_logits);
    cudaGetSymbolAddress((void**)&degi,   g_degi);

    cudaFuncSetAttribute(mma_gemm, cudaFuncAttributeMaxDynamicSharedMemorySize,
                         TC_SMEM_BYTES);

    // zero output + degree counters
    zero_f<<<1024, 256>>>(out, (size_t)out_size);
    zero_i<<<128, 256>>>(degi, (size_t)NN);

    // neighbor buckets (per-dst lists)
    fill_bucket_kernel<<<(EE + 255) / 256, 256>>>(src, dst);

    // x = h + mean-aggregated neighbors (shared by both GIN branches)
    gather_x_kernel<<<(NN * 32 + 255) / 256, 256>>>(h);

    // feat branch: two 32000x128x128 GEMMs (tensor cores, tf32 split)
    mma_gemm<<<dim3(250, 1, 1), 256, TC_SMEM_BYTES>>>(x, W1f, b1f, t1,
        NN, DD, DD, DD, DD, DD, 0, 0, 0, 0);
    mma_gemm<<<dim3(250, 1, 1), 256, TC_SMEM_BYTES>>>(t1, W2f, b2f, feat,
        NN, DD, DD, DD, DD, DD, 0, 0, 0, 0);

    // pool branch layer 1: 32000 x 1600 x 128
    mma_gemm<<<dim3(250, 13, 1), 256, TC_SMEM_BYTES>>>(x, W1p, b1p, x2,
        NN, KK, DD, DD, KK, KK, 0, 0, 0, 0);

    // pool branch layer 2: per graph [2000,1600] @ [1600,100] -> compact logits
    mma_gemm<<<dim3(16, 1, NB), 256, TC_SMEM_BYTES>>>(x2, W2p, b2p, logits,
        NPG, KPG, KK, KK, KK, KPG,
        (long)NPG * KK, (long)KPG, (long)NPG * KPG, (long)KPG);

    // masked softmax (compact in-block)
    softmax_kernel<<<(NN * 32 + 255) / 256, 256>>>();

    // tmp = gather-sum of assign over incoming edges (no atomics)
    gather_tmp_kernel<<<(NN * 32 + 255) / 256, 256>>>();

    // h_pool and adj (block-diagonal), atomic split-K into pre-zeroed d_out
    hpool_kernel<<<dim3(8, NB), 256>>>(out + ADJ_ELEMS);
    adj_kernel<<<dim3(8, NB), 256>>>(out);
}

// round 6
// speedup vs baseline: 1.3231x; 1.1580x over previous
#include <cuda_runtime.h>
#include <cuda_bf16.h>
#include <math.h>
#include <cstdint>
#include <cstddef>

// Problem constants
static constexpr int NN   = 32000;     // nodes
static constexpr int NB   = 16;        // graphs
static constexpr int NPG  = 2000;      // nodes per graph
static constexpr int KK   = 1600;      // clusters total
static constexpr int KPG  = 100;       // clusters per graph
static constexpr int DD   = 128;       // feature dim
static constexpr int EE   = 512000;    // edges
static constexpr int ADJ_ELEMS = KK * KK;
static constexpr int CAP  = 96;        // neighbor bucket capacity

// ---------------- scratch (__device__ globals) ------------------------------
__device__ float g_x[(size_t)NN * DD];
__device__ float g_t1[(size_t)NN * DD];
__device__ float g_feat[(size_t)NN * DD];
__device__ float g_x2[(size_t)NN * KK];
__device__ float g_logits[(size_t)NN * KPG];
__device__ float g_assign[(size_t)NN * KPG];
__device__ float g_tmp[(size_t)NN * KPG];
__device__ int   g_degi[NN];
__device__ int   g_nbr[(size_t)NN * CAP];

// ---------------- helpers ----------------------------------------------------
__device__ __forceinline__ void mma_bf16(float* c, const uint32_t* a,
                                         uint32_t b0, uint32_t b1) {
    asm volatile(
        "mma.sync.aligned.m16n8k16.row.col.f32.bf16.bf16.f32 "
        "{%0,%1,%2,%3}, {%4,%5,%6,%7}, {%8,%9}, {%0,%1,%2,%3};"
        : "+f"(c[0]), "+f"(c[1]), "+f"(c[2]), "+f"(c[3])
        : "r"(a[0]), "r"(a[1]), "r"(a[2]), "r"(a[3]), "r"(b0), "r"(b1));
}
// split f0,f1 into bf16 hi pair + fp32-residual bf16 lo pair (packed words)
__device__ __forceinline__ void split2(float f0, float f1, uint32_t& hi, uint32_t& lo) {
    __nv_bfloat16 h0 = __float2bfloat16(f0);
    __nv_bfloat16 h1 = __float2bfloat16(f1);
    __nv_bfloat16 l0 = __float2bfloat16(f0 - __bfloat162float(h0));
    __nv_bfloat16 l1 = __float2bfloat16(f1 - __bfloat162float(h1));
    __nv_bfloat162 hp = __nv_bfloat162(h0, h1);
    __nv_bfloat162 lp = __nv_bfloat162(l0, l1);
    hi = *reinterpret_cast<uint32_t*>(&hp);
    lo = *reinterpret_cast<uint32_t*>(&lp);
}

// ---------------- zero helpers ----------------------------------------------
__global__ void zero_f(float* __restrict__ p, size_t n) {
    size_t i = (size_t)blockIdx.x * blockDim.x + threadIdx.x;
    size_t st = (size_t)gridDim.x * blockDim.x;
    for (; i < n; i += st) p[i] = 0.f;
}
__global__ void zero_i(int* __restrict__ p, size_t n) {
    size_t i = (size_t)blockIdx.x * blockDim.x + threadIdx.x;
    size_t st = (size_t)gridDim.x * blockDim.x;
    for (; i < n; i += st) p[i] = 0;
}

// ---------------- bucket fill: per-dst neighbor lists ------------------------
__global__ void fill_bucket_kernel(const int* __restrict__ src,
                                   const int* __restrict__ dst) {
    int e = blockIdx.x * blockDim.x + threadIdx.x;
    if (e >= EE) return;
    int d = dst[e];
    int p = atomicAdd(&g_degi[d], 1);
    if (p < CAP) g_nbr[(size_t)d * CAP + p] = src[e];
}

// ---------------- gather: x = h + mean_{s in N(n)} h[s] ---------------------
__global__ void gather_x_kernel(const float* __restrict__ h) {
    int n = (blockIdx.x * blockDim.x + threadIdx.x) >> 5;
    int lane = threadIdx.x & 31;
    if (n >= NN) return;
    int dg = min(g_degi[n], CAP);
    const int* nb = g_nbr + (size_t)n * CAP;
    float a0 = 0.f, a1 = 0.f, a2 = 0.f, a3 = 0.f;
    for (int j = 0; j < dg; j++) {
        const float* hr = h + (size_t)nb[j] * DD;
        a0 += hr[lane];
        a1 += hr[lane + 32];
        a2 += hr[lane + 64];
        a3 += hr[lane + 96];
    }
    float inv = 1.f / fmaxf((float)dg, 1.f);
    const float* hn = h + (size_t)n * DD;
    float* xo = g_x + (size_t)n * DD;
    xo[lane]      = hn[lane]      + a0 * inv;
    xo[lane + 32] = hn[lane + 32] + a1 * inv;
    xo[lane + 64] = hn[lane + 64] + a2 * inv;
    xo[lane + 96] = hn[lane + 96] + a3 * inv;
}

// ---------------- gather: tmp[n] = sum_{s in N(n)} assign[s] ----------------
__global__ void gather_tmp_kernel() {
    int n = (blockIdx.x * blockDim.x + threadIdx.x) >> 5;
    int lane = threadIdx.x & 31;
    if (n >= NN) return;
    int dg = min(g_degi[n], CAP);
    const int* nb = g_nbr + (size_t)n * CAP;
    float a0 = 0.f, a1 = 0.f, a2 = 0.f, a3 = 0.f;
    for (int j = 0; j < dg; j++) {
        const float* ar = g_assign + (size_t)nb[j] * KPG;
        a0 += ar[lane];
        a1 += ar[lane + 32];
        a2 += ar[lane + 64];
        if (lane < 4) a3 += ar[lane + 96];
    }
    float* tp = g_tmp + (size_t)n * KPG;
    tp[lane]      = a0;
    tp[lane + 32] = a1;
    tp[lane + 64] = a2;
    if (lane < 4) tp[lane + 96] = a3;
}

// ---------------- tensor-core bf16 split GEMM: C = relu(A@B + bias) ---------
// A [M,K] (lda), B [K,N] (ldb), C [M,N] (ldc). 128x128 CTA tile, BK=32,
// 256 threads = 8 warps (4 in M x 2 in N), warp tile 32x64, mma m16n8k16 bf16.
// 2-term bf16 split: hi*hi + hi*lo + lo*hi (fp32 accumulate).
// Smem: packed bf16x2 words, [kpair][m|n] with stride 132 (conflict-free).
static constexpr int TCK = 32;                 // BK (k elements)
static constexpr int TCP = TCK / 2;            // kpairs per tile = 16
static constexpr int TCS = 132;                // stride in uint32

__global__ __launch_bounds__(256)
void mma_gemm(const float* __restrict__ A, const float* __restrict__ B,
              const float* __restrict__ bias, float* __restrict__ C,
              int M, int N, int K, int lda, int ldb, int ldc,
              long zsA, long zsB, long zsC, long zsBias) {
    __shared__ uint32_t Ah[TCP * TCS];
    __shared__ uint32_t Al[TCP * TCS];
    __shared__ uint32_t Bh[TCP * TCS];
    __shared__ uint32_t Bl[TCP * TCS];

    A    += (size_t)blockIdx.z * zsA;
    B    += (size_t)blockIdx.z * zsB;
    C    += (size_t)blockIdx.z * zsC;
    bias += (size_t)blockIdx.z * zsBias;

    const int tid  = threadIdx.x;
    const int wid  = tid >> 5;
    const int lane = tid & 31;
    const int wm   = wid & 3;          // warp row (M)
    const int wn   = wid >> 2;         // warp col (N)
    const int g    = lane >> 2;        // groupID 0..7
    const int tig  = lane & 3;         // thread-in-group
    const int bm   = blockIdx.x * 128;
    const int bn   = blockIdx.y * 128;

    // A loader: thread -> (row am, 16-wide k chunk akq)
    const int am   = tid >> 1;
    const int akq  = (tid & 1) * 16;
    const int arow = min(bm + am, M - 1);
    const float* Aptr = A + (size_t)arow * lda + akq;
    // B loader: thread -> (kpair bk2 = 2 k rows, 8-wide n chunk bnq)
    const int bk2  = tid >> 4;             // 0..15
    const int bnq  = (tid & 15) * 8;       // 0..120

    float c[2][8][4];
#pragma unroll
    for (int mt = 0; mt < 2; mt++)
#pragma unroll
        for (int nt = 0; nt < 8; nt++)
#pragma unroll
            for (int q = 0; q < 4; q++) c[mt][nt][q] = 0.f;

    for (int k0 = 0; k0 < K; k0 += TCK) {
        // ---- A tile
#pragma unroll
        for (int v = 0; v < 4; v++) {
            float4 va = *(const float4*)(Aptr + k0 + v * 4);
            uint32_t hi, lo;
            int kp = (akq + v * 4) >> 1;
            split2(va.x, va.y, hi, lo);
            Ah[kp * TCS + am] = hi; Al[kp * TCS + am] = lo;
            split2(va.z, va.w, hi, lo);
            Ah[(kp + 1) * TCS + am] = hi; Al[(kp + 1) * TCS + am] = lo;
        }
        // ---- B tile (two k rows per thread, 8 n cols)
        {
            const float* Bp0 = B + (size_t)(k0 + 2 * bk2) * ldb;
            const float* Bp1 = Bp0 + ldb;
            float f0[8], f1[8];
            if (bn + bnq + 7 < N) {
                *(float4*)&f0[0] = *(const float4*)(Bp0 + bn + bnq);
                *(float4*)&f0[4] = *(const float4*)(Bp0 + bn + bnq + 4);
                *(float4*)&f1[0] = *(const float4*)(Bp1 + bn + bnq);
                *(float4*)&f1[4] = *(const float4*)(Bp1 + bn + bnq + 4);
            } else {
#pragma unroll
                for (int i = 0; i < 8; i++) {
                    int col = bn + bnq + i;
                    bool ok = (col < N);
                    int cc = min(col, N - 1);
                    f0[i] = ok ? Bp0[cc] : 0.f;
                    f1[i] = ok ? Bp1[cc] : 0.f;
                }
            }
#pragma unroll
            for (int i = 0; i < 8; i++) {
                uint32_t hi, lo;
                split2(f0[i], f1[i], hi, lo);
                Bh[bk2 * TCS + bnq + i] = hi;
                Bl[bk2 * TCS + bnq + i] = lo;
            }
        }
        __syncthreads();

#pragma unroll
        for (int ks = 0; ks < 2; ks++) {
            const int kp = ks * 8 + tig;
            uint32_t ah[2][4], al[2][4];
#pragma unroll
            for (int mt = 0; mt < 2; mt++) {
                const int mr = wm * 32 + mt * 16 + g;
                ah[mt][0] = Ah[kp * TCS + mr];
                ah[mt][1] = Ah[kp * TCS + mr + 8];
                ah[mt][2] = Ah[(kp + 4) * TCS + mr];
                ah[mt][3] = Ah[(kp + 4) * TCS + mr + 8];
                al[mt][0] = Al[kp * TCS + mr];
                al[mt][1] = Al[kp * TCS + mr + 8];
                al[mt][2] = Al[(kp + 4) * TCS + mr];
                al[mt][3] = Al[(kp + 4) * TCS + mr + 8];
            }
#pragma unroll
            for (int nt = 0; nt < 8; nt++) {
                const int nc = wn * 64 + nt * 8 + g;
                uint32_t bh0 = Bh[kp * TCS + nc];
                uint32_t bh1 = Bh[(kp + 4) * TCS + nc];
                uint32_t bl0 = Bl[kp * TCS + nc];
                uint32_t bl1 = Bl[(kp + 4) * TCS + nc];
#pragma unroll
                for (int mt = 0; mt < 2; mt++) {
                    mma_bf16(c[mt][nt], ah[mt], bh0, bh1);
                    mma_bf16(c[mt][nt], ah[mt], bl0, bl1);
                    mma_bf16(c[mt][nt], al[mt], bh0, bh1);
                }
            }
        }
        __syncthreads();
    }

    // ---- epilogue: bias + relu
#pragma unroll
    for (int mt = 0; mt < 2; mt++) {
        const int r0 = bm + wm * 32 + mt * 16 + g;
        const int r1 = r0 + 8;
#pragma unroll
        for (int nt = 0; nt < 8; nt++) {
            const int col = bn + wn * 64 + nt * 8 + 2 * tig;
            if (col >= N) continue;
            const bool pair = (col + 1 < N);
            const float b0 = bias[col];
            const float b1 = pair ? bias[col + 1] : 0.f;
            if (r0 < M) {
                float v0 = fmaxf(c[mt][nt][0] + b0, 0.f);
                float v1 = fmaxf(c[mt][nt][1] + b1, 0.f);
                if (pair) *(float2*)(C + (size_t)r0 * ldc + col) = make_float2(v0, v1);
                else      C[(size_t)r0 * ldc + col] = v0;
            }
            if (r1 < M) {
                float v2 = fmaxf(c[mt][nt][2] + b0, 0.f);
                float v3 = fmaxf(c[mt][nt][3] + b1, 0.f);
                if (pair) *(float2*)(C + (size_t)r1 * ldc + col) = make_float2(v2, v3);
                else      C[(size_t)r1 * ldc + col] = v2;
            }
        }
    }
}

// ---------------- per-node softmax over 100 compact logits ------------------
__global__ void softmax_kernel() {
    int node = (blockIdx.x * blockDim.x + threadIdx.x) >> 5;
    int lane = threadIdx.x & 31;
    if (node >= NN) return;
    const float* lp = g_logits + (size_t)node * KPG;
    float v[4];
    float mx = -1e30f;
#pragma unroll
    for (int i = 0; i < 4; i++) {
        int c = lane + 32 * i;
        v[i] = (c < KPG) ? lp[c] : -1e30f;
        mx = fmaxf(mx, v[i]);
    }
#pragma unroll
    for (int o = 16; o; o >>= 1) mx = fmaxf(mx, __shfl_xor_sync(0xFFFFFFFFu, mx, o));
    float sum = 0.f;
#pragma unroll
    for (int i = 0; i < 4; i++) {
        int c = lane + 32 * i;
        v[i] = (c < KPG) ? expf(v[i] - mx) : 0.f;
        sum += v[i];
    }
#pragma unroll
    for (int o = 16; o; o >>= 1) sum += __shfl_xor_sync(0xFFFFFFFFu, sum, o);
    float inv = 1.f / sum;
    float* ap = g_assign + (size_t)node * KPG;
#pragma unroll
    for (int i = 0; i < 4; i++) {
        int c = lane + 32 * i;
        if (c < KPG) ap[c] = v[i] * inv;
    }
}

// ---------------- h_pool: per graph, assign_b^T [2000x100] @ feat_b [2000x128]
__global__ __launch_bounds__(256)
void hpool_kernel(float* __restrict__ out) {   // out = d_out + ADJ_ELEMS
    const int g = blockIdx.y;
    const int split = blockIdx.x;      // 8 splits
    const int kbeg = split * (NPG / 8);
    const int kend = kbeg + (NPG / 8);
    const float* A = g_assign + (size_t)g * NPG * KPG;
    const float* F = g_feat + (size_t)g * NPG * DD;

    __shared__ float As[8][KPG];
    __shared__ float Fs[8][DD];
    const int tx = threadIdx.x & 15;
    const int ty = threadIdx.x >> 4;

    float acc[7][8];
#pragma unroll
    for (int i = 0; i < 7; i++)
#pragma unroll
        for (int j = 0; j < 8; j++) acc[i][j] = 0.f;

    for (int k0 = kbeg; k0 < kend; k0 += 8) {
        int kc = min(8, kend - k0);
        for (int idx = threadIdx.x; idx < 8 * KPG; idx += 256) {
            int r = idx / KPG, c = idx % KPG;
            As[r][c] = (r < kc) ? A[(size_t)(k0 + r) * KPG + c] : 0.f;
        }
        for (int idx = threadIdx.x; idx < 8 * DD; idx += 256) {
            int r = idx >> 7, c = idx & 127;
            Fs[r][c] = (r < kc) ? F[(size_t)(k0 + r) * DD + c] : 0.f;
        }
        __syncthreads();
#pragma unroll
        for (int k = 0; k < 8; k++) {
            float a[7], f[8];
#pragma unroll
            for (int i = 0; i < 7; i++) {
                int c = ty + 16 * i;
                a[i] = (c < KPG) ? As[k][c] : 0.f;
            }
#pragma unroll
            for (int j = 0; j < 8; j++) f[j] = Fs[k][tx + 16 * j];
#pragma unroll
            for (int i = 0; i < 7; i++)
#pragma unroll
                for (int j = 0; j < 8; j++) acc[i][j] += a[i] * f[j];
        }
        __syncthreads();
    }
#pragma unroll
    for (int i = 0; i < 7; i++) {
        int c = ty + 16 * i;
        if (c >= KPG) continue;
#pragma unroll
        for (int j = 0; j < 8; j++) {
            int d = tx + 16 * j;
            atomicAdd(&out[(size_t)(g * KPG + c) * DD + d], acc[i][j]);
        }
    }
}

// ---------------- adj: per graph, assign_b^T [2000x100] @ tmp_b [2000x100] --
__global__ __launch_bounds__(256)
void adj_kernel(float* __restrict__ out) {   // adj part of d_out (pre-zeroed)
    const int g = blockIdx.y;
    const int split = blockIdx.x;      // 8 splits
    const int kbeg = split * (NPG / 8);
    const int kend = kbeg + (NPG / 8);
    const float* A = g_assign + (size_t)g * NPG * KPG;
    const float* T = g_tmp + (size_t)g * NPG * KPG;

    __shared__ float As[8][KPG];
    __shared__ float Ts[8][KPG];
    const int tx = threadIdx.x & 15;
    const int ty = threadIdx.x >> 4;

    float acc[7][7];
#pragma unroll
    for (int i = 0; i < 7; i++)
#pragma unroll
        for (int j = 0; j < 7; j++) acc[i][j] = 0.f;

    for (int k0 = kbeg; k0 < kend; k0 += 8) {
        int kc = min(8, kend - k0);
        for (int idx = threadIdx.x; idx < 8 * KPG; idx += 256) {
            int r = idx / KPG, c = idx % KPG;
            As[r][c] = (r < kc) ? A[(size_t)(k0 + r) * KPG + c] : 0.f;
            Ts[r][c] = (r < kc) ? T[(size_t)(k0 + r) * KPG + c] : 0.f;
        }
        __syncthreads();
#pragma unroll
        for (int k = 0; k < 8; k++) {
            float a[7], b[7];
#pragma unroll
            for (int i = 0; i < 7; i++) {
                int c = ty + 16 * i;
                a[i] = (c < KPG) ? As[k][c] : 0.f;
            }
#pragma unroll
            for (int j = 0; j < 7; j++) {
                int c = tx + 16 * j;
                b[j] = (c < KPG) ? Ts[k][c] : 0.f;
            }
#pragma unroll
            for (int i = 0; i < 7; i++)
#pragma unroll
                for (int j = 0; j < 7; j++) acc[i][j] += a[i] * b[j];
        }
        __syncthreads();
    }
#pragma unroll
    for (int i = 0; i < 7; i++) {
        int c1 = ty + 16 * i;
        if (c1 >= KPG) continue;
#pragma unroll
        for (int j = 0; j < 7; j++) {
            int c2 = tx + 16 * j;
            if (c2 >= KPG) continue;
            atomicAdd(&out[(size_t)(g * KPG + c1) * KK + (g * KPG + c2)], acc[i][j]);
        }
    }
}

// ---------------- launch ----------------------------------------------------
extern "C" void kernel_launch(void* const* d_in, const int* in_sizes, int n_in,
                              void* d_out, int out_size) {
    const float* h   = (const float*)d_in[0];
    const int*   src = (const int*)d_in[1];
    const int*   dst = (const int*)d_in[2];
    const float* W1f = (const float*)d_in[3];
    const float* b1f = (const float*)d_in[4];
    const float* W2f = (const float*)d_in[5];
    const float* b2f = (const float*)d_in[6];
    const float* W1p = (const float*)d_in[7];
    const float* b1p = (const float*)d_in[8];
    const float* W2p = (const float*)d_in[9];
    const float* b2p = (const float*)d_in[10];
    float* out = (float*)d_out;

    float *x, *t1, *feat, *x2, *logits;
    int* degi;
    cudaGetSymbolAddress((void**)&x,      g_x);
    cudaGetSymbolAddress((void**)&t1,     g_t1);
    cudaGetSymbolAddress((void**)&feat,   g_feat);
    cudaGetSymbolAddress((void**)&x2,     g_x2);
    cudaGetSymbolAddress((void**)&logits, g_logits);
    cudaGetSymbolAddress((void**)&degi,   g_degi);

    // zero output + degree counters
    zero_f<<<1024, 256>>>(out, (size_t)out_size);
    zero_i<<<128, 256>>>(degi, (size_t)NN);

    // neighbor buckets (per-dst lists)
    fill_bucket_kernel<<<(EE + 255) / 256, 256>>>(src, dst);

    // x = h + mean-aggregated neighbors (shared by both GIN branches)
    gather_x_kernel<<<(NN * 32 + 255) / 256, 256>>>(h);

    // feat branch: two 32000x128x128 GEMMs (tensor cores, bf16 split)
    mma_gemm<<<dim3(250, 1, 1), 256>>>(x, W1f, b1f, t1,
        NN, DD, DD, DD, DD, DD, 0, 0, 0, 0);
    mma_gemm<<<dim3(250, 1, 1), 256>>>(t1, W2f, b2f, feat,
        NN, DD, DD, DD, DD, DD, 0, 0, 0, 0);

    // pool branch layer 1: 32000 x 1600 x 128
    mma_gemm<<<dim3(250, 13, 1), 256>>>(x, W1p, b1p, x2,
        NN, KK, DD, DD, KK, KK, 0, 0, 0, 0);

    // pool branch layer 2: per graph [2000,1600] @ [1600,100] -> compact logits
    mma_gemm<<<dim3(16, 1, NB), 256>>>(x2, W2p, b2p, logits,
        NPG, KPG, KK, KK, KK, KPG,
        (long)NPG * KK, (long)KPG, (long)NPG * KPG, (long)KPG);

    // masked softmax (compact in-block)
    softmax_kernel<<<(NN * 32 + 255) / 256, 256>>>();

    // tmp = gather-sum of assign over incoming edges (no atomics)
    gather_tmp_kernel<<<(NN * 32 + 255) / 256, 256>>>();

    // h_pool and adj (block-diagonal), atomic split-K into pre-zeroed d_out
    hpool_kernel<<<dim3(8, NB), 256>>>(out + ADJ_ELEMS);
    adj_kernel<<<dim3(8, NB), 256>>>(out);
}

// round 7
// speedup vs baseline: 1.4581x; 1.1020x over previous
#include <cuda_runtime.h>
#include <cuda_bf16.h>
#include <math.h>
#include <cstdint>
#include <cstddef>

// Problem constants
static constexpr int NN   = 32000;     // nodes
static constexpr int NB   = 16;        // graphs
static constexpr int NPG  = 2000;      // nodes per graph
static constexpr int KK   = 1600;      // clusters total
static constexpr int KPG  = 100;       // clusters per graph
static constexpr int DD   = 128;       // feature dim
static constexpr int EE   = 512000;    // edges
static constexpr int ADJ_ELEMS = KK * KK;
static constexpr int CAP  = 96;        // neighbor bucket capacity

// ---------------- scratch (__device__ globals) ------------------------------
// packed bf16x2 hi/lo operand buffers (A-format: [rows][K/2] words)
__device__ uint32_t g_xh[(size_t)NN * DD / 2];
__device__ uint32_t g_xl[(size_t)NN * DD / 2];
__device__ uint32_t g_t1h[(size_t)NN * DD / 2];
__device__ uint32_t g_t1l[(size_t)NN * DD / 2];
__device__ uint32_t g_x2h[(size_t)NN * KK / 2];
__device__ uint32_t g_x2l[(size_t)NN * KK / 2];
// B-format packed weights: [K/2][N] words
__device__ uint32_t g_w1fh[DD / 2 * DD];
__device__ uint32_t g_w1fl[DD / 2 * DD];
__device__ uint32_t g_w2fh[DD / 2 * DD];
__device__ uint32_t g_w2fl[DD / 2 * DD];
__device__ uint32_t g_w1ph[(size_t)DD / 2 * KK];
__device__ uint32_t g_w1pl[(size_t)DD / 2 * KK];
__device__ uint32_t g_w2ph[(size_t)KK / 2 * KK];
__device__ uint32_t g_w2pl[(size_t)KK / 2 * KK];
// fp32 buffers
__device__ float g_feat[(size_t)NN * DD];
__device__ float g_logits[(size_t)NN * KPG];
__device__ float g_assign[(size_t)NN * KPG];
__device__ float g_tmp[(size_t)NN * KPG];
__device__ int   g_degi[NN];
__device__ int   g_nbr[(size_t)NN * CAP];

// ---------------- helpers ----------------------------------------------------
__device__ __forceinline__ uint32_t smem_u32(const void* p) {
    uint32_t a;
    asm("{ .reg .u64 t; cvta.to.shared.u64 t, %1; cvt.u32.u64 %0, t; }" : "=r"(a) : "l"(p));
    return a;
}
__device__ __forceinline__ void cp16(uint32_t saddr, const void* g) {
    asm volatile("cp.async.ca.shared.global [%0], [%1], 16;" :: "r"(saddr), "l"(g) : "memory");
}
__device__ __forceinline__ void cp_commit() {
    asm volatile("cp.async.commit_group;" ::: "memory");
}
__device__ __forceinline__ void cp_wait0() {
    asm volatile("cp.async.wait_group 0;" ::: "memory");
}
__device__ __forceinline__ void mma_bf16(float* c, const uint32_t* a,
                                         uint32_t b0, uint32_t b1) {
    asm volatile(
        "mma.sync.aligned.m16n8k16.row.col.f32.bf16.bf16.f32 "
        "{%0,%1,%2,%3}, {%4,%5,%6,%7}, {%8,%9}, {%0,%1,%2,%3};"
        : "+f"(c[0]), "+f"(c[1]), "+f"(c[2]), "+f"(c[3])
        : "r"(a[0]), "r"(a[1]), "r"(a[2]), "r"(a[3]), "r"(b0), "r"(b1));
}
__device__ __forceinline__ void split2(float f0, float f1, uint32_t& hi, uint32_t& lo) {
    __nv_bfloat16 h0 = __float2bfloat16(f0);
    __nv_bfloat16 h1 = __float2bfloat16(f1);
    __nv_bfloat16 l0 = __float2bfloat16(f0 - __bfloat162float(h0));
    __nv_bfloat16 l1 = __float2bfloat16(f1 - __bfloat162float(h1));
    __nv_bfloat162 hp = __nv_bfloat162(h0, h1);
    __nv_bfloat162 lp = __nv_bfloat162(l0, l1);
    hi = *reinterpret_cast<uint32_t*>(&hp);
    lo = *reinterpret_cast<uint32_t*>(&lp);
}

// ---------------- zero helpers ----------------------------------------------
__global__ void zero_f(float* __restrict__ p, size_t n) {
    size_t i = (size_t)blockIdx.x * blockDim.x + threadIdx.x;
    size_t st = (size_t)gridDim.x * blockDim.x;
    for (; i < n; i += st) p[i] = 0.f;
}
__global__ void zero_i(int* __restrict__ p, size_t n) {
    size_t i = (size_t)blockIdx.x * blockDim.x + threadIdx.x;
    size_t st = (size_t)gridDim.x * blockDim.x;
    for (; i < n; i += st) p[i] = 0;
}

// ---------------- bucket fill: per-dst neighbor lists ------------------------
__global__ void fill_bucket_kernel(const int* __restrict__ src,
                                   const int* __restrict__ dst) {
    int e = blockIdx.x * blockDim.x + threadIdx.x;
    if (e >= EE) return;
    int d = dst[e];
    int p = atomicAdd(&g_degi[d], 1);
    if (p < CAP) g_nbr[(size_t)d * CAP + p] = src[e];
}

// ---------------- B-format weight split: Bpack[kp][n] = (B[2kp][n], B[2kp+1][n])
__global__ void split_B_kernel(const float* __restrict__ B,
                               uint32_t* __restrict__ Bh, uint32_t* __restrict__ Bl,
                               int K2, int N) {
    int idx = blockIdx.x * blockDim.x + threadIdx.x;
    if (idx >= K2 * N) return;
    int kp = idx / N, n = idx - kp * N;
    float f0 = B[(size_t)(2 * kp) * N + n];
    float f1 = B[(size_t)(2 * kp + 1) * N + n];
    uint32_t hi, lo;
    split2(f0, f1, hi, lo);
    Bh[idx] = hi;
    Bl[idx] = lo;
}

// ---------------- gather: x = h + mean nbr, write packed bf16 hi/lo ---------
__global__ void gather_x_kernel(const float* __restrict__ h) {
    int n = (blockIdx.x * blockDim.x + threadIdx.x) >> 5;
    int lane = threadIdx.x & 31;
    if (n >= NN) return;
    int dg = min(g_degi[n], CAP);
    const int* nb = g_nbr + (size_t)n * CAP;
    float a0 = 0.f, a1 = 0.f, a2 = 0.f, a3 = 0.f;
    for (int j = 0; j < dg; j++) {
        float4 v = ((const float4*)(h + (size_t)nb[j] * DD))[lane];
        a0 += v.x; a1 += v.y; a2 += v.z; a3 += v.w;
    }
    float inv = 1.f / fmaxf((float)dg, 1.f);
    float4 hn = ((const float4*)(h + (size_t)n * DD))[lane];
    float v0 = hn.x + a0 * inv;
    float v1 = hn.y + a1 * inv;
    float v2 = hn.z + a2 * inv;
    float v3 = hn.w + a3 * inv;
    uint32_t hi0, lo0, hi1, lo1;
    split2(v0, v1, hi0, lo0);
    split2(v2, v3, hi1, lo1);
    size_t base = (size_t)n * (DD / 2) + lane * 2;
    g_xh[base] = hi0; g_xh[base + 1] = hi1;
    g_xl[base] = lo0; g_xl[base + 1] = lo1;
}

// ---------------- tensor-core bf16 split GEMM, pre-packed operands ----------
// A packed [M][K/2] hi/lo words; B packed [K/2][N] hi/lo words.
// C = relu(A@B + bias); OUT_SPLIT writes packed hi/lo words, else fp32.
// 128x128 CTA tile, BK=32 (16 kpairs), 256 thr = 8 warps, warp tile 32x64.
// Double-buffered smem via cp.async.
static constexpr int AW = 20;     // A smem row stride (words) - conflict-free
static constexpr int BW = 132;    // B smem kpair-row stride (words)
static constexpr int OFF_AL = 128 * AW;            // 2560
static constexpr int OFF_BH = 2 * 128 * AW;        // 5120
static constexpr int OFF_BL = OFF_BH + 16 * BW;    // 7232
static constexpr int BUFW   = OFF_BL + 16 * BW;    // 9344 words
static constexpr int GEMM_SMEM = 2 * BUFW * 4;     // 74752 bytes

template<bool OUT_SPLIT>
__global__ __launch_bounds__(256)
void mma_gemm(const uint32_t* __restrict__ Ahg, const uint32_t* __restrict__ Alg,
              const uint32_t* __restrict__ Bhg, const uint32_t* __restrict__ Blg,
              const float* __restrict__ bias,
              float* __restrict__ C, uint32_t* __restrict__ Ch, uint32_t* __restrict__ Cl,
              int M, int N, int K, int ldaw, int ldbw, int ldc, int ldcw,
              long zsAw, long zsBw, long zsC, long zsBias) {
    extern __shared__ uint32_t sm[];
    const uint32_t sbase = smem_u32(sm);

    Ahg  += (size_t)blockIdx.z * zsAw;
    Alg  += (size_t)blockIdx.z * zsAw;
    Bhg  += (size_t)blockIdx.z * zsBw;
    Blg  += (size_t)blockIdx.z * zsBw;
    bias += (size_t)blockIdx.z * zsBias;
    if (!OUT_SPLIT) C += (size_t)blockIdx.z * zsC;
    else { Ch += (size_t)blockIdx.z * zsC; Cl += (size_t)blockIdx.z * zsC; }

    const int tid  = threadIdx.x;
    const int wid  = tid >> 5;
    const int lane = tid & 31;
    const int wm   = wid & 3;
    const int wn   = wid >> 2;
    const int g    = lane >> 2;
    const int tig  = lane & 3;
    const int bm   = blockIdx.x * 128;
    const int bn   = blockIdx.y * 128;

    // A loader: row am, 8-word chunk aq
    const int am   = tid >> 1;
    const int aq   = (tid & 1) * 8;
    const int arow = min(bm + am, M - 1);
    const uint32_t* ApH = Ahg + (size_t)arow * ldaw + aq;
    const uint32_t* ApL = Alg + (size_t)arow * ldaw + aq;
    // B loader: kpair bk2, 8-word n chunk bnq
    const int bk2  = tid >> 4;
    const int bnq  = (tid & 15) * 8;
    const bool bFull = (bn + bnq + 7 < N);

    float c[2][8][4];
#pragma unroll
    for (int mt = 0; mt < 2; mt++)
#pragma unroll
        for (int nt = 0; nt < 8; nt++)
#pragma unroll
            for (int q = 0; q < 4; q++) c[mt][nt][q] = 0.f;

    auto issue = [&](int t, int buf) {
        const int kpt = t * 16;
        const uint32_t abase = sbase + (uint32_t)(buf * BUFW + am * AW + aq) * 4;
        cp16(abase,                ApH + kpt);
        cp16(abase + 16,           ApH + kpt + 4);
        cp16(abase + OFF_AL * 4,       ApL + kpt);
        cp16(abase + OFF_AL * 4 + 16,  ApL + kpt + 4);
        const uint32_t* BrH = Bhg + (size_t)(kpt + bk2) * ldbw + bn;
        const uint32_t* BrL = Blg + (size_t)(kpt + bk2) * ldbw + bn;
        const uint32_t bbase = sbase + (uint32_t)(buf * BUFW + OFF_BH + bk2 * BW + bnq) * 4;
        if (bFull) {
            cp16(bbase,                          BrH + bnq);
            cp16(bbase + 16,                     BrH + bnq + 4);
            cp16(bbase + (OFF_BL - OFF_BH) * 4,      BrL + bnq);
            cp16(bbase + (OFF_BL - OFF_BH) * 4 + 16, BrL + bnq + 4);
        } else {
            uint32_t* s = sm + buf * BUFW + OFF_BH + bk2 * BW + bnq;
#pragma unroll
            for (int i = 0; i < 8; i++) {
                int col = bn + bnq + i;
                bool ok = (col < N);
                s[i]                     = ok ? BrH[bnq + i] : 0u;
                s[(OFF_BL - OFF_BH) + i] = ok ? BrL[bnq + i] : 0u;
            }
        }
    };

    const int nT = K >> 5;
    issue(0, 0);
    cp_commit();
    cp_wait0();
    __syncthreads();

    for (int t = 0; t < nT; t++) {
        const int buf = t & 1;
        if (t + 1 < nT) { issue(t + 1, buf ^ 1); cp_commit(); }

        const uint32_t* AsH = sm + buf * BUFW;
        const uint32_t* AsL = AsH + OFF_AL;
        const uint32_t* BsH = sm + buf * BUFW + OFF_BH;
        const uint32_t* BsL = BsH + (OFF_BL - OFF_BH);

#pragma unroll
        for (int ks = 0; ks < 2; ks++) {
            const int kp = ks * 8 + tig;
            uint32_t ah[2][4], al[2][4];
#pragma unroll
            for (int mt = 0; mt < 2; mt++) {
                const int mr = wm * 32 + mt * 16 + g;
                ah[mt][0] = AsH[mr * AW + kp];
                ah[mt][1] = AsH[(mr + 8) * AW + kp];
                ah[mt][2] = AsH[mr * AW + kp + 4];
                ah[mt][3] = AsH[(mr + 8) * AW + kp + 4];
                al[mt][0] = AsL[mr * AW + kp];
                al[mt][1] = AsL[(mr + 8) * AW + kp];
                al[mt][2] = AsL[mr * AW + kp + 4];
                al[mt][3] = AsL[(mr + 8) * AW + kp + 4];
            }
#pragma unroll
            for (int nt = 0; nt < 8; nt++) {
                const int nc = wn * 64 + nt * 8 + g;
                uint32_t bh0 = BsH[kp * BW + nc];
                uint32_t bh1 = BsH[(kp + 4) * BW + nc];
                uint32_t bl0 = BsL[kp * BW + nc];
                uint32_t bl1 = BsL[(kp + 4) * BW + nc];
#pragma unroll
                for (int mt = 0; mt < 2; mt++) {
                    mma_bf16(c[mt][nt], ah[mt], bh0, bh1);
                    mma_bf16(c[mt][nt], ah[mt], bl0, bl1);
                    mma_bf16(c[mt][nt], al[mt], bh0, bh1);
                }
            }
        }
        if (t + 1 < nT) cp_wait0();
        __syncthreads();
    }

    // ---- epilogue: bias + relu
#pragma unroll
    for (int mt = 0; mt < 2; mt++) {
        const int r0 = bm + wm * 32 + mt * 16 + g;
        const int r1 = r0 + 8;
#pragma unroll
        for (int nt = 0; nt < 8; nt++) {
            const int col = bn + wn * 64 + nt * 8 + 2 * tig;
            if (col >= N) continue;
            const bool pair = (col + 1 < N);
            const float b0 = bias[col];
            const float b1 = pair ? bias[col + 1] : 0.f;
            float v0 = fmaxf(c[mt][nt][0] + b0, 0.f);
            float v1 = fmaxf(c[mt][nt][1] + b1, 0.f);
            float v2 = fmaxf(c[mt][nt][2] + b0, 0.f);
            float v3 = fmaxf(c[mt][nt][3] + b1, 0.f);
            if (OUT_SPLIT) {
                uint32_t hi, lo;
                if (r0 < M) {
                    split2(v0, v1, hi, lo);
                    Ch[(size_t)r0 * ldcw + (col >> 1)] = hi;
                    Cl[(size_t)r0 * ldcw + (col >> 1)] = lo;
                }
                if (r1 < M) {
                    split2(v2, v3, hi, lo);
                    Ch[(size_t)r1 * ldcw + (col >> 1)] = hi;
                    Cl[(size_t)r1 * ldcw + (col >> 1)] = lo;
                }
            } else {
                if (r0 < M) {
                    if (pair) *(float2*)(C + (size_t)r0 * ldc + col) = make_float2(v0, v1);
                    else      C[(size_t)r0 * ldc + col] = v0;
                }
                if (r1 < M) {
                    if (pair) *(float2*)(C + (size_t)r1 * ldc + col) = make_float2(v2, v3);
                    else      C[(size_t)r1 * ldc + col] = v2;
                }
            }
        }
    }
}

// ---------------- per-node softmax over 100 compact logits ------------------
__global__ void softmax_kernel() {
    int node = (blockIdx.x * blockDim.x + threadIdx.x) >> 5;
    int lane = threadIdx.x & 31;
    if (node >= NN) return;
    const float* lp = g_logits + (size_t)node * KPG;
    float v[4];
    float mx = -1e30f;
#pragma unroll
    for (int i = 0; i < 4; i++) {
        int c = lane + 32 * i;
        v[i] = (c < KPG) ? lp[c] : -1e30f;
        mx = fmaxf(mx, v[i]);
    }
#pragma unroll
    for (int o = 16; o; o >>= 1) mx = fmaxf(mx, __shfl_xor_sync(0xFFFFFFFFu, mx, o));
    float sum = 0.f;
#pragma unroll
    for (int i = 0; i < 4; i++) {
        int c = lane + 32 * i;
        v[i] = (c < KPG) ? expf(v[i] - mx) : 0.f;
        sum += v[i];
    }
#pragma unroll
    for (int o = 16; o; o >>= 1) sum += __shfl_xor_sync(0xFFFFFFFFu, sum, o);
    float inv = 1.f / sum;
    float* ap = g_assign + (size_t)node * KPG;
#pragma unroll
    for (int i = 0; i < 4; i++) {
        int c = lane + 32 * i;
        if (c < KPG) ap[c] = v[i] * inv;
    }
}

// ---------------- gather: tmp[n] = sum_{s in N(n)} assign[s] ----------------
__global__ void gather_tmp_kernel() {
    int n = (blockIdx.x * blockDim.x + threadIdx.x) >> 5;
    int lane = threadIdx.x & 31;
    if (n >= NN) return;
    int dg = min(g_degi[n], CAP);
    const int* nb = g_nbr + (size_t)n * CAP;
    float a0 = 0.f, a1 = 0.f, a2 = 0.f, a3 = 0.f;
    for (int j = 0; j < dg; j++) {
        const float* ar = g_assign + (size_t)nb[j] * KPG;
        a0 += ar[lane];
        a1 += ar[lane + 32];
        a2 += ar[lane + 64];
        if (lane < 4) a3 += ar[lane + 96];
    }
    float* tp = g_tmp + (size_t)n * KPG;
    tp[lane]      = a0;
    tp[lane + 32] = a1;
    tp[lane + 64] = a2;
    if (lane < 4) tp[lane + 96] = a3;
}

// ---------------- h_pool: per graph, assign_b^T [2000x100] @ feat_b [2000x128]
__global__ __launch_bounds__(256)
void hpool_kernel(float* __restrict__ out) {   // out = d_out + ADJ_ELEMS
    const int g = blockIdx.y;
    const int split = blockIdx.x;
    const int kbeg = split * (NPG / 8);
    const int kend = kbeg + (NPG / 8);
    const float* A = g_assign + (size_t)g * NPG * KPG;
    const float* F = g_feat + (size_t)g * NPG * DD;

    __shared__ float As[8][KPG];
    __shared__ float Fs[8][DD];
    const int tx = threadIdx.x & 15;
    const int ty = threadIdx.x >> 4;

    float acc[7][8];
#pragma unroll
    for (int i = 0; i < 7; i++)
#pragma unroll
        for (int j = 0; j < 8; j++) acc[i][j] = 0.f;

    for (int k0 = kbeg; k0 < kend; k0 += 8) {
        int kc = min(8, kend - k0);
        for (int idx = threadIdx.x; idx < 8 * KPG; idx += 256) {
            int r = idx / KPG, c = idx % KPG;
            As[r][c] = (r < kc) ? A[(size_t)(k0 + r) * KPG + c] : 0.f;
        }
        for (int idx = threadIdx.x; idx < 8 * DD; idx += 256) {
            int r = idx >> 7, c = idx & 127;
            Fs[r][c] = (r < kc) ? F[(size_t)(k0 + r) * DD + c] : 0.f;
        }
        __syncthreads();
#pragma unroll
        for (int k = 0; k < 8; k++) {
            float a[7], f[8];
#pragma unroll
            for (int i = 0; i < 7; i++) {
                int c = ty + 16 * i;
                a[i] = (c < KPG) ? As[k][c] : 0.f;
            }
#pragma unroll
            for (int j = 0; j < 8; j++) f[j] = Fs[k][tx + 16 * j];
#pragma unroll
            for (int i = 0; i < 7; i++)
#pragma unroll
                for (int j = 0; j < 8; j++) acc[i][j] += a[i] * f[j];
        }
        __syncthreads();
    }
#pragma unroll
    for (int i = 0; i < 7; i++) {
        int c = ty + 16 * i;
        if (c >= KPG) continue;
#pragma unroll
        for (int j = 0; j < 8; j++) {
            int d = tx + 16 * j;
            atomicAdd(&out[(size_t)(g * KPG + c) * DD + d], acc[i][j]);
        }
    }
}

// ---------------- adj: per graph, assign_b^T [2000x100] @ tmp_b [2000x100] --
__global__ __launch_bounds__(256)
void adj_kernel(float* __restrict__ out) {
    const int g = blockIdx.y;
    const int split = blockIdx.x;
    const int kbeg = split * (NPG / 8);
    const int kend = kbeg + (NPG / 8);
    const float* A = g_assign + (size_t)g * NPG * KPG;
    const float* T = g_tmp + (size_t)g * NPG * KPG;

    __shared__ float As[8][KPG];
    __shared__ float Ts[8][KPG];
    const int tx = threadIdx.x & 15;
    const int ty = threadIdx.x >> 4;

    float acc[7][7];
#pragma unroll
    for (int i = 0; i < 7; i++)
#pragma unroll
        for (int j = 0; j < 7; j++) acc[i][j] = 0.f;

    for (int k0 = kbeg; k0 < kend; k0 += 8) {
        int kc = min(8, kend - k0);
        for (int idx = threadIdx.x; idx < 8 * KPG; idx += 256) {
            int r = idx / KPG, c = idx % KPG;
            As[r][c] = (r < kc) ? A[(size_t)(k0 + r) * KPG + c] : 0.f;
            Ts[r][c] = (r < kc) ? T[(size_t)(k0 + r) * KPG + c] : 0.f;
        }
        __syncthreads();
#pragma unroll
        for (int k = 0; k < 8; k++) {
            float a[7], b[7];
#pragma unroll
            for (int i = 0; i < 7; i++) {
                int c = ty + 16 * i;
                a[i] = (c < KPG) ? As[k][c] : 0.f;
            }
#pragma unroll
            for (int j = 0; j < 7; j++) {
                int c = tx + 16 * j;
                b[j] = (c < KPG) ? Ts[k][c] : 0.f;
            }
#pragma unroll
            for (int i = 0; i < 7; i++)
#pragma unroll
                for (int j = 0; j < 7; j++) acc[i][j] += a[i] * b[j];
        }
        __syncthreads();
    }
#pragma unroll
    for (int i = 0; i < 7; i++) {
        int c1 = ty + 16 * i;
        if (c1 >= KPG) continue;
#pragma unroll
        for (int j = 0; j < 7; j++) {
            int c2 = tx + 16 * j;
            if (c2 >= KPG) continue;
            atomicAdd(&out[(size_t)(g * KPG + c1) * KK + (g * KPG + c2)], acc[i][j]);
        }
    }
}

// ---------------- launch ----------------------------------------------------
extern "C" void kernel_launch(void* const* d_in, const int* in_sizes, int n_in,
                              void* d_out, int out_size) {
    const float* h   = (const float*)d_in[0];
    const int*   src = (const int*)d_in[1];
    const int*   dst = (const int*)d_in[2];
    const float* W1f = (const float*)d_in[3];
    const float* b1f = (const float*)d_in[4];
    const float* W2f = (const float*)d_in[5];
    const float* b2f = (const float*)d_in[6];
    const float* W1p = (const float*)d_in[7];
    const float* b1p = (const float*)d_in[8];
    const float* W2p = (const float*)d_in[9];
    const float* b2p = (const float*)d_in[10];
    float* out = (float*)d_out;

    uint32_t *xh, *xl, *t1h, *t1l, *x2h, *x2l;
    uint32_t *w1fh, *w1fl, *w2fh, *w2fl, *w1ph, *w1pl, *w2ph, *w2pl;
    float *feat, *logits;
    int* degi;
    cudaGetSymbolAddress((void**)&xh,   g_xh);
    cudaGetSymbolAddress((void**)&xl,   g_xl);
    cudaGetSymbolAddress((void**)&t1h,  g_t1h);
    cudaGetSymbolAddress((void**)&t1l,  g_t1l);
    cudaGetSymbolAddress((void**)&x2h,  g_x2h);
    cudaGetSymbolAddress((void**)&x2l,  g_x2l);
    cudaGetSymbolAddress((void**)&w1fh, g_w1fh);
    cudaGetSymbolAddress((void**)&w1fl, g_w1fl);
    cudaGetSymbolAddress((void**)&w2fh, g_w2fh);
    cudaGetSymbolAddress((void**)&w2fl, g_w2fl);
    cudaGetSymbolAddress((void**)&w1ph, g_w1ph);
    cudaGetSymbolAddress((void**)&w1pl, g_w1pl);
    cudaGetSymbolAddress((void**)&w2ph, g_w2ph);
    cudaGetSymbolAddress((void**)&w2pl, g_w2pl);
    cudaGetSymbolAddress((void**)&feat,   g_feat);
    cudaGetSymbolAddress((void**)&logits, g_logits);
    cudaGetSymbolAddress((void**)&degi,   g_degi);

    cudaFuncSetAttribute(mma_gemm<true>,  cudaFuncAttributeMaxDynamicSharedMemorySize, GEMM_SMEM);
    cudaFuncSetAttribute(mma_gemm<false>, cudaFuncAttributeMaxDynamicSharedMemorySize, GEMM_SMEM);

    // zero output + degree counters
    zero_f<<<1024, 256>>>(out, (size_t)out_size);
    zero_i<<<128, 256>>>(degi, (size_t)NN);

    // neighbor buckets
    fill_bucket_kernel<<<(EE + 255) / 256, 256>>>(src, dst);

    // weight splits (B-format)
    split_B_kernel<<<(DD / 2 * DD + 255) / 256, 256>>>(W1f, w1fh, w1fl, DD / 2, DD);
    split_B_kernel<<<(DD / 2 * DD + 255) / 256, 256>>>(W2f, w2fh, w2fl, DD / 2, DD);
    split_B_kernel<<<(DD / 2 * KK + 255) / 256, 256>>>(W1p, w1ph, w1pl, DD / 2, KK);
    split_B_kernel<<<(KK / 2 * KK + 255) / 256, 256>>>(W2p, w2ph, w2pl, KK / 2, KK);

    // x = h + mean-aggregated neighbors, packed bf16 hi/lo
    gather_x_kernel<<<(NN * 32 + 255) / 256, 256>>>(h);

    // feat branch
    mma_gemm<true><<<dim3(250, 1, 1), 256, GEMM_SMEM>>>(
        xh, xl, w1fh, w1fl, b1f, nullptr, t1h, t1l,
        NN, DD, DD, DD / 2, DD, 0, DD / 2, 0, 0, 0, 0);
    mma_gemm<false><<<dim3(250, 1, 1), 256, GEMM_SMEM>>>(
        t1h, t1l, w2fh, w2fl, b2f, feat, nullptr, nullptr,
        NN, DD, DD, DD / 2, DD, DD, 0, 0, 0, 0, 0);

    // pool branch layer 1: 32000 x 1600 x 128, split output
    mma_gemm<true><<<dim3(250, 13, 1), 256, GEMM_SMEM>>>(
        xh, xl, w1ph, w1pl, b1p, nullptr, x2h, x2l,
        NN, KK, DD, DD / 2, KK, 0, KK / 2, 0, 0, 0, 0);

    // pool branch layer 2: per graph [2000,1600] @ [1600,100] -> logits
    mma_gemm<false><<<dim3(16, 1, NB), 256, GEMM_SMEM>>>(
        x2h, x2l, w2ph, w2pl, b2p, logits, nullptr, nullptr,
        NPG, KPG, KK, KK / 2, KK, KPG, 0,
        (long)NPG * (KK / 2), (long)KPG, (long)NPG * KPG, (long)KPG);

    // masked softmax
    softmax_kernel<<<(NN * 32 + 255) / 256, 256>>>();

    // tmp = gather-sum of assign over incoming edges
    gather_tmp_kernel<<<(NN * 32 + 255) / 256, 256>>>();

    // h_pool and adj (block-diagonal), atomic split-K into pre-zeroed d_out
    hpool_kernel<<<dim3(8, NB), 256>>>(out + ADJ_ELEMS);
    adj_kernel<<<dim3(8, NB), 256>>>(out);
}

// round 8
// speedup vs baseline: 1.6004x; 1.0976x over previous
#include <cuda_runtime.h>
#include <cuda_bf16.h>
#include <math.h>
#include <cstdint>
#include <cstddef>

// Problem constants
static constexpr int NN   = 32000;     // nodes
static constexpr int NB   = 16;        // graphs
static constexpr int NPG  = 2000;      // nodes per graph
static constexpr int KK   = 1600;      // clusters total
static constexpr int KPG  = 100;       // clusters per graph
static constexpr int DD   = 128;       // feature dim
static constexpr int EE   = 512000;    // edges
static constexpr int ADJ_ELEMS = KK * KK;
static constexpr int CAP  = 96;        // neighbor bucket capacity

// ---------------- scratch (__device__ globals) ------------------------------
// packed bf16x2 hi/lo operand buffers (A-format: [rows][K/2] words)
__device__ uint32_t g_xh[(size_t)NN * DD / 2];
__device__ uint32_t g_xl[(size_t)NN * DD / 2];
__device__ uint32_t g_t1h[(size_t)NN * DD / 2];
__device__ uint32_t g_t1l[(size_t)NN * DD / 2];
__device__ uint32_t g_x2h[(size_t)NN * KK / 2];
__device__ uint32_t g_x2l[(size_t)NN * KK / 2];
// transposed packed weights (A-format too): [N][K/2] words
__device__ uint32_t g_w1fh[DD * DD / 2];
__device__ uint32_t g_w1fl[DD * DD / 2];
__device__ uint32_t g_w2fh[DD * DD / 2];
__device__ uint32_t g_w2fl[DD * DD / 2];
__device__ uint32_t g_w1ph[(size_t)KK * DD / 2];
__device__ uint32_t g_w1pl[(size_t)KK * DD / 2];
__device__ uint32_t g_w2ph[(size_t)KK * KK / 2];
__device__ uint32_t g_w2pl[(size_t)KK * KK / 2];
// fp32 buffers
__device__ float g_feat[(size_t)NN * DD];
__device__ float g_logits[(size_t)NN * KPG];
__device__ float g_assign[(size_t)NN * KPG];
__device__ float g_tmp[(size_t)NN * KPG];
__device__ int   g_degi[NN];
__device__ int   g_nbr[(size_t)NN * CAP];

// ---------------- helpers ----------------------------------------------------
__device__ __forceinline__ uint32_t smem_u32(const void* p) {
    uint32_t a;
    asm("{ .reg .u64 t; cvta.to.shared.u64 t, %1; cvt.u32.u64 %0, t; }" : "=r"(a) : "l"(p));
    return a;
}
__device__ __forceinline__ void cp16(uint32_t saddr, const void* g) {
    asm volatile("cp.async.ca.shared.global [%0], [%1], 16;" :: "r"(saddr), "l"(g) : "memory");
}
__device__ __forceinline__ void cp_commit() {
    asm volatile("cp.async.commit_group;" ::: "memory");
}
__device__ __forceinline__ void cp_wait0() {
    asm volatile("cp.async.wait_group 0;" ::: "memory");
}
__device__ __forceinline__ void cp_wait1() {
    asm volatile("cp.async.wait_group 1;" ::: "memory");
}
__device__ __forceinline__ void ldm_x4(uint32_t* r, uint32_t saddr) {
    asm volatile("ldmatrix.sync.aligned.m8n8.x4.shared.b16 {%0,%1,%2,%3}, [%4];"
                 : "=r"(r[0]), "=r"(r[1]), "=r"(r[2]), "=r"(r[3]) : "r"(saddr));
}
__device__ __forceinline__ void mma_bf16(float* c, const uint32_t* a,
                                         uint32_t b0, uint32_t b1) {
    asm volatile(
        "mma.sync.aligned.m16n8k16.row.col.f32.bf16.bf16.f32 "
        "{%0,%1,%2,%3}, {%4,%5,%6,%7}, {%8,%9}, {%0,%1,%2,%3};"
        : "+f"(c[0]), "+f"(c[1]), "+f"(c[2]), "+f"(c[3])
        : "r"(a[0]), "r"(a[1]), "r"(a[2]), "r"(a[3]), "r"(b0), "r"(b1));
}
__device__ __forceinline__ void split2(float f0, float f1, uint32_t& hi, uint32_t& lo) {
    __nv_bfloat16 h0 = __float2bfloat16(f0);
    __nv_bfloat16 h1 = __float2bfloat16(f1);
    __nv_bfloat16 l0 = __float2bfloat16(f0 - __bfloat162float(h0));
    __nv_bfloat16 l1 = __float2bfloat16(f1 - __bfloat162float(h1));
    __nv_bfloat162 hp = __nv_bfloat162(h0, h1);
    __nv_bfloat162 lp = __nv_bfloat162(l0, l1);
    hi = *reinterpret_cast<uint32_t*>(&hp);
    lo = *reinterpret_cast<uint32_t*>(&lp);
}

// ---------------- zero helpers ----------------------------------------------
__global__ void zero_f(float* __restrict__ p, size_t n) {
    size_t i = (size_t)blockIdx.x * blockDim.x + threadIdx.x;
    size_t st = (size_t)gridDim.x * blockDim.x;
    for (; i < n; i += st) p[i] = 0.f;
}
__global__ void zero_i(int* __restrict__ p, size_t n) {
    size_t i = (size_t)blockIdx.x * blockDim.x + threadIdx.x;
    size_t st = (size_t)gridDim.x * blockDim.x;
    for (; i < n; i += st) p[i] = 0;
}

// ---------------- bucket fill: per-dst neighbor lists ------------------------
__global__ void fill_bucket_kernel(const int* __restrict__ src,
                                   const int* __restrict__ dst) {
    int e = blockIdx.x * blockDim.x + threadIdx.x;
    if (e >= EE) return;
    int d = dst[e];
    int p = atomicAdd(&g_degi[d], 1);
    if (p < CAP) g_nbr[(size_t)d * CAP + p] = src[e];
}

// ---------------- weight split+transpose: Bt[n][kp] = pack(B[2kp][n], B[2kp+1][n])
__global__ void split_BT_kernel(const float* __restrict__ B,
                                uint32_t* __restrict__ Bh, uint32_t* __restrict__ Bl,
                                int K2, int N) {
    int idx = blockIdx.x * blockDim.x + threadIdx.x;
    if (idx >= N * K2) return;
    int n = idx / K2, kp = idx - n * K2;
    float f0 = B[(size_t)(2 * kp) * N + n];
    float f1 = B[(size_t)(2 * kp + 1) * N + n];
    uint32_t hi, lo;
    split2(f0, f1, hi, lo);
    Bh[idx] = hi;
    Bl[idx] = lo;
}

// ---------------- gather: x = h + mean nbr, write packed bf16 hi/lo ---------
__global__ void gather_x_kernel(const float* __restrict__ h) {
    int n = (blockIdx.x * blockDim.x + threadIdx.x) >> 5;
    int lane = threadIdx.x & 31;
    if (n >= NN) return;
    int dg = min(g_degi[n], CAP);
    const int* nb = g_nbr + (size_t)n * CAP;
    float a0 = 0.f, a1 = 0.f, a2 = 0.f, a3 = 0.f;
    for (int j = 0; j < dg; j++) {
        float4 v = ((const float4*)(h + (size_t)nb[j] * DD))[lane];
        a0 += v.x; a1 += v.y; a2 += v.z; a3 += v.w;
    }
    float inv = 1.f / fmaxf((float)dg, 1.f);
    float4 hn = ((const float4*)(h + (size_t)n * DD))[lane];
    float v0 = hn.x + a0 * inv;
    float v1 = hn.y + a1 * inv;
    float v2 = hn.z + a2 * inv;
    float v3 = hn.w + a3 * inv;
    uint32_t hi0, lo0, hi1, lo1;
    split2(v0, v1, hi0, lo0);
    split2(v2, v3, hi1, lo1);
    size_t base = (size_t)n * (DD / 2) + lane * 2;
    g_xh[base] = hi0; g_xh[base + 1] = hi1;
    g_xl[base] = lo0; g_xl[base + 1] = lo1;
}

// ---------------- tensor-core bf16 split GEMM --------------------------------
// A packed [M][K/2] hi/lo words; B packed [N][K/2] hi/lo words (both A-format).
// C = relu(A@B^T + bias); OUT_SPLIT writes packed hi/lo, else fp32.
// 128x128 CTA tile, BK=32 (16 kpairs), 256 thr = 8 warps, warp tile 32x64.
// 3-stage cp.async pipeline; all fragments via ldmatrix.x4 (conflict-free
// with 20-word row stride).
static constexpr int AW = 20;               // smem row stride (words)
static constexpr int OFF_AL = 128 * AW;     // 2560
static constexpr int OFF_BH = 2 * 128 * AW; // 5120
static constexpr int OFF_BL = 3 * 128 * AW; // 7680
static constexpr int STAGEW = 4 * 128 * AW; // 10240 words = 40960 B
static constexpr int GEMM_SMEM = 3 * STAGEW * 4;  // 122880 B

template<bool OUT_SPLIT>
__global__ __launch_bounds__(256)
void mma_gemm(const uint32_t* __restrict__ Ahg, const uint32_t* __restrict__ Alg,
              const uint32_t* __restrict__ Bhg, const uint32_t* __restrict__ Blg,
              const float* __restrict__ bias,
              float* __restrict__ C, uint32_t* __restrict__ Ch, uint32_t* __restrict__ Cl,
              int M, int N, int K, int ldaw, int ldbw, int ldc, int ldcw,
              long zsAw, long zsBw, long zsC, long zsBias) {
    extern __shared__ uint32_t sm[];
    const uint32_t sbase = smem_u32(sm);

    Ahg  += (size_t)blockIdx.z * zsAw;
    Alg  += (size_t)blockIdx.z * zsAw;
    Bhg  += (size_t)blockIdx.z * zsBw;
    Blg  += (size_t)blockIdx.z * zsBw;
    bias += (size_t)blockIdx.z * zsBias;
    if (!OUT_SPLIT) C += (size_t)blockIdx.z * zsC;
    else { Ch += (size_t)blockIdx.z * zsC; Cl += (size_t)blockIdx.z * zsC; }

    const int tid  = threadIdx.x;
    const int wid  = tid >> 5;
    const int lane = tid & 31;
    const int wm   = wid & 3;
    const int wn   = wid >> 2;
    const int g    = lane >> 2;
    const int tig  = lane & 3;
    const int bm   = blockIdx.x * 128;
    const int bn   = blockIdx.y * 128;

    // loader mapping: row am (0..127), 8-word chunk aq
    const int am = tid >> 1;
    const int aq = (tid & 1) * 8;
    const int arow = min(bm + am, M - 1);
    const int brow = min(bn + am, N - 1);
    const uint32_t* ApH = Ahg + (size_t)arow * ldaw + aq;
    const uint32_t* ApL = Alg + (size_t)arow * ldaw + aq;
    const uint32_t* BpH = Bhg + (size_t)brow * ldbw + aq;
    const uint32_t* BpL = Blg + (size_t)brow * ldbw + aq;
    const uint32_t aSm = (uint32_t)(am * AW + aq) * 4;

    // ldmatrix per-thread row/word select
    const int lrow = (lane < 16) ? lane : (lane - 16);
    const int lsel = (lane >= 16) ? 4 : 0;

    float c[2][8][4];
#pragma unroll
    for (int mt = 0; mt < 2; mt++)
#pragma unroll
        for (int nt = 0; nt < 8; nt++)
#pragma unroll
            for (int q = 0; q < 4; q++) c[mt][nt][q] = 0.f;

    auto issue = [&](int t, int buf) {
        const int kpt = t * 16;
        const uint32_t sa = sbase + (uint32_t)(buf * STAGEW) * 4 + aSm;
        cp16(sa,                    ApH + kpt);
        cp16(sa + 16,               ApH + kpt + 4);
        cp16(sa + OFF_AL * 4,       ApL + kpt);
        cp16(sa + OFF_AL * 4 + 16,  ApL + kpt + 4);
        const uint32_t sb = sa + OFF_BH * 4;
        cp16(sb,                              BpH + kpt);
        cp16(sb + 16,                         BpH + kpt + 4);
        cp16(sb + (OFF_BL - OFF_BH) * 4,      BpL + kpt);
        cp16(sb + (OFF_BL - OFF_BH) * 4 + 16, BpL + kpt + 4);
    };

    const int nT = K >> 5;
    issue(0, 0); cp_commit();
    issue(1, 1); cp_commit();

    for (int t = 0; t < nT; t++) {
        if (t + 1 < nT) cp_wait1(); else cp_wait0();
        __syncthreads();

        const int buf = t % 3;
        const uint32_t stage = sbase + (uint32_t)(buf * STAGEW) * 4;
        const uint32_t aBase = stage + (uint32_t)((wm * 32 + lrow) * AW + lsel) * 4;
        const uint32_t bBase = stage + (uint32_t)(OFF_BH + (wn * 64 + lrow) * AW + lsel) * 4;

#pragma unroll
        for (int ks = 0; ks < 2; ks++) {
            const uint32_t ko = (uint32_t)(ks * 8) * 4;
            uint32_t ah[2][4], al[2][4];
#pragma unroll
            for (int mt = 0; mt < 2; mt++) {
                const uint32_t ao = aBase + (uint32_t)(mt * 16 * AW) * 4 + ko;
                ldm_x4(ah[mt], ao);
                ldm_x4(al[mt], ao + OFF_AL * 4);
            }
#pragma unroll
            for (int ng = 0; ng < 4; ng++) {
                uint32_t bh[4], bl[4];
                const uint32_t bo = bBase + (uint32_t)(ng * 16 * AW) * 4 + ko;
                ldm_x4(bh, bo);
                ldm_x4(bl, bo + (OFF_BL - OFF_BH) * 4);
#pragma unroll
                for (int sub = 0; sub < 2; sub++) {
                    const int nt = ng * 2 + sub;
#pragma unroll
                    for (int mt = 0; mt < 2; mt++) {
                        mma_bf16(c[mt][nt], ah[mt], bh[sub], bh[2 + sub]);
                        mma_bf16(c[mt][nt], ah[mt], bl[sub], bl[2 + sub]);
                        mma_bf16(c[mt][nt], al[mt], bh[sub], bh[2 + sub]);
                    }
                }
            }
        }
        if (t + 2 < nT) { issue(t + 2, (t + 2) % 3); cp_commit(); }
    }

    // ---- epilogue: bias + relu
#pragma unroll
    for (int mt = 0; mt < 2; mt++) {
        const int r0 = bm + wm * 32 + mt * 16 + g;
        const int r1 = r0 + 8;
#pragma unroll
        for (int nt = 0; nt < 8; nt++) {
            const int col = bn + wn * 64 + nt * 8 + 2 * tig;
            if (col >= N) continue;
            const bool pair = (col + 1 < N);
            const float b0 = bias[col];
            const float b1 = pair ? bias[col + 1] : 0.f;
            float v0 = fmaxf(c[mt][nt][0] + b0, 0.f);
            float v1 = fmaxf(c[mt][nt][1] + b1, 0.f);
            float v2 = fmaxf(c[mt][nt][2] + b0, 0.f);
            float v3 = fmaxf(c[mt][nt][3] + b1, 0.f);
            if (OUT_SPLIT) {
                uint32_t hi, lo;
                if (r0 < M) {
                    split2(v0, v1, hi, lo);
                    Ch[(size_t)r0 * ldcw + (col >> 1)] = hi;
                    Cl[(size_t)r0 * ldcw + (col >> 1)] = lo;
                }
                if (r1 < M) {
                    split2(v2, v3, hi, lo);
                    Ch[(size_t)r1 * ldcw + (col >> 1)] = hi;
                    Cl[(size_t)r1 * ldcw + (col >> 1)] = lo;
                }
            } else {
                if (r0 < M) {
                    if (pair) *(float2*)(C + (size_t)r0 * ldc + col) = make_float2(v0, v1);
                    else      C[(size_t)r0 * ldc + col] = v0;
                }
                if (r1 < M) {
                    if (pair) *(float2*)(C + (size_t)r1 * ldc + col) = make_float2(v2, v3);
                    else      C[(size_t)r1 * ldc + col] = v2;
                }
            }
        }
    }
}

// ---------------- per-node softmax over 100 compact logits ------------------
__global__ void softmax_kernel() {
    int node = (blockIdx.x * blockDim.x + threadIdx.x) >> 5;
    int lane = threadIdx.x & 31;
    if (node >= NN) return;
    const float* lp = g_logits + (size_t)node * KPG;
    float v[4];
    float mx = -1e30f;
#pragma unroll
    for (int i = 0; i < 4; i++) {
        int c = lane + 32 * i;
        v[i] = (c < KPG) ? lp[c] : -1e30f;
        mx = fmaxf(mx, v[i]);
    }
#pragma unroll
    for (int o = 16; o; o >>= 1) mx = fmaxf(mx, __shfl_xor_sync(0xFFFFFFFFu, mx, o));
    float sum = 0.f;
#pragma unroll
    for (int i = 0; i < 4; i++) {
        int c = lane + 32 * i;
        v[i] = (c < KPG) ? expf(v[i] - mx) : 0.f;
        sum += v[i];
    }
#pragma unroll
    for (int o = 16; o; o >>= 1) sum += __shfl_xor_sync(0xFFFFFFFFu, sum, o);
    float inv = 1.f / sum;
    float* ap = g_assign + (size_t)node * KPG;
#pragma unroll
    for (int i = 0; i < 4; i++) {
        int c = lane + 32 * i;
        if (c < KPG) ap[c] = v[i] * inv;
    }
}

// ---------------- gather: tmp[n] = sum_{s in N(n)} assign[s] ----------------
__global__ void gather_tmp_kernel() {
    int n = (blockIdx.x * blockDim.x + threadIdx.x) >> 5;
    int lane = threadIdx.x & 31;
    if (n >= NN) return;
    int dg = min(g_degi[n], CAP);
    const int* nb = g_nbr + (size_t)n * CAP;
    float a0 = 0.f, a1 = 0.f, a2 = 0.f, a3 = 0.f;
    for (int j = 0; j < dg; j++) {
        const float* ar = g_assign + (size_t)nb[j] * KPG;
        a0 += ar[lane];
        a1 += ar[lane + 32];
        a2 += ar[lane + 64];
        if (lane < 4) a3 += ar[lane + 96];
    }
    float* tp = g_tmp + (size_t)n * KPG;
    tp[lane]      = a0;
    tp[lane + 32] = a1;
    tp[lane + 64] = a2;
    if (lane < 4) tp[lane + 96] = a3;
}

// ---------------- h_pool: per graph, assign_b^T [2000x100] @ feat_b [2000x128]
__global__ __launch_bounds__(256)
void hpool_kernel(float* __restrict__ out) {   // out = d_out + ADJ_ELEMS
    const int g = blockIdx.y;
    const int split = blockIdx.x;
    const int kbeg = split * (NPG / 8);
    const int kend = kbeg + (NPG / 8);
    const float* A = g_assign + (size_t)g * NPG * KPG;
    const float* F = g_feat + (size_t)g * NPG * DD;

    __shared__ float As[8][KPG];
    __shared__ float Fs[8][DD];
    const int tx = threadIdx.x & 15;
    const int ty = threadIdx.x >> 4;

    float acc[7][8];
#pragma unroll
    for (int i = 0; i < 7; i++)
#pragma unroll
        for (int j = 0; j < 8; j++) acc[i][j] = 0.f;

    for (int k0 = kbeg; k0 < kend; k0 += 8) {
        int kc = min(8, kend - k0);
        for (int idx = threadIdx.x; idx < 8 * KPG; idx += 256) {
            int r = idx / KPG, c = idx % KPG;
            As[r][c] = (r < kc) ? A[(size_t)(k0 + r) * KPG + c] : 0.f;
        }
        for (int idx = threadIdx.x; idx < 8 * DD; idx += 256) {
            int r = idx >> 7, c = idx & 127;
            Fs[r][c] = (r < kc) ? F[(size_t)(k0 + r) * DD + c] : 0.f;
        }
        __syncthreads();
#pragma unroll
        for (int k = 0; k < 8; k++) {
            float a[7], f[8];
#pragma unroll
            for (int i = 0; i < 7; i++) {
                int c = ty + 16 * i;
                a[i] = (c < KPG) ? As[k][c] : 0.f;
            }
#pragma unroll
            for (int j = 0; j < 8; j++) f[j] = Fs[k][tx + 16 * j];
#pragma unroll
            for (int i = 0; i < 7; i++)
#pragma unroll
                for (int j = 0; j < 8; j++) acc[i][j] += a[i] * f[j];
        }
        __syncthreads();
    }
#pragma unroll
    for (int i = 0; i < 7; i++) {
        int c = ty + 16 * i;
        if (c >= KPG) continue;
#pragma unroll
        for (int j = 0; j < 8; j++) {
            int d = tx + 16 * j;
            atomicAdd(&out[(size_t)(g * KPG + c) * DD + d], acc[i][j]);
        }
    }
}

// ---------------- adj: per graph, assign_b^T [2000x100] @ tmp_b [2000x100] --
__global__ __launch_bounds__(256)
void adj_kernel(float* __restrict__ out) {
    const int g = blockIdx.y;
    const int split = blockIdx.x;
    const int kbeg = split * (NPG / 8);
    const int kend = kbeg + (NPG / 8);
    const float* A = g_assign + (size_t)g * NPG * KPG;
    const float* T = g_tmp + (size_t)g * NPG * KPG;

    __shared__ float As[8][KPG];
    __shared__ float Ts[8][KPG];
    const int tx = threadIdx.x & 15;
    const int ty = threadIdx.x >> 4;

    float acc[7][7];
#pragma unroll
    for (int i = 0; i < 7; i++)
#pragma unroll
        for (int j = 0; j < 7; j++) acc[i][j] = 0.f;

    for (int k0 = kbeg; k0 < kend; k0 += 8) {
        int kc = min(8, kend - k0);
        for (int idx = threadIdx.x; idx < 8 * KPG; idx += 256) {
            int r = idx / KPG, c = idx % KPG;
            As[r][c] = (r < kc) ? A[(size_t)(k0 + r) * KPG + c] : 0.f;
            Ts[r][c] = (r < kc) ? T[(size_t)(k0 + r) * KPG + c] : 0.f;
        }
        __syncthreads();
#pragma unroll
        for (int k = 0; k < 8; k++) {
            float a[7], b[7];
#pragma unroll
            for (int i = 0; i < 7; i++) {
                int c = ty + 16 * i;
                a[i] = (c < KPG) ? As[k][c] : 0.f;
            }
#pragma unroll
            for (int j = 0; j < 7; j++) {
                int c = tx + 16 * j;
                b[j] = (c < KPG) ? Ts[k][c] : 0.f;
            }
#pragma unroll
            for (int i = 0; i < 7; i++)
#pragma unroll
                for (int j = 0; j < 7; j++) acc[i][j] += a[i] * b[j];
        }
        __syncthreads();
    }
#pragma unroll
    for (int i = 0; i < 7; i++) {
        int c1 = ty + 16 * i;
        if (c1 >= KPG) continue;
#pragma unroll
        for (int j = 0; j < 7; j++) {
            int c2 = tx + 16 * j;
            if (c2 >= KPG) continue;
            atomicAdd(&out[(size_t)(g * KPG + c1) * KK + (g * KPG + c2)], acc[i][j]);
        }
    }
}

// ---------------- launch ----------------------------------------------------
extern "C" void kernel_launch(void* const* d_in, const int* in_sizes, int n_in,
                              void* d_out, int out_size) {
    const float* h   = (const float*)d_in[0];
    const int*   src = (const int*)d_in[1];
    const int*   dst = (const int*)d_in[2];
    const float* W1f = (const float*)d_in[3];
    const float* b1f = (const float*)d_in[4];
    const float* W2f = (const float*)d_in[5];
    const float* b2f = (const float*)d_in[6];
    const float* W1p = (const float*)d_in[7];
    const float* b1p = (const float*)d_in[8];
    const float* W2p = (const float*)d_in[9];
    const float* b2p = (const float*)d_in[10];
    float* out = (float*)d_out;

    uint32_t *xh, *xl, *t1h, *t1l, *x2h, *x2l;
    uint32_t *w1fh, *w1fl, *w2fh, *w2fl, *w1ph, *w1pl, *w2ph, *w2pl;
    float *feat, *logits;
    int* degi;
    cudaGetSymbolAddress((void**)&xh,   g_xh);
    cudaGetSymbolAddress((void**)&xl,   g_xl);
    cudaGetSymbolAddress((void**)&t1h,  g_t1h);
    cudaGetSymbolAddress((void**)&t1l,  g_t1l);
    cudaGetSymbolAddress((void**)&x2h,  g_x2h);
    cudaGetSymbolAddress((void**)&x2l,  g_x2l);
    cudaGetSymbolAddress((void**)&w1fh, g_w1fh);
    cudaGetSymbolAddress((void**)&w1fl, g_w1fl);
    cudaGetSymbolAddress((void**)&w2fh, g_w2fh);
    cudaGetSymbolAddress((void**)&w2fl, g_w2fl);
    cudaGetSymbolAddress((void**)&w1ph, g_w1ph);
    cudaGetSymbolAddress((void**)&w1pl, g_w1pl);
    cudaGetSymbolAddress((void**)&w2ph, g_w2ph);
    cudaGetSymbolAddress((void**)&w2pl, g_w2pl);
    cudaGetSymbolAddress((void**)&feat,   g_feat);
    cudaGetSymbolAddress((void**)&logits, g_logits);
    cudaGetSymbolAddress((void**)&degi,   g_degi);

    cudaFuncSetAttribute(mma_gemm<true>,  cudaFuncAttributeMaxDynamicSharedMemorySize, GEMM_SMEM);
    cudaFuncSetAttribute(mma_gemm<false>, cudaFuncAttributeMaxDynamicSharedMemorySize, GEMM_SMEM);

    // zero output + degree counters
    zero_f<<<1024, 256>>>(out, (size_t)out_size);
    zero_i<<<128, 256>>>(degi, (size_t)NN);

    // neighbor buckets
    fill_bucket_kernel<<<(EE + 255) / 256, 256>>>(src, dst);

    // weight split+transpose (A-format: [N][K/2])
    split_BT_kernel<<<(DD * DD / 2 + 255) / 256, 256>>>(W1f, w1fh, w1fl, DD / 2, DD);
    split_BT_kernel<<<(DD * DD / 2 + 255) / 256, 256>>>(W2f, w2fh, w2fl, DD / 2, DD);
    split_BT_kernel<<<((size_t)KK * DD / 2 + 255) / 256, 256>>>(W1p, w1ph, w1pl, DD / 2, KK);
    split_BT_kernel<<<((size_t)KK * KK / 2 + 255) / 256, 256>>>(W2p, w2ph, w2pl, KK / 2, KK);

    // x = h + mean-aggregated neighbors, packed bf16 hi/lo
    gather_x_kernel<<<(NN * 32 + 255) / 256, 256>>>(h);

    // feat branch
    mma_gemm<true><<<dim3(250, 1, 1), 256, GEMM_SMEM>>>(
        xh, xl, w1fh, w1fl, b1f, nullptr, t1h, t1l,
        NN, DD, DD, DD / 2, DD / 2, 0, DD / 2, 0, 0, 0, 0);
    mma_gemm<false><<<dim3(250, 1, 1), 256, GEMM_SMEM>>>(
        t1h, t1l, w2fh, w2fl, b2f, feat, nullptr, nullptr,
        NN, DD, DD, DD / 2, DD / 2, DD, 0, 0, 0, 0, 0);

    // pool branch layer 1: 32000 x 1600 x 128, split output
    mma_gemm<true><<<dim3(250, 13, 1), 256, GEMM_SMEM>>>(
        xh, xl, w1ph, w1pl, b1p, nullptr, x2h, x2l,
        NN, KK, DD, DD / 2, DD / 2, 0, KK / 2, 0, 0, 0, 0);

    // pool branch layer 2: per graph [2000,1600] @ [1600,100] -> logits
    mma_gemm<false><<<dim3(16, 1, NB), 256, GEMM_SMEM>>>(
        x2h, x2l, w2ph, w2pl, b2p, logits, nullptr, nullptr,
        NPG, KPG, KK, KK / 2, KK / 2, KPG, 0,
        (long)NPG * (KK / 2), (long)KPG * (KK / 2), (long)NPG * KPG, (long)KPG);

    // masked softmax
    softmax_kernel<<<(NN * 32 + 255) / 256, 256>>>();

    // tmp = gather-sum of assign over incoming edges
    gather_tmp_kernel<<<(NN * 32 + 255) / 256, 256>>>();

    // h_pool and adj (block-diagonal), atomic split-K into pre-zeroed d_out
    hpool_kernel<<<dim3(8, NB), 256>>>(out + ADJ_ELEMS);
    adj_kernel<<<dim3(8, NB), 256>>>(out);
}

// round 9
// speedup vs baseline: 2.0289x; 1.2678x over previous
#include <cuda_runtime.h>
#include <cuda_bf16.h>
#include <math.h>
#include <cstdint>
#include <cstddef>

// Problem constants
static constexpr int NN   = 32000;     // nodes
static constexpr int NB   = 16;        // graphs
static constexpr int NPG  = 2000;      // nodes per graph
static constexpr int KK   = 1600;      // clusters total
static constexpr int KPG  = 100;       // clusters per graph
static constexpr int DD   = 128;       // feature dim
static constexpr int EE   = 512000;    // edges
static constexpr int ADJ_ELEMS = KK * KK;
static constexpr int CAP  = 96;        // neighbor bucket capacity

// ---------------- scratch (__device__ globals) ------------------------------
__device__ uint32_t g_xh[(size_t)NN * DD / 2];
__device__ uint32_t g_xl[(size_t)NN * DD / 2];
__device__ uint32_t g_t1h[(size_t)NN * DD / 2];
__device__ uint32_t g_t1l[(size_t)NN * DD / 2];
// transposed packed weights (A-format): [N][K/2] words
__device__ uint32_t g_w1fh[DD * DD / 2];
__device__ uint32_t g_w1fl[DD * DD / 2];
__device__ uint32_t g_w2fh[DD * DD / 2];
__device__ uint32_t g_w2fl[DD * DD / 2];
__device__ uint32_t g_w1ph[(size_t)KK * DD / 2];
__device__ uint32_t g_w1pl[(size_t)KK * DD / 2];
__device__ uint32_t g_w2ph[(size_t)KK * KK / 2];
__device__ uint32_t g_w2pl[(size_t)KK * KK / 2];
// fp32 buffers
__device__ float g_feat[(size_t)NN * DD];
__device__ float g_logits[(size_t)NN * KPG];
__device__ float g_assign[(size_t)NN * KPG];
__device__ float g_tmp[(size_t)NN * KPG];
__device__ int   g_degi[NN];
__device__ int   g_nbr[(size_t)NN * CAP];

// ---------------- helpers ----------------------------------------------------
__device__ __forceinline__ uint32_t smem_u32(const void* p) {
    uint32_t a;
    asm("{ .reg .u64 t; cvta.to.shared.u64 t, %1; cvt.u32.u64 %0, t; }" : "=r"(a) : "l"(p));
    return a;
}
__device__ __forceinline__ void cp16(uint32_t saddr, const void* g) {
    asm volatile("cp.async.ca.shared.global [%0], [%1], 16;" :: "r"(saddr), "l"(g) : "memory");
}
__device__ __forceinline__ void cp_commit() {
    asm volatile("cp.async.commit_group;" ::: "memory");
}
__device__ __forceinline__ void cp_wait0() {
    asm volatile("cp.async.wait_group 0;" ::: "memory");
}
__device__ __forceinline__ void cp_wait1() {
    asm volatile("cp.async.wait_group 1;" ::: "memory");
}
__device__ __forceinline__ void ldm_x4(uint32_t* r, uint32_t saddr) {
    asm volatile("ldmatrix.sync.aligned.m8n8.x4.shared.b16 {%0,%1,%2,%3}, [%4];"
                 : "=r"(r[0]), "=r"(r[1]), "=r"(r[2]), "=r"(r[3]) : "r"(saddr));
}
__device__ __forceinline__ void mma_bf16(float* c, const uint32_t* a,
                                         uint32_t b0, uint32_t b1) {
    asm volatile(
        "mma.sync.aligned.m16n8k16.row.col.f32.bf16.bf16.f32 "
        "{%0,%1,%2,%3}, {%4,%5,%6,%7}, {%8,%9}, {%0,%1,%2,%3};"
        : "+f"(c[0]), "+f"(c[1]), "+f"(c[2]), "+f"(c[3])
        : "r"(a[0]), "r"(a[1]), "r"(a[2]), "r"(a[3]), "r"(b0), "r"(b1));
}
__device__ __forceinline__ void split2(float f0, float f1, uint32_t& hi, uint32_t& lo) {
    __nv_bfloat16 h0 = __float2bfloat16(f0);
    __nv_bfloat16 h1 = __float2bfloat16(f1);
    __nv_bfloat16 l0 = __float2bfloat16(f0 - __bfloat162float(h0));
    __nv_bfloat16 l1 = __float2bfloat16(f1 - __bfloat162float(h1));
    __nv_bfloat162 hp = __nv_bfloat162(h0, h1);
    __nv_bfloat162 lp = __nv_bfloat162(l0, l1);
    hi = *reinterpret_cast<uint32_t*>(&hp);
    lo = *reinterpret_cast<uint32_t*>(&lp);
}

// ---------------- zero helpers ----------------------------------------------
__global__ void zero_f(float* __restrict__ p, size_t n) {
    size_t i = (size_t)blockIdx.x * blockDim.x + threadIdx.x;
    size_t st = (size_t)gridDim.x * blockDim.x;
    for (; i < n; i += st) p[i] = 0.f;
}
__global__ void zero_i(int* __restrict__ p, size_t n) {
    size_t i = (size_t)blockIdx.x * blockDim.x + threadIdx.x;
    size_t st = (size_t)gridDim.x * blockDim.x;
    for (; i < n; i += st) p[i] = 0;
}

// ---------------- bucket fill: per-dst neighbor lists ------------------------
__global__ void fill_bucket_kernel(const int* __restrict__ src,
                                   const int* __restrict__ dst) {
    int e = blockIdx.x * blockDim.x + threadIdx.x;
    if (e >= EE) return;
    int d = dst[e];
    int p = atomicAdd(&g_degi[d], 1);
    if (p < CAP) g_nbr[(size_t)d * CAP + p] = src[e];
}

// ---------------- weight split+transpose: Bt[n][kp] = pack(B[2kp][n], B[2kp+1][n])
__global__ void split_BT_kernel(const float* __restrict__ B,
                                uint32_t* __restrict__ Bh, uint32_t* __restrict__ Bl,
                                int K2, int N) {
    int idx = blockIdx.x * blockDim.x + threadIdx.x;
    if (idx >= N * K2) return;
    int n = idx / K2, kp = idx - n * K2;
    float f0 = B[(size_t)(2 * kp) * N + n];
    float f1 = B[(size_t)(2 * kp + 1) * N + n];
    uint32_t hi, lo;
    split2(f0, f1, hi, lo);
    Bh[idx] = hi;
    Bl[idx] = lo;
}

// ---------------- gather: x = h + mean nbr, write packed bf16 hi/lo ---------
__global__ void gather_x_kernel(const float* __restrict__ h) {
    int n = (blockIdx.x * blockDim.x + threadIdx.x) >> 5;
    int lane = threadIdx.x & 31;
    if (n >= NN) return;
    int dg = min(g_degi[n], CAP);
    const int* nb = g_nbr + (size_t)n * CAP;
    float a0 = 0.f, a1 = 0.f, a2 = 0.f, a3 = 0.f;
    for (int j = 0; j < dg; j++) {
        float4 v = ((const float4*)(h + (size_t)nb[j] * DD))[lane];
        a0 += v.x; a1 += v.y; a2 += v.z; a3 += v.w;
    }
    float inv = 1.f / fmaxf((float)dg, 1.f);
    float4 hn = ((const float4*)(h + (size_t)n * DD))[lane];
    float v0 = hn.x + a0 * inv;
    float v1 = hn.y + a1 * inv;
    float v2 = hn.z + a2 * inv;
    float v3 = hn.w + a3 * inv;
    uint32_t hi0, lo0, hi1, lo1;
    split2(v0, v1, hi0, lo0);
    split2(v2, v3, hi1, lo1);
    size_t base = (size_t)n * (DD / 2) + lane * 2;
    g_xh[base] = hi0; g_xh[base + 1] = hi1;
    g_xl[base] = lo0; g_xl[base + 1] = lo1;
}

// ================= FUSED pool1+pool2 =========================================
// Per CTA: 128 rows of one graph.  x-tile resident in smem.
// Loop 25 chunks of 64 clusters:
//   stage1: x2c = relu(x @ W1p[:,chunk] + b1p)  -> split -> smem (no DRAM)
//   stage2: logits += x2c @ W2p[chunk, graph-block-100]
// All fragments via ldmatrix; cp.async streams W1p (double-buf) and W2p.
static constexpr int CW  = 64;            // chunk width
static constexpr int NCH = KK / CW;       // 25
static constexpr int S1  = 68;            // stride for 64-word rows (conflict-free)
static constexpr int S2  = 36;            // stride for 32-word rows
static constexpr int XT_H   = 0;
static constexpr int XT_L   = 128 * S1;               // 8704
static constexpr int W1_0   = 2 * 128 * S1;           // 17408
static constexpr int W1_BUF = 2 * 64 * S1;            // 8704 (hi+lo per buffer)
static constexpr int X2_H   = W1_0 + 2 * W1_BUF;      // 34816
static constexpr int X2_L   = X2_H + 128 * S2;        // 39424
static constexpr int W2_H   = X2_H + 2 * 128 * S2;    // 44032
static constexpr int W2_L   = W2_H + 128 * S2;        // 48640
static constexpr int FUSED_W    = W2_H + 2 * 128 * S2;  // 53248 words
static constexpr int FUSED_SMEM = FUSED_W * 4;          // 212992 B

__global__ __launch_bounds__(256)
void fused_pool_kernel(const float* __restrict__ b1p, const float* __restrict__ b2p) {
    extern __shared__ uint32_t sm[];
    const uint32_t sb = smem_u32(sm);
    const int mt128 = blockIdx.x;       // m-tile within graph (0..15)
    const int gz    = blockIdx.y;       // graph
    const int tid = threadIdx.x, wid = tid >> 5, lane = tid & 31;
    const int wm = wid & 3, wn = wid >> 2;
    const int lg = lane >> 2, tig = lane & 3;
    const int lrow = lane & 15;
    const int lsel = (lane >= 16) ? 4 : 0;

    // ---- prologue: load x-tile + W1p chunk0 (one cp.async group)
#pragma unroll
    for (int i = 0; i < 8; i++) {
        int q = tid + i * 256;                 // 0..2047
        int row = q >> 4, w = (q & 15) * 4;
        int grow = gz * NPG + min(mt128 * 128 + row, NPG - 1);
        cp16(sb + (uint32_t)(XT_H + row * S1 + w) * 4, g_xh + (size_t)grow * 64 + w);
        cp16(sb + (uint32_t)(XT_L + row * S1 + w) * 4, g_xl + (size_t)grow * 64 + w);
    }
#pragma unroll
    for (int i = 0; i < 4; i++) {
        int q = tid + i * 256;                 // 0..1023
        int row = q >> 4, w = (q & 15) * 4;
        cp16(sb + (uint32_t)(W1_0 + row * S1 + w) * 4,           g_w1ph + (size_t)row * 64 + w);
        cp16(sb + (uint32_t)(W1_0 + 64 * S1 + row * S1 + w) * 4, g_w1pl + (size_t)row * 64 + w);
    }
    cp_commit();
    cp_wait0();

    float c2[2][8][4];
#pragma unroll
    for (int mt = 0; mt < 2; mt++)
#pragma unroll
        for (int nt = 0; nt < 8; nt++)
#pragma unroll
            for (int q = 0; q < 4; q++) c2[mt][nt][q] = 0.f;

    for (int c = 0; c < NCH; c++) {
        const int buf = c & 1;
        if (c > 0) cp_wait0();             // W1p[c] arrived
        __syncthreads();                   // stage2(c-1) done; loads visible

        // ---- issue W2p[c] (commit first), then W1p[c+1]
#pragma unroll
        for (int i = 0; i < 4; i++) {
            int q = tid + i * 256;
            if (q < 800) {
                int row = q >> 3, w = (q & 7) * 4;
                const size_t go = (size_t)(gz * 100 + row) * 800 + c * 32 + w;
                cp16(sb + (uint32_t)(W2_H + row * S2 + w) * 4, g_w2ph + go);
                cp16(sb + (uint32_t)(W2_L + row * S2 + w) * 4, g_w2pl + go);
            }
        }
        cp_commit();                       // Gw2_c
        if (c + 1 < NCH) {
            const int nb = buf ^ 1;
#pragma unroll
            for (int i = 0; i < 4; i++) {
                int q = tid + i * 256;
                int row = q >> 4, w = (q & 15) * 4;
                const size_t go = (size_t)((c + 1) * 64 + row) * 64 + w;
                cp16(sb + (uint32_t)(W1_0 + nb * W1_BUF + row * S1 + w) * 4,           g_w1ph + go);
                cp16(sb + (uint32_t)(W1_0 + nb * W1_BUF + 64 * S1 + row * S1 + w) * 4, g_w1pl + go);
            }
            cp_commit();                   // Gw1_{c+1}
        }

        // ---- stage1: c1 = x @ W1p_chunk  (out 128x64, K=128)
        float c1[2][4][4];
#pragma unroll
        for (int mt = 0; mt < 2; mt++)
#pragma unroll
            for (int nt = 0; nt < 4; nt++)
#pragma unroll
                for (int q = 0; q < 4; q++) c1[mt][nt][q] = 0.f;

        const uint32_t w1b = (uint32_t)(W1_0 + buf * W1_BUF);
#pragma unroll
        for (int ks = 0; ks < 8; ks++) {
            const uint32_t ko = (uint32_t)(ks * 8 + lsel) * 4;
            uint32_t ah[2][4], al[2][4];
#pragma unroll
            for (int mt = 0; mt < 2; mt++) {
                const uint32_t ro = (uint32_t)((wm * 32 + mt * 16 + lrow) * S1) * 4;
                ldm_x4(ah[mt], sb + (uint32_t)(XT_H * 4) + ro + ko);
                ldm_x4(al[mt], sb + (uint32_t)(XT_L * 4) + ro + ko);
            }
#pragma unroll
            for (int ng = 0; ng < 2; ng++) {
                uint32_t bh[4], bl[4];
                const uint32_t ro = (uint32_t)((wn * 32 + ng * 16 + lrow) * S1) * 4;
                ldm_x4(bh, sb + w1b * 4 + ro + ko);
                ldm_x4(bl, sb + (w1b + 64 * S1) * 4 + ro + ko);
#pragma unroll
                for (int sub = 0; sub < 2; sub++) {
                    const int nt = ng * 2 + sub;
#pragma unroll
                    for (int mt = 0; mt < 2; mt++) {
                        mma_bf16(c1[mt][nt], ah[mt], bh[sub], bh[2 + sub]);
                        mma_bf16(c1[mt][nt], ah[mt], bl[sub], bl[2 + sub]);
                        mma_bf16(c1[mt][nt], al[mt], bh[sub], bh[2 + sub]);
                    }
                }
            }
        }

        // ---- bias + relu + split -> X2 smem
#pragma unroll
        for (int mt = 0; mt < 2; mt++) {
            const int r0 = wm * 32 + mt * 16 + lg;
#pragma unroll
            for (int nt = 0; nt < 4; nt++) {
                const int colL = wn * 32 + nt * 8 + 2 * tig;
                const int colG = c * 64 + colL;
                const float b0 = b1p[colG];
                const float b1 = b1p[colG + 1];
                float v0 = fmaxf(c1[mt][nt][0] + b0, 0.f);
                float v1 = fmaxf(c1[mt][nt][1] + b1, 0.f);
                float v2 = fmaxf(c1[mt][nt][2] + b0, 0.f);
                float v3 = fmaxf(c1[mt][nt][3] + b1, 0.f);
                uint32_t hi, lo;
                const int wi = colL >> 1;
                split2(v0, v1, hi, lo);
                sm[X2_H + r0 * S2 + wi] = hi;
                sm[X2_L + r0 * S2 + wi] = lo;
                split2(v2, v3, hi, lo);
                sm[X2_H + (r0 + 8) * S2 + wi] = hi;
                sm[X2_L + (r0 + 8) * S2 + wi] = lo;
            }
        }
        if (c + 1 < NCH) cp_wait1(); else cp_wait0();   // W2p[c] arrived
        __syncthreads();                                // X2 + W2 visible

        // ---- stage2: logits += x2c @ W2p_block  (out 128x128(mask 100), K=64)
#pragma unroll
        for (int ks = 0; ks < 4; ks++) {
            const uint32_t ko = (uint32_t)(ks * 8 + lsel) * 4;
            uint32_t ah[2][4], al[2][4];
#pragma unroll
            for (int mt = 0; mt < 2; mt++) {
                const uint32_t ro = (uint32_t)((wm * 32 + mt * 16 + lrow) * S2) * 4;
                ldm_x4(ah[mt], sb + (uint32_t)(X2_H * 4) + ro + ko);
                ldm_x4(al[mt], sb + (uint32_t)(X2_L * 4) + ro + ko);
            }
#pragma unroll
            for (int ng = 0; ng < 4; ng++) {
                uint32_t bh[4], bl[4];
                const uint32_t ro = (uint32_t)((wn * 64 + ng * 16 + lrow) * S2) * 4;
                ldm_x4(bh, sb + (uint32_t)(W2_H * 4) + ro + ko);
                ldm_x4(bl, sb + (uint32_t)(W2_L * 4) + ro + ko);
#pragma unroll
                for (int sub = 0; sub < 2; sub++) {
                    const int nt = ng * 2 + sub;
#pragma unroll
                    for (int mt = 0; mt < 2; mt++) {
                        mma_bf16(c2[mt][nt], ah[mt], bh[sub], bh[2 + sub]);
                        mma_bf16(c2[mt][nt], ah[mt], bl[sub], bl[2 + sub]);
                        mma_bf16(c2[mt][nt], al[mt], bh[sub], bh[2 + sub]);
                    }
                }
            }
        }
    }

    // ---- epilogue: bias + relu, write logits (compact [NPG][100] per graph)
#pragma unroll
    for (int mt = 0; mt < 2; mt++) {
        const int rL0 = mt128 * 128 + wm * 32 + mt * 16 + lg;
        const int rL1 = rL0 + 8;
#pragma unroll
        for (int nt = 0; nt < 8; nt++) {
            const int col = wn * 64 + nt * 8 + 2 * tig;
            if (col >= KPG) continue;
            const float b0 = b2p[gz * KPG + col];
            const float b1 = b2p[gz * KPG + col + 1];
            if (rL0 < NPG) {
                float v0 = fmaxf(c2[mt][nt][0] + b0, 0.f);
                float v1 = fmaxf(c2[mt][nt][1] + b1, 0.f);
                *(float2*)(g_logits + (size_t)(gz * NPG + rL0) * KPG + col) = make_float2(v0, v1);
            }
            if (rL1 < NPG) {
                float v2 = fmaxf(c2[mt][nt][2] + b0, 0.f);
                float v3 = fmaxf(c2[mt][nt][3] + b1, 0.f);
                *(float2*)(g_logits + (size_t)(gz * NPG + rL1) * KPG + col) = make_float2(v2, v3);
            }
        }
    }
}

// ---------------- tensor-core bf16 split GEMM (feat branch) ------------------
static constexpr int AW = 20;               // smem row stride (words)
static constexpr int OFF_AL = 128 * AW;
static constexpr int OFF_BH = 2 * 128 * AW;
static constexpr int OFF_BL = 3 * 128 * AW;
static constexpr int STAGEW = 4 * 128 * AW;
static constexpr int GEMM_SMEM = 3 * STAGEW * 4;

template<bool OUT_SPLIT>
__global__ __launch_bounds__(256)
void mma_gemm(const uint32_t* __restrict__ Ahg, const uint32_t* __restrict__ Alg,
              const uint32_t* __restrict__ Bhg, const uint32_t* __restrict__ Blg,
              const float* __restrict__ bias,
              float* __restrict__ C, uint32_t* __restrict__ Ch, uint32_t* __restrict__ Cl,
              int M, int N, int K, int ldaw, int ldbw, int ldc, int ldcw) {
    extern __shared__ uint32_t sm2[];
    const uint32_t sbase = smem_u32(sm2);

    const int tid  = threadIdx.x;
    const int wid  = tid >> 5;
    const int lane = tid & 31;
    const int wm   = wid & 3;
    const int wn   = wid >> 2;
    const int g    = lane >> 2;
    const int tig  = lane & 3;
    const int bm   = blockIdx.x * 128;
    const int bn   = blockIdx.y * 128;

    const int am = tid >> 1;
    const int aq = (tid & 1) * 8;
    const int arow = min(bm + am, M - 1);
    const int brow = min(bn + am, N - 1);
    const uint32_t* ApH = Ahg + (size_t)arow * ldaw + aq;
    const uint32_t* ApL = Alg + (size_t)arow * ldaw + aq;
    const uint32_t* BpH = Bhg + (size_t)brow * ldbw + aq;
    const uint32_t* BpL = Blg + (size_t)brow * ldbw + aq;
    const uint32_t aSm = (uint32_t)(am * AW + aq) * 4;

    const int lrow = (lane < 16) ? lane : (lane - 16);
    const int lsel = (lane >= 16) ? 4 : 0;

    float c[2][8][4];
#pragma unroll
    for (int mt = 0; mt < 2; mt++)
#pragma unroll
        for (int nt = 0; nt < 8; nt++)
#pragma unroll
            for (int q = 0; q < 4; q++) c[mt][nt][q] = 0.f;

    auto issue = [&](int t, int buf) {
        const int kpt = t * 16;
        const uint32_t sa = sbase + (uint32_t)(buf * STAGEW) * 4 + aSm;
        cp16(sa,                    ApH + kpt);
        cp16(sa + 16,               ApH + kpt + 4);
        cp16(sa + OFF_AL * 4,       ApL + kpt);
        cp16(sa + OFF_AL * 4 + 16,  ApL + kpt + 4);
        const uint32_t sbb = sa + OFF_BH * 4;
        cp16(sbb,                              BpH + kpt);
        cp16(sbb + 16,                         BpH + kpt + 4);
        cp16(sbb + (OFF_BL - OFF_BH) * 4,      BpL + kpt);
        cp16(sbb + (OFF_BL - OFF_BH) * 4 + 16, BpL + kpt + 4);
    };

    const int nT = K >> 5;
    issue(0, 0); cp_commit();
    if (nT > 1) { issue(1, 1); cp_commit(); }

    for (int t = 0; t < nT; t++) {
        if (t + 1 < nT) cp_wait1(); else cp_wait0();
        __syncthreads();

        const int buf = t % 3;
        const uint32_t stage = sbase + (uint32_t)(buf * STAGEW) * 4;
        const uint32_t aBase = stage + (uint32_t)((wm * 32 + lrow) * AW + lsel) * 4;
        const uint32_t bBase = stage + (uint32_t)(OFF_BH + (wn * 64 + lrow) * AW + lsel) * 4;

#pragma unroll
        for (int ks = 0; ks < 2; ks++) {
            const uint32_t ko = (uint32_t)(ks * 8) * 4;
            uint32_t ah[2][4], al[2][4];
#pragma unroll
            for (int mt = 0; mt < 2; mt++) {
                const uint32_t ao = aBase + (uint32_t)(mt * 16 * AW) * 4 + ko;
                ldm_x4(ah[mt], ao);
                ldm_x4(al[mt], ao + OFF_AL * 4);
            }
#pragma unroll
            for (int ng = 0; ng < 4; ng++) {
                uint32_t bh[4], bl[4];
                const uint32_t bo = bBase + (uint32_t)(ng * 16 * AW) * 4 + ko;
                ldm_x4(bh, bo);
                ldm_x4(bl, bo + (OFF_BL - OFF_BH) * 4);
#pragma unroll
                for (int sub = 0; sub < 2; sub++) {
                    const int nt = ng * 2 + sub;
#pragma unroll
                    for (int mt = 0; mt < 2; mt++) {
                        mma_bf16(c[mt][nt], ah[mt], bh[sub], bh[2 + sub]);
                        mma_bf16(c[mt][nt], ah[mt], bl[sub], bl[2 + sub]);
                        mma_bf16(c[mt][nt], al[mt], bh[sub], bh[2 + sub]);
                    }
                }
            }
        }
        if (t + 2 < nT) { issue(t + 2, (t + 2) % 3); cp_commit(); }
    }

#pragma unroll
    for (int mt = 0; mt < 2; mt++) {
        const int r0 = bm + wm * 32 + mt * 16 + g;
        const int r1 = r0 + 8;
#pragma unroll
        for (int nt = 0; nt < 8; nt++) {
            const int col = bn + wn * 64 + nt * 8 + 2 * tig;
            if (col >= N) continue;
            const bool pair = (col + 1 < N);
            const float b0 = bias[col];
            const float b1 = pair ? bias[col + 1] : 0.f;
            float v0 = fmaxf(c[mt][nt][0] + b0, 0.f);
            float v1 = fmaxf(c[mt][nt][1] + b1, 0.f);
            float v2 = fmaxf(c[mt][nt][2] + b0, 0.f);
            float v3 = fmaxf(c[mt][nt][3] + b1, 0.f);
            if (OUT_SPLIT) {
                uint32_t hi, lo;
                if (r0 < M) {
                    split2(v0, v1, hi, lo);
                    Ch[(size_t)r0 * ldcw + (col >> 1)] = hi;
                    Cl[(size_t)r0 * ldcw + (col >> 1)] = lo;
                }
                if (r1 < M) {
                    split2(v2, v3, hi, lo);
                    Ch[(size_t)r1 * ldcw + (col >> 1)] = hi;
                    Cl[(size_t)r1 * ldcw + (col >> 1)] = lo;
                }
            } else {
                if (r0 < M) {
                    if (pair) *(float2*)(C + (size_t)r0 * ldc + col) = make_float2(v0, v1);
                    else      C[(size_t)r0 * ldc + col] = v0;
                }
                if (r1 < M) {
                    if (pair) *(float2*)(C + (size_t)r1 * ldc + col) = make_float2(v2, v3);
                    else      C[(size_t)r1 * ldc + col] = v2;
                }
            }
        }
    }
}

// ---------------- per-node softmax over 100 compact logits ------------------
__global__ void softmax_kernel() {
    int node = (blockIdx.x * blockDim.x + threadIdx.x) >> 5;
    int lane = threadIdx.x & 31;
    if (node >= NN) return;
    const float* lp = g_logits + (size_t)node * KPG;
    float v[4];
    float mx = -1e30f;
#pragma unroll
    for (int i = 0; i < 4; i++) {
        int c = lane + 32 * i;
        v[i] = (c < KPG) ? lp[c] : -1e30f;
        mx = fmaxf(mx, v[i]);
    }
#pragma unroll
    for (int o = 16; o; o >>= 1) mx = fmaxf(mx, __shfl_xor_sync(0xFFFFFFFFu, mx, o));
    float sum = 0.f;
#pragma unroll
    for (int i = 0; i < 4; i++) {
        int c = lane + 32 * i;
        v[i] = (c < KPG) ? expf(v[i] - mx) : 0.f;
        sum += v[i];
    }
#pragma unroll
    for (int o = 16; o; o >>= 1) sum += __shfl_xor_sync(0xFFFFFFFFu, sum, o);
    float inv = 1.f / sum;
    float* ap = g_assign + (size_t)node * KPG;
#pragma unroll
    for (int i = 0; i < 4; i++) {
        int c = lane + 32 * i;
        if (c < KPG) ap[c] = v[i] * inv;
    }
}

// ---------------- gather: tmp[n] = sum_{s in N(n)} assign[s] ----------------
__global__ void gather_tmp_kernel() {
    int n = (blockIdx.x * blockDim.x + threadIdx.x) >> 5;
    int lane = threadIdx.x & 31;
    if (n >= NN) return;
    int dg = min(g_degi[n], CAP);
    const int* nb = g_nbr + (size_t)n * CAP;
    float a0 = 0.f, a1 = 0.f, a2 = 0.f, a3 = 0.f;
    for (int j = 0; j < dg; j++) {
        const float* ar = g_assign + (size_t)nb[j] * KPG;
        a0 += ar[lane];
        a1 += ar[lane + 32];
        a2 += ar[lane + 64];
        if (lane < 4) a3 += ar[lane + 96];
    }
    float* tp = g_tmp + (size_t)n * KPG;
    tp[lane]      = a0;
    tp[lane + 32] = a1;
    tp[lane + 64] = a2;
    if (lane < 4) tp[lane + 96] = a3;
}

// ---------------- h_pool: per graph, assign_b^T [2000x100] @ feat_b [2000x128]
__global__ __launch_bounds__(256)
void hpool_kernel(float* __restrict__ out) {   // out = d_out + ADJ_ELEMS
    const int g = blockIdx.y;
    const int split = blockIdx.x;
    const int kbeg = split * (NPG / 8);
    const int kend = kbeg + (NPG / 8);
    const float* A = g_assign + (size_t)g * NPG * KPG;
    const float* F = g_feat + (size_t)g * NPG * DD;

    __shared__ float As[8][KPG];
    __shared__ float Fs[8][DD];
    const int tx = threadIdx.x & 15;
    const int ty = threadIdx.x >> 4;

    float acc[7][8];
#pragma unroll
    for (int i = 0; i < 7; i++)
#pragma unroll
        for (int j = 0; j < 8; j++) acc[i][j] = 0.f;

    for (int k0 = kbeg; k0 < kend; k0 += 8) {
        int kc = min(8, kend - k0);
        for (int idx = threadIdx.x; idx < 8 * KPG; idx += 256) {
            int r = idx / KPG, c = idx % KPG;
            As[r][c] = (r < kc) ? A[(size_t)(k0 + r) * KPG + c] : 0.f;
        }
        for (int idx = threadIdx.x; idx < 8 * DD; idx += 256) {
            int r = idx >> 7, c = idx & 127;
            Fs[r][c] = (r < kc) ? F[(size_t)(k0 + r) * DD + c] : 0.f;
        }
        __syncthreads();
#pragma unroll
        for (int k = 0; k < 8; k++) {
            float a[7], f[8];
#pragma unroll
            for (int i = 0; i < 7; i++) {
                int c = ty + 16 * i;
                a[i] = (c < KPG) ? As[k][c] : 0.f;
            }
#pragma unroll
            for (int j = 0; j < 8; j++) f[j] = Fs[k][tx + 16 * j];
#pragma unroll
            for (int i = 0; i < 7; i++)
#pragma unroll
                for (int j = 0; j < 8; j++) acc[i][j] += a[i] * f[j];
        }
        __syncthreads();
    }
#pragma unroll
    for (int i = 0; i < 7; i++) {
        int c = ty + 16 * i;
        if (c >= KPG) continue;
#pragma unroll
        for (int j = 0; j < 8; j++) {
            int d = tx + 16 * j;
            atomicAdd(&out[(size_t)(g * KPG + c) * DD + d], acc[i][j]);
        }
    }
}

// ---------------- adj: per graph, assign_b^T [2000x100] @ tmp_b [2000x100] --
__global__ __launch_bounds__(256)
void adj_kernel(float* __restrict__ out) {
    const int g = blockIdx.y;
    const int split = blockIdx.x;
    const int kbeg = split * (NPG / 8);
    const int kend = kbeg + (NPG / 8);
    const float* A = g_assign + (size_t)g * NPG * KPG;
    const float* T = g_tmp + (size_t)g * NPG * KPG;

    __shared__ float As[8][KPG];
    __shared__ float Ts[8][KPG];
    const int tx = threadIdx.x & 15;
    const int ty = threadIdx.x >> 4;

    float acc[7][7];
#pragma unroll
    for (int i = 0; i < 7; i++)
#pragma unroll
        for (int j = 0; j < 7; j++) acc[i][j] = 0.f;

    for (int k0 = kbeg; k0 < kend; k0 += 8) {
        int kc = min(8, kend - k0);
        for (int idx = threadIdx.x; idx < 8 * KPG; idx += 256) {
            int r = idx / KPG, c = idx % KPG;
            As[r][c] = (r < kc) ? A[(size_t)(k0 + r) * KPG + c] : 0.f;
            Ts[r][c] = (r < kc) ? T[(size_t)(k0 + r) * KPG + c] : 0.f;
        }
        __syncthreads();
#pragma unroll
        for (int k = 0; k < 8; k++) {
            float a[7], b[7];
#pragma unroll
            for (int i = 0; i < 7; i++) {
                int c = ty + 16 * i;
                a[i] = (c < KPG) ? As[k][c] : 0.f;
            }
#pragma unroll
            for (int j = 0; j < 7; j++) {
                int c = tx + 16 * j;
                b[j] = (c < KPG) ? Ts[k][c] : 0.f;
            }
#pragma unroll
            for (int i = 0; i < 7; i++)
#pragma unroll
                for (int j = 0; j < 7; j++) acc[i][j] += a[i] * b[j];
        }
        __syncthreads();
    }
#pragma unroll
    for (int i = 0; i < 7; i++) {
        int c1 = ty + 16 * i;
        if (c1 >= KPG) continue;
#pragma unroll
        for (int j = 0; j < 7; j++) {
            int c2 = tx + 16 * j;
            if (c2 >= KPG) continue;
            atomicAdd(&out[(size_t)(g * KPG + c1) * KK + (g * KPG + c2)], acc[i][j]);
        }
    }
}

// ---------------- launch ----------------------------------------------------
extern "C" void kernel_launch(void* const* d_in, const int* in_sizes, int n_in,
                              void* d_out, int out_size) {
    const float* h   = (const float*)d_in[0];
    const int*   src = (const int*)d_in[1];
    const int*   dst = (const int*)d_in[2];
    const float* W1f = (const float*)d_in[3];
    const float* b1f = (const float*)d_in[4];
    const float* W2f = (const float*)d_in[5];
    const float* b2f = (const float*)d_in[6];
    const float* W1p = (const float*)d_in[7];
    const float* b1p = (const float*)d_in[8];
    const float* W2p = (const float*)d_in[9];
    const float* b2p = (const float*)d_in[10];
    float* out = (float*)d_out;

    uint32_t *xh, *xl, *t1h, *t1l;
    uint32_t *w1fh, *w1fl, *w2fh, *w2fl, *w1ph, *w1pl, *w2ph, *w2pl;
    float *feat;
    int* degi;
    cudaGetSymbolAddress((void**)&xh,   g_xh);
    cudaGetSymbolAddress((void**)&xl,   g_xl);
    cudaGetSymbolAddress((void**)&t1h,  g_t1h);
    cudaGetSymbolAddress((void**)&t1l,  g_t1l);
    cudaGetSymbolAddress((void**)&w1fh, g_w1fh);
    cudaGetSymbolAddress((void**)&w1fl, g_w1fl);
    cudaGetSymbolAddress((void**)&w2fh, g_w2fh);
    cudaGetSymbolAddress((void**)&w2fl, g_w2fl);
    cudaGetSymbolAddress((void**)&w1ph, g_w1ph);
    cudaGetSymbolAddress((void**)&w1pl, g_w1pl);
    cudaGetSymbolAddress((void**)&w2ph, g_w2ph);
    cudaGetSymbolAddress((void**)&w2pl, g_w2pl);
    cudaGetSymbolAddress((void**)&feat,   g_feat);
    cudaGetSymbolAddress((void**)&degi,   g_degi);

    cudaFuncSetAttribute(mma_gemm<true>,  cudaFuncAttributeMaxDynamicSharedMemorySize, GEMM_SMEM);
    cudaFuncSetAttribute(mma_gemm<false>, cudaFuncAttributeMaxDynamicSharedMemorySize, GEMM_SMEM);
    cudaFuncSetAttribute(fused_pool_kernel, cudaFuncAttributeMaxDynamicSharedMemorySize, FUSED_SMEM);

    // 0-4: prep for fused pool (launch #5 = fused_pool for ncu -s 5)
    zero_i<<<128, 256>>>(degi, (size_t)NN);
    fill_bucket_kernel<<<(EE + 255) / 256, 256>>>(src, dst);
    gather_x_kernel<<<(NN * 32 + 255) / 256, 256>>>(h);
    split_BT_kernel<<<((size_t)KK * DD / 2 + 255) / 256, 256>>>(W1p, w1ph, w1pl, DD / 2, KK);
    split_BT_kernel<<<((size_t)KK * KK / 2 + 255) / 256, 256>>>(W2p, w2ph, w2pl, KK / 2, KK);

    // 5: fused pool1+pool2 -> logits
    fused_pool_kernel<<<dim3(16, NB), 256, FUSED_SMEM>>>(b1p, b2p);

    // 6-10: output zero + feat branch
    zero_f<<<1024, 256>>>(out, (size_t)out_size);
    split_BT_kernel<<<(DD * DD / 2 + 255) / 256, 256>>>(W1f, w1fh, w1fl, DD / 2, DD);
    split_BT_kernel<<<(DD * DD / 2 + 255) / 256, 256>>>(W2f, w2fh, w2fl, DD / 2, DD);
    mma_gemm<true><<<dim3(250, 1, 1), 256, GEMM_SMEM>>>(
        xh, xl, w1fh, w1fl, b1f, nullptr, t1h, t1l,
        NN, DD, DD, DD / 2, DD / 2, 0, DD / 2);
    mma_gemm<false><<<dim3(250, 1, 1), 256, GEMM_SMEM>>>(
        t1h, t1l, w2fh, w2fl, b2f, feat, nullptr, nullptr,
        NN, DD, DD, DD / 2, DD / 2, DD, 0);

    // 11-14: softmax, tmp gather, output GEMMs
    softmax_kernel<<<(NN * 32 + 255) / 256, 256>>>();
    gather_tmp_kernel<<<(NN * 32 + 255) / 256, 256>>>();
    hpool_kernel<<<dim3(8, NB), 256>>>(out + ADJ_ELEMS);
    adj_kernel<<<dim3(8, NB), 256>>>(out);
}

// round 10
// speedup vs baseline: 2.0536x; 1.0122x over previous
#include <cuda_runtime.h>
#include <cuda_bf16.h>
#include <math.h>
#include <cstdint>
#include <cstddef>

// Problem constants
static constexpr int NN   = 32000;     // nodes
static constexpr int NB   = 16;        // graphs
static constexpr int NPG  = 2000;      // nodes per graph
static constexpr int KK   = 1600;      // clusters total
static constexpr int KPG  = 100;       // clusters per graph
static constexpr int DD   = 128;       // feature dim
static constexpr int EE   = 512000;    // edges
static constexpr int ADJ_ELEMS = KK * KK;
static constexpr int CAP  = 96;        // neighbor bucket capacity

// ---------------- scratch (__device__ globals) ------------------------------
__device__ uint32_t g_xh[(size_t)NN * DD / 2];
__device__ uint32_t g_xl[(size_t)NN * DD / 2];
__device__ uint32_t g_t1h[(size_t)NN * DD / 2];
__device__ uint32_t g_t1l[(size_t)NN * DD / 2];
// transposed packed weights (A-format): [N][K/2] words
__device__ uint32_t g_w1fh[DD * DD / 2];
__device__ uint32_t g_w1fl[DD * DD / 2];
__device__ uint32_t g_w2fh[DD * DD / 2];
__device__ uint32_t g_w2fl[DD * DD / 2];
__device__ uint32_t g_w1ph[(size_t)KK * DD / 2];
__device__ uint32_t g_w1pl[(size_t)KK * DD / 2];
__device__ uint32_t g_w2ph[(size_t)KK * KK / 2];
__device__ uint32_t g_w2pl[(size_t)KK * KK / 2];
// fp32 buffers
__device__ float g_feat[(size_t)NN * DD];
__device__ float g_logits[(size_t)NN * KPG];
__device__ float g_assign[(size_t)NN * KPG];
__device__ float g_tmp[(size_t)NN * KPG];
__device__ int   g_degi[NN];
__device__ int   g_nbr[(size_t)NN * CAP];

// ---------------- helpers ----------------------------------------------------
__device__ __forceinline__ uint32_t smem_u32(const void* p) {
    uint32_t a;
    asm("{ .reg .u64 t; cvta.to.shared.u64 t, %1; cvt.u32.u64 %0, t; }" : "=r"(a) : "l"(p));
    return a;
}
__device__ __forceinline__ void cp16(uint32_t saddr, const void* g) {
    asm volatile("cp.async.ca.shared.global [%0], [%1], 16;" :: "r"(saddr), "l"(g) : "memory");
}
__device__ __forceinline__ void cp_commit() {
    asm volatile("cp.async.commit_group;" ::: "memory");
}
__device__ __forceinline__ void cp_wait0() {
    asm volatile("cp.async.wait_group 0;" ::: "memory");
}
__device__ __forceinline__ void cp_wait1() {
    asm volatile("cp.async.wait_group 1;" ::: "memory");
}
__device__ __forceinline__ void ldm_x4(uint32_t* r, uint32_t saddr) {
    asm volatile("ldmatrix.sync.aligned.m8n8.x4.shared.b16 {%0,%1,%2,%3}, [%4];"
                 : "=r"(r[0]), "=r"(r[1]), "=r"(r[2]), "=r"(r[3]) : "r"(saddr));
}
__device__ __forceinline__ void mma_bf16(float* c, const uint32_t* a,
                                         uint32_t b0, uint32_t b1) {
    asm volatile(
        "mma.sync.aligned.m16n8k16.row.col.f32.bf16.bf16.f32 "
        "{%0,%1,%2,%3}, {%4,%5,%6,%7}, {%8,%9}, {%0,%1,%2,%3};"
        : "+f"(c[0]), "+f"(c[1]), "+f"(c[2]), "+f"(c[3])
        : "r"(a[0]), "r"(a[1]), "r"(a[2]), "r"(a[3]), "r"(b0), "r"(b1));
}
__device__ __forceinline__ void split2(float f0, float f1, uint32_t& hi, uint32_t& lo) {
    __nv_bfloat16 h0 = __float2bfloat16(f0);
    __nv_bfloat16 h1 = __float2bfloat16(f1);
    __nv_bfloat16 l0 = __float2bfloat16(f0 - __bfloat162float(h0));
    __nv_bfloat16 l1 = __float2bfloat16(f1 - __bfloat162float(h1));
    __nv_bfloat162 hp = __nv_bfloat162(h0, h1);
    __nv_bfloat162 lp = __nv_bfloat162(l0, l1);
    hi = *reinterpret_cast<uint32_t*>(&hp);
    lo = *reinterpret_cast<uint32_t*>(&lp);
}

// ---------------- zero helpers ----------------------------------------------
__global__ void zero_f(float* __restrict__ p, size_t n) {
    size_t i = (size_t)blockIdx.x * blockDim.x + threadIdx.x;
    size_t st = (size_t)gridDim.x * blockDim.x;
    for (; i < n; i += st) p[i] = 0.f;
}
__global__ void zero_i(int* __restrict__ p, size_t n) {
    size_t i = (size_t)blockIdx.x * blockDim.x + threadIdx.x;
    size_t st = (size_t)gridDim.x * blockDim.x;
    for (; i < n; i += st) p[i] = 0;
}

// ---------------- bucket fill: per-dst neighbor lists ------------------------
__global__ void fill_bucket_kernel(const int* __restrict__ src,
                                   const int* __restrict__ dst) {
    int e = blockIdx.x * blockDim.x + threadIdx.x;
    if (e >= EE) return;
    int d = dst[e];
    int p = atomicAdd(&g_degi[d], 1);
    if (p < CAP) g_nbr[(size_t)d * CAP + p] = src[e];
}

// ---------------- weight split+transpose: Bt[n][kp] = pack(B[2kp][n], B[2kp+1][n])
__global__ void split_BT_kernel(const float* __restrict__ B,
                                uint32_t* __restrict__ Bh, uint32_t* __restrict__ Bl,
                                int K2, int N) {
    int idx = blockIdx.x * blockDim.x + threadIdx.x;
    if (idx >= N * K2) return;
    int n = idx / K2, kp = idx - n * K2;
    float f0 = B[(size_t)(2 * kp) * N + n];
    float f1 = B[(size_t)(2 * kp + 1) * N + n];
    uint32_t hi, lo;
    split2(f0, f1, hi, lo);
    Bh[idx] = hi;
    Bl[idx] = lo;
}

// ---------------- gather: x = h + mean nbr, write packed bf16 hi/lo ---------
__global__ void gather_x_kernel(const float* __restrict__ h) {
    int n = (blockIdx.x * blockDim.x + threadIdx.x) >> 5;
    int lane = threadIdx.x & 31;
    if (n >= NN) return;
    int dg = min(g_degi[n], CAP);
    const int* nb = g_nbr + (size_t)n * CAP;
    float a0 = 0.f, a1 = 0.f, a2 = 0.f, a3 = 0.f;
    for (int j = 0; j < dg; j++) {
        float4 v = ((const float4*)(h + (size_t)nb[j] * DD))[lane];
        a0 += v.x; a1 += v.y; a2 += v.z; a3 += v.w;
    }
    float inv = 1.f / fmaxf((float)dg, 1.f);
    float4 hn = ((const float4*)(h + (size_t)n * DD))[lane];
    float v0 = hn.x + a0 * inv;
    float v1 = hn.y + a1 * inv;
    float v2 = hn.z + a2 * inv;
    float v3 = hn.w + a3 * inv;
    uint32_t hi0, lo0, hi1, lo1;
    split2(v0, v1, hi0, lo0);
    split2(v2, v3, hi1, lo1);
    size_t base = (size_t)n * (DD / 2) + lane * 2;
    g_xh[base] = hi0; g_xh[base + 1] = hi1;
    g_xl[base] = lo0; g_xl[base + 1] = lo1;
}

// ================= FUSED pool1+pool2 (register x2) ===========================
// Per CTA: 128 rows of one graph; 8 warps, each owns 16 rows (m16).
// Loop 25 chunks of 64 clusters:
//   stage1: c1 = x @ W1p[:,chunk]   (per warp: m16 x 64, K=128)
//   relu+bias in regs; C-fragments repacked directly as stage2 A-fragments
//   stage2: c2 += x2c @ W2p[chunk, cols 0..103]   (skip masked cols >= 104)
// One __syncthreads per chunk (W1/W2 double-buffer recycle). No X2 smem.
static constexpr int CW  = 64;            // chunk width
static constexpr int NCH = KK / CW;       // 25
static constexpr int S1  = 68;            // stride for 64-word rows
static constexpr int S2  = 36;            // stride for 32-word rows
static constexpr int XT_H    = 0;
static constexpr int XT_L    = 128 * S1;              // 8704
static constexpr int W1_BASE = 2 * 128 * S1;          // 17408
static constexpr int W1_BUF  = 2 * 64 * S1;           // 8704 (hi, lo at +64*S1)
static constexpr int W2_BASE = W1_BASE + 2 * W1_BUF;  // 34816
static constexpr int W2_BUF  = 2 * 128 * S2;          // 9216 (hi, lo at +128*S2)
static constexpr int FUSED_W    = W2_BASE + 2 * W2_BUF;  // 53248 words
static constexpr int FUSED_SMEM = FUSED_W * 4;           // 212992 B

__global__ __launch_bounds__(256)
void fused_pool_kernel(const float* __restrict__ b1p, const float* __restrict__ b2p) {
    extern __shared__ uint32_t sm[];
    const uint32_t sb = smem_u32(sm);
    const int mt128 = blockIdx.x;       // m-tile within graph (0..15)
    const int gz    = blockIdx.y;       // graph
    const int tid = threadIdx.x, wid = tid >> 5, lane = tid & 31;
    const int g = lane >> 2, tig = lane & 3;
    const int lrow = (lane < 16) ? lane : (lane - 16);
    const int lsel = (lane >= 16) ? 4 : 0;

    // ---- prologue: X tile + W1[0] + W2[0], one group
#pragma unroll
    for (int i = 0; i < 8; i++) {
        int q = tid + i * 256;                 // 0..2047
        int row = q >> 4, w = (q & 15) * 4;
        int grow = gz * NPG + min(mt128 * 128 + row, NPG - 1);
        cp16(sb + (uint32_t)(XT_H + row * S1 + w) * 4, g_xh + (size_t)grow * 64 + w);
        cp16(sb + (uint32_t)(XT_L + row * S1 + w) * 4, g_xl + (size_t)grow * 64 + w);
    }
#pragma unroll
    for (int i = 0; i < 4; i++) {
        int q = tid + i * 256;                 // 0..1023
        int row = q >> 4, w = (q & 15) * 4;
        cp16(sb + (uint32_t)(W1_BASE + row * S1 + w) * 4,           g_w1ph + (size_t)row * 64 + w);
        cp16(sb + (uint32_t)(W1_BASE + 64 * S1 + row * S1 + w) * 4, g_w1pl + (size_t)row * 64 + w);
    }
#pragma unroll
    for (int i = 0; i < 4; i++) {
        int q = tid + i * 256;
        if (q < 800) {
            int row = q >> 3, w = (q & 7) * 4;
            const size_t go = (size_t)(gz * 100 + row) * 800 + w;
            cp16(sb + (uint32_t)(W2_BASE + row * S2 + w) * 4,            g_w2ph + go);
            cp16(sb + (uint32_t)(W2_BASE + 128 * S2 + row * S2 + w) * 4, g_w2pl + go);
        }
    }
    cp_commit();

    float c2[13][4];
#pragma unroll
    for (int nt = 0; nt < 13; nt++)
#pragma unroll
        for (int q = 0; q < 4; q++) c2[nt][q] = 0.f;

    for (int c = 0; c < NCH; c++) {
        cp_wait0();
        __syncthreads();      // chunk data arrived; all warps done with alt bufs

        // ---- prefetch next chunk into alternate buffers
        if (c + 1 < NCH) {
            const int nb = (c + 1) & 1;
#pragma unroll
            for (int i = 0; i < 4; i++) {
                int q = tid + i * 256;
                int row = q >> 4, w = (q & 15) * 4;
                const size_t go = (size_t)((c + 1) * 64 + row) * 64 + w;
                cp16(sb + (uint32_t)(W1_BASE + nb * W1_BUF + row * S1 + w) * 4,           g_w1ph + go);
                cp16(sb + (uint32_t)(W1_BASE + nb * W1_BUF + 64 * S1 + row * S1 + w) * 4, g_w1pl + go);
            }
#pragma unroll
            for (int i = 0; i < 4; i++) {
                int q = tid + i * 256;
                if (q < 800) {
                    int row = q >> 3, w = (q & 7) * 4;
                    const size_t go = (size_t)(gz * 100 + row) * 800 + (c + 1) * 32 + w;
                    cp16(sb + (uint32_t)(W2_BASE + nb * W2_BUF + row * S2 + w) * 4,            g_w2ph + go);
                    cp16(sb + (uint32_t)(W2_BASE + nb * W2_BUF + 128 * S2 + row * S2 + w) * 4, g_w2pl + go);
                }
            }
            cp_commit();
        }

        // ---- stage1: c1 = x @ W1p_chunk  (per warp m16 x 64, K=128)
        float c1[8][4];
#pragma unroll
        for (int nt = 0; nt < 8; nt++)
#pragma unroll
            for (int q = 0; q < 4; q++) c1[nt][q] = 0.f;

        const uint32_t w1b = (uint32_t)(W1_BASE + (c & 1) * W1_BUF);
        const uint32_t aRowOff = (uint32_t)((wid * 16 + lrow) * S1) * 4;
#pragma unroll
        for (int ks = 0; ks < 8; ks++) {
            const uint32_t ko = (uint32_t)(ks * 8 + lsel) * 4;
            uint32_t ah[4], al[4];
            ldm_x4(ah, sb + aRowOff + ko);
            ldm_x4(al, sb + (uint32_t)(XT_L * 4) + aRowOff + ko);
#pragma unroll
            for (int ng = 0; ng < 4; ng++) {
                uint32_t bh[4], bl[4];
                const uint32_t ro = (uint32_t)((ng * 16 + lrow) * S1) * 4;
                ldm_x4(bh, sb + w1b * 4 + ro + ko);
                ldm_x4(bl, sb + (w1b + 64 * S1) * 4 + ro + ko);
#pragma unroll
                for (int sub = 0; sub < 2; sub++) {
                    const int nt = ng * 2 + sub;
                    mma_bf16(c1[nt], ah, bh[sub], bh[2 + sub]);
                    mma_bf16(c1[nt], ah, bl[sub], bl[2 + sub]);
                    mma_bf16(c1[nt], al, bh[sub], bh[2 + sub]);
                }
            }
        }

        // ---- bias + relu in registers
#pragma unroll
        for (int nt = 0; nt < 8; nt++) {
            const int colG = c * 64 + nt * 8 + 2 * tig;
            const float b0 = b1p[colG];
            const float b1 = b1p[colG + 1];
            c1[nt][0] = fmaxf(c1[nt][0] + b0, 0.f);
            c1[nt][1] = fmaxf(c1[nt][1] + b1, 0.f);
            c1[nt][2] = fmaxf(c1[nt][2] + b0, 0.f);
            c1[nt][3] = fmaxf(c1[nt][3] + b1, 0.f);
        }

        // ---- stage2: c2 += x2c @ W2p_block (K=64 via 4 k16 steps)
        const uint32_t w2b = (uint32_t)(W2_BASE + (c & 1) * W2_BUF);
#pragma unroll
        for (int ks = 0; ks < 4; ks++) {
            // A fragments straight from stage1 C fragments (hi/lo split)
            uint32_t ah2[4], al2[4];
            split2(c1[2 * ks][0],     c1[2 * ks][1],     ah2[0], al2[0]);
            split2(c1[2 * ks][2],     c1[2 * ks][3],     ah2[1], al2[1]);
            split2(c1[2 * ks + 1][0], c1[2 * ks + 1][1], ah2[2], al2[2]);
            split2(c1[2 * ks + 1][2], c1[2 * ks + 1][3], ah2[3], al2[3]);
            const uint32_t ko = (uint32_t)(ks * 8 + lsel) * 4;
#pragma unroll
            for (int ng = 0; ng < 7; ng++) {            // cols 0..111 (skip 112+)
                uint32_t bh[4], bl[4];
                const uint32_t ro = (uint32_t)((ng * 16 + lrow) * S2) * 4;
                ldm_x4(bh, sb + w2b * 4 + ro + ko);
                ldm_x4(bl, sb + (w2b + 128 * S2) * 4 + ro + ko);
#pragma unroll
                for (int sub = 0; sub < 2; sub++) {
                    const int nt = ng * 2 + sub;
                    if (nt > 12) continue;              // cols 104..111 masked
                    mma_bf16(c2[nt], ah2, bh[sub], bh[2 + sub]);
                    mma_bf16(c2[nt], ah2, bl[sub], bl[2 + sub]);
                    mma_bf16(c2[nt], al2, bh[sub], bh[2 + sub]);
                }
            }
        }
    }

    // ---- epilogue: bias + relu, write logits (compact [NPG][100] per graph)
    const int rL0 = mt128 * 128 + wid * 16 + g;
    const int rL1 = rL0 + 8;
#pragma unroll
    for (int nt = 0; nt < 13; nt++) {
        const int col = nt * 8 + 2 * tig;
        if (col >= KPG) continue;                       // pairs never straddle 100
        const float b0 = b2p[gz * KPG + col];
        const float b1 = b2p[gz * KPG + col + 1];
        if (rL0 < NPG) {
            float v0 = fmaxf(c2[nt][0] + b0, 0.f);
            float v1 = fmaxf(c2[nt][1] + b1, 0.f);
            *(float2*)(g_logits + (size_t)(gz * NPG + rL0) * KPG + col) = make_float2(v0, v1);
        }
        if (rL1 < NPG) {
            float v2 = fmaxf(c2[nt][2] + b0, 0.f);
            float v3 = fmaxf(c2[nt][3] + b1, 0.f);
            *(float2*)(g_logits + (size_t)(gz * NPG + rL1) * KPG + col) = make_float2(v2, v3);
        }
    }
}

// ---------------- tensor-core bf16 split GEMM (feat branch) ------------------
static constexpr int AW = 20;               // smem row stride (words)
static constexpr int OFF_AL = 128 * AW;
static constexpr int OFF_BH = 2 * 128 * AW;
static constexpr int OFF_BL = 3 * 128 * AW;
static constexpr int STAGEW = 4 * 128 * AW;
static constexpr int GEMM_SMEM = 3 * STAGEW * 4;

template<bool OUT_SPLIT>
__global__ __launch_bounds__(256)
void mma_gemm(const uint32_t* __restrict__ Ahg, const uint32_t* __restrict__ Alg,
              const uint32_t* __restrict__ Bhg, const uint32_t* __restrict__ Blg,
              const float* __restrict__ bias,
              float* __restrict__ C, uint32_t* __restrict__ Ch, uint32_t* __restrict__ Cl,
              int M, int N, int K, int ldaw, int ldbw, int ldc, int ldcw) {
    extern __shared__ uint32_t sm2[];
    const uint32_t sbase = smem_u32(sm2);

    const int tid  = threadIdx.x;
    const int wid  = tid >> 5;
    const int lane = tid & 31;
    const int wm   = wid & 3;
    const int wn   = wid >> 2;
    const int g    = lane >> 2;
    const int tig  = lane & 3;
    const int bm   = blockIdx.x * 128;
    const int bn   = blockIdx.y * 128;

    const int am = tid >> 1;
    const int aq = (tid & 1) * 8;
    const int arow = min(bm + am, M - 1);
    const int brow = min(bn + am, N - 1);
    const uint32_t* ApH = Ahg + (size_t)arow * ldaw + aq;
    const uint32_t* ApL = Alg + (size_t)arow * ldaw + aq;
    const uint32_t* BpH = Bhg + (size_t)brow * ldbw + aq;
    const uint32_t* BpL = Blg + (size_t)brow * ldbw + aq;
    const uint32_t aSm = (uint32_t)(am * AW + aq) * 4;

    const int lrow = (lane < 16) ? lane : (lane - 16);
    const int lsel = (lane >= 16) ? 4 : 0;

    float c[2][8][4];
#pragma unroll
    for (int mt = 0; mt < 2; mt++)
#pragma unroll
        for (int nt = 0; nt < 8; nt++)
#pragma unroll
            for (int q = 0; q < 4; q++) c[mt][nt][q] = 0.f;

    auto issue = [&](int t, int buf) {
        const int kpt = t * 16;
        const uint32_t sa = sbase + (uint32_t)(buf * STAGEW) * 4 + aSm;
        cp16(sa,                    ApH + kpt);
        cp16(sa + 16,               ApH + kpt + 4);
        cp16(sa + OFF_AL * 4,       ApL + kpt);
        cp16(sa + OFF_AL * 4 + 16,  ApL + kpt + 4);
        const uint32_t sbb = sa + OFF_BH * 4;
        cp16(sbb,                              BpH + kpt);
        cp16(sbb + 16,                         BpH + kpt + 4);
        cp16(sbb + (OFF_BL - OFF_BH) * 4,      BpL + kpt);
        cp16(sbb + (OFF_BL - OFF_BH) * 4 + 16, BpL + kpt + 4);
    };

    const int nT = K >> 5;
    issue(0, 0); cp_commit();
    if (nT > 1) { issue(1, 1); cp_commit(); }

    for (int t = 0; t < nT; t++) {
        if (t + 1 < nT) cp_wait1(); else cp_wait0();
        __syncthreads();

        const int buf = t % 3;
        const uint32_t stage = sbase + (uint32_t)(buf * STAGEW) * 4;
        const uint32_t aBase = stage + (uint32_t)((wm * 32 + lrow) * AW + lsel) * 4;
        const uint32_t bBase = stage + (uint32_t)(OFF_BH + (wn * 64 + lrow) * AW + lsel) * 4;

#pragma unroll
        for (int ks = 0; ks < 2; ks++) {
            const uint32_t ko = (uint32_t)(ks * 8) * 4;
            uint32_t ah[2][4], al[2][4];
#pragma unroll
            for (int mt = 0; mt < 2; mt++) {
                const uint32_t ao = aBase + (uint32_t)(mt * 16 * AW) * 4 + ko;
                ldm_x4(ah[mt], ao);
                ldm_x4(al[mt], ao + OFF_AL * 4);
            }
#pragma unroll
            for (int ng = 0; ng < 4; ng++) {
                uint32_t bh[4], bl[4];
                const uint32_t bo = bBase + (uint32_t)(ng * 16 * AW) * 4 + ko;
                ldm_x4(bh, bo);
                ldm_x4(bl, bo + (OFF_BL - OFF_BH) * 4);
#pragma unroll
                for (int sub = 0; sub < 2; sub++) {
                    const int nt = ng * 2 + sub;
#pragma unroll
                    for (int mt = 0; mt < 2; mt++) {
                        mma_bf16(c[mt][nt], ah[mt], bh[sub], bh[2 + sub]);
                        mma_bf16(c[mt][nt], ah[mt], bl[sub], bl[2 + sub]);
                        mma_bf16(c[mt][nt], al[mt], bh[sub], bh[2 + sub]);
                    }
                }
            }
        }
        if (t + 2 < nT) { issue(t + 2, (t + 2) % 3); cp_commit(); }
    }

#pragma unroll
    for (int mt = 0; mt < 2; mt++) {
        const int r0 = bm + wm * 32 + mt * 16 + g;
        const int r1 = r0 + 8;
#pragma unroll
        for (int nt = 0; nt < 8; nt++) {
            const int col = bn + wn * 64 + nt * 8 + 2 * tig;
            if (col >= N) continue;
            const bool pair = (col + 1 < N);
            const float b0 = bias[col];
            const float b1 = pair ? bias[col + 1] : 0.f;
            float v0 = fmaxf(c[mt][nt][0] + b0, 0.f);
            float v1 = fmaxf(c[mt][nt][1] + b1, 0.f);
            float v2 = fmaxf(c[mt][nt][2] + b0, 0.f);
            float v3 = fmaxf(c[mt][nt][3] + b1, 0.f);
            if (OUT_SPLIT) {
                uint32_t hi, lo;
                if (r0 < M) {
                    split2(v0, v1, hi, lo);
                    Ch[(size_t)r0 * ldcw + (col >> 1)] = hi;
                    Cl[(size_t)r0 * ldcw + (col >> 1)] = lo;
                }
                if (r1 < M) {
                    split2(v2, v3, hi, lo);
                    Ch[(size_t)r1 * ldcw + (col >> 1)] = hi;
                    Cl[(size_t)r1 * ldcw + (col >> 1)] = lo;
                }
            } else {
                if (r0 < M) {
                    if (pair) *(float2*)(C + (size_t)r0 * ldc + col) = make_float2(v0, v1);
                    else      C[(size_t)r0 * ldc + col] = v0;
                }
                if (r1 < M) {
                    if (pair) *(float2*)(C + (size_t)r1 * ldc + col) = make_float2(v2, v3);
                    else      C[(size_t)r1 * ldc + col] = v2;
                }
            }
        }
    }
}

// ---------------- per-node softmax over 100 compact logits ------------------
__global__ void softmax_kernel() {
    int node = (blockIdx.x * blockDim.x + threadIdx.x) >> 5;
    int lane = threadIdx.x & 31;
    if (node >= NN) return;
    const float* lp = g_logits + (size_t)node * KPG;
    float v[4];
    float mx = -1e30f;
#pragma unroll
    for (int i = 0; i < 4; i++) {
        int c = lane + 32 * i;
        v[i] = (c < KPG) ? lp[c] : -1e30f;
        mx = fmaxf(mx, v[i]);
    }
#pragma unroll
    for (int o = 16; o; o >>= 1) mx = fmaxf(mx, __shfl_xor_sync(0xFFFFFFFFu, mx, o));
    float sum = 0.f;
#pragma unroll
    for (int i = 0; i < 4; i++) {
        int c = lane + 32 * i;
        v[i] = (c < KPG) ? expf(v[i] - mx) : 0.f;
        sum += v[i];
    }
#pragma unroll
    for (int o = 16; o; o >>= 1) sum += __shfl_xor_sync(0xFFFFFFFFu, sum, o);
    float inv = 1.f / sum;
    float* ap = g_assign + (size_t)node * KPG;
#pragma unroll
    for (int i = 0; i < 4; i++) {
        int c = lane + 32 * i;
        if (c < KPG) ap[c] = v[i] * inv;
    }
}

// ---------------- gather: tmp[n] = sum_{s in N(n)} assign[s] ----------------
__global__ void gather_tmp_kernel() {
    int n = (blockIdx.x * blockDim.x + threadIdx.x) >> 5;
    int lane = threadIdx.x & 31;
    if (n >= NN) return;
    int dg = min(g_degi[n], CAP);
    const int* nb = g_nbr + (size_t)n * CAP;
    float a0 = 0.f, a1 = 0.f, a2 = 0.f, a3 = 0.f;
    for (int j = 0; j < dg; j++) {
        const float* ar = g_assign + (size_t)nb[j] * KPG;
        a0 += ar[lane];
        a1 += ar[lane + 32];
        a2 += ar[lane + 64];
        if (lane < 4) a3 += ar[lane + 96];
    }
    float* tp = g_tmp + (size_t)n * KPG;
    tp[lane]      = a0;
    tp[lane + 32] = a1;
    tp[lane + 64] = a2;
    if (lane < 4) tp[lane + 96] = a3;
}

// ---------------- h_pool: per graph, assign_b^T [2000x100] @ feat_b [2000x128]
__global__ __launch_bounds__(256)
void hpool_kernel(float* __restrict__ out) {   // out = d_out + ADJ_ELEMS
    const int g = blockIdx.y;
    const int split = blockIdx.x;
    const int kbeg = split * (NPG / 8);
    const int kend = kbeg + (NPG / 8);
    const float* A = g_assign + (size_t)g * NPG * KPG;
    const float* F = g_feat + (size_t)g * NPG * DD;

    __shared__ float As[8][KPG];
    __shared__ float Fs[8][DD];
    const int tx = threadIdx.x & 15;
    const int ty = threadIdx.x >> 4;

    float acc[7][8];
#pragma unroll
    for (int i = 0; i < 7; i++)
#pragma unroll
        for (int j = 0; j < 8; j++) acc[i][j] = 0.f;

    for (int k0 = kbeg; k0 < kend; k0 += 8) {
        int kc = min(8, kend - k0);
        for (int idx = threadIdx.x; idx < 8 * KPG; idx += 256) {
            int r = idx / KPG, c = idx % KPG;
            As[r][c] = (r < kc) ? A[(size_t)(k0 + r) * KPG + c] : 0.f;
        }
        for (int idx = threadIdx.x; idx < 8 * DD; idx += 256) {
            int r = idx >> 7, c = idx & 127;
            Fs[r][c] = (r < kc) ? F[(size_t)(k0 + r) * DD + c] : 0.f;
        }
        __syncthreads();
#pragma unroll
        for (int k = 0; k < 8; k++) {
            float a[7], f[8];
#pragma unroll
            for (int i = 0; i < 7; i++) {
                int c = ty + 16 * i;
                a[i] = (c < KPG) ? As[k][c] : 0.f;
            }
#pragma unroll
            for (int j = 0; j < 8; j++) f[j] = Fs[k][tx + 16 * j];
#pragma unroll
            for (int i = 0; i < 7; i++)
#pragma unroll
                for (int j = 0; j < 8; j++) acc[i][j] += a[i] * f[j];
        }
        __syncthreads();
    }
#pragma unroll
    for (int i = 0; i < 7; i++) {
        int c = ty + 16 * i;
        if (c >= KPG) continue;
#pragma unroll
        for (int j = 0; j < 8; j++) {
            int d = tx + 16 * j;
            atomicAdd(&out[(size_t)(g * KPG + c) * DD + d], acc[i][j]);
        }
    }
}

// ---------------- adj: per graph, assign_b^T [2000x100] @ tmp_b [2000x100] --
__global__ __launch_bounds__(256)
void adj_kernel(float* __restrict__ out) {
    const int g = blockIdx.y;
    const int split = blockIdx.x;
    const int kbeg = split * (NPG / 8);
    const int kend = kbeg + (NPG / 8);
    const float* A = g_assign + (size_t)g * NPG * KPG;
    const float* T = g_tmp + (size_t)g * NPG * KPG;

    __shared__ float As[8][KPG];
    __shared__ float Ts[8][KPG];
    const int tx = threadIdx.x & 15;
    const int ty = threadIdx.x >> 4;

    float acc[7][7];
#pragma unroll
    for (int i = 0; i < 7; i++)
#pragma unroll
        for (int j = 0; j < 7; j++) acc[i][j] = 0.f;

    for (int k0 = kbeg; k0 < kend; k0 += 8) {
        int kc = min(8, kend - k0);
        for (int idx = threadIdx.x; idx < 8 * KPG; idx += 256) {
            int r = idx / KPG, c = idx % KPG;
            As[r][c] = (r < kc) ? A[(size_t)(k0 + r) * KPG + c] : 0.f;
            Ts[r][c] = (r < kc) ? T[(size_t)(k0 + r) * KPG + c] : 0.f;
        }
        __syncthreads();
#pragma unroll
        for (int k = 0; k < 8; k++) {
            float a[7], b[7];
#pragma unroll
            for (int i = 0; i < 7; i++) {
                int c = ty + 16 * i;
                a[i] = (c < KPG) ? As[k][c] : 0.f;
            }
#pragma unroll
            for (int j = 0; j < 7; j++) {
                int c = tx + 16 * j;
                b[j] = (c < KPG) ? Ts[k][c] : 0.f;
            }
#pragma unroll
            for (int i = 0; i < 7; i++)
#pragma unroll
                for (int j = 0; j < 7; j++) acc[i][j] += a[i] * b[j];
        }
        __syncthreads();
    }
#pragma unroll
    for (int i = 0; i < 7; i++) {
        int c1 = ty + 16 * i;
        if (c1 >= KPG) continue;
#pragma unroll
        for (int j = 0; j < 7; j++) {
            int c2 = tx + 16 * j;
            if (c2 >= KPG) continue;
            atomicAdd(&out[(size_t)(g * KPG + c1) * KK + (g * KPG + c2)], acc[i][j]);
        }
    }
}

// ---------------- launch ----------------------------------------------------
extern "C" void kernel_launch(void* const* d_in, const int* in_sizes, int n_in,
                              void* d_out, int out_size) {
    const float* h   = (const float*)d_in[0];
    const int*   src = (const int*)d_in[1];
    const int*   dst = (const int*)d_in[2];
    const float* W1f = (const float*)d_in[3];
    const float* b1f = (const float*)d_in[4];
    const float* W2f = (const float*)d_in[5];
    const float* b2f = (const float*)d_in[6];
    const float* W1p = (const float*)d_in[7];
    const float* b1p = (const float*)d_in[8];
    const float* W2p = (const float*)d_in[9];
    const float* b2p = (const float*)d_in[10];
    float* out = (float*)d_out;

    uint32_t *xh, *xl, *t1h, *t1l;
    uint32_t *w1fh, *w1fl, *w2fh, *w2fl, *w1ph, *w1pl, *w2ph, *w2pl;
    float *feat;
    int* degi;
    cudaGetSymbolAddress((void**)&xh,   g_xh);
    cudaGetSymbolAddress((void**)&xl,   g_xl);
    cudaGetSymbolAddress((void**)&t1h,  g_t1h);
    cudaGetSymbolAddress((void**)&t1l,  g_t1l);
    cudaGetSymbolAddress((void**)&w1fh, g_w1fh);
    cudaGetSymbolAddress((void**)&w1fl, g_w1fl);
    cudaGetSymbolAddress((void**)&w2fh, g_w2fh);
    cudaGetSymbolAddress((void**)&w2fl, g_w2fl);
    cudaGetSymbolAddress((void**)&w1ph, g_w1ph);
    cudaGetSymbolAddress((void**)&w1pl, g_w1pl);
    cudaGetSymbolAddress((void**)&w2ph, g_w2ph);
    cudaGetSymbolAddress((void**)&w2pl, g_w2pl);
    cudaGetSymbolAddress((void**)&feat,   g_feat);
    cudaGetSymbolAddress((void**)&degi,   g_degi);

    cudaFuncSetAttribute(mma_gemm<true>,  cudaFuncAttributeMaxDynamicSharedMemorySize, GEMM_SMEM);
    cudaFuncSetAttribute(mma_gemm<false>, cudaFuncAttributeMaxDynamicSharedMemorySize, GEMM_SMEM);
    cudaFuncSetAttribute(fused_pool_kernel, cudaFuncAttributeMaxDynamicSharedMemorySize, FUSED_SMEM);

    // 0-4: prep for fused pool
    zero_i<<<128, 256>>>(degi, (size_t)NN);
    fill_bucket_kernel<<<(EE + 255) / 256, 256>>>(src, dst);
    gather_x_kernel<<<(NN * 32 + 255) / 256, 256>>>(h);
    split_BT_kernel<<<((size_t)KK * DD / 2 + 255) / 256, 256>>>(W1p, w1ph, w1pl, DD / 2, KK);
    split_BT_kernel<<<((size_t)KK * KK / 2 + 255) / 256, 256>>>(W2p, w2ph, w2pl, KK / 2, KK);

    // 5: fused pool1+pool2 -> logits
    fused_pool_kernel<<<dim3(16, NB), 256, FUSED_SMEM>>>(b1p, b2p);

    // 6-10: output zero + feat branch
    zero_f<<<1024, 256>>>(out, (size_t)out_size);
    split_BT_kernel<<<(DD * DD / 2 + 255) / 256, 256>>>(W1f, w1fh, w1fl, DD / 2, DD);
    split_BT_kernel<<<(DD * DD / 2 + 255) / 256, 256>>>(W2f, w2fh, w2fl, DD / 2, DD);
    mma_gemm<true><<<dim3(250, 1, 1), 256, GEMM_SMEM>>>(
        xh, xl, w1fh, w1fl, b1f, nullptr, t1h, t1l,
        NN, DD, DD, DD / 2, DD / 2, 0, DD / 2);
    mma_gemm<false><<<dim3(250, 1, 1), 256, GEMM_SMEM>>>(
        t1h, t1l, w2fh, w2fl, b2f, feat, nullptr, nullptr,
        NN, DD, DD, DD / 2, DD / 2, DD, 0);

    // 11-14: softmax, tmp gather, output GEMMs
    softmax_kernel<<<(NN * 32 + 255) / 256, 256>>>();
    gather_tmp_kernel<<<(NN * 32 + 255) / 256, 256>>>();
    hpool_kernel<<<dim3(8, NB), 256>>>(out + ADJ_ELEMS);
    adj_kernel<<<dim3(8, NB), 256>>>(out);
}

// round 11
// speedup vs baseline: 2.5049x; 1.2198x over previous
#include <cuda_runtime.h>
#include <cuda_fp16.h>
#include <math.h>
#include <cstdint>
#include <cstddef>

// Problem constants
static constexpr int NN   = 32000;     // nodes
static constexpr int NB   = 16;        // graphs
static constexpr int NPG  = 2000;      // nodes per graph
static constexpr int KK   = 1600;      // clusters total
static constexpr int KPG  = 100;       // clusters per graph
static constexpr int DD   = 128;       // feature dim
static constexpr int EE   = 512000;    // edges
static constexpr int ADJ_ELEMS = KK * KK;
static constexpr int CAP  = 96;        // neighbor bucket capacity

// ---------------- scratch (__device__ globals) ------------------------------
// activations: packed fp16x2 hi/lo (A-format: [rows][K/2] words)
__device__ uint32_t g_xh[(size_t)NN * DD / 2];
__device__ uint32_t g_xl[(size_t)NN * DD / 2];
__device__ uint32_t g_t1h[(size_t)NN * DD / 2];
__device__ uint32_t g_t1l[(size_t)NN * DD / 2];
// weights: single fp16 packed, transposed A-format [N][K/2]
__device__ uint32_t g_w1f[DD * DD / 2];
__device__ uint32_t g_w2f[DD * DD / 2];
__device__ uint32_t g_w1p[(size_t)KK * DD / 2];
__device__ uint32_t g_w2p[(size_t)KK * KK / 2];
// fp32 buffers
__device__ float g_feat[(size_t)NN * DD];
__device__ float g_logits[(size_t)NN * KPG];
__device__ float g_assign[(size_t)NN * KPG];
__device__ float g_tmp[(size_t)NN * KPG];
__device__ int   g_degi[NN];
__device__ int   g_nbr[(size_t)NN * CAP];

// ---------------- helpers ----------------------------------------------------
__device__ __forceinline__ uint32_t smem_u32(const void* p) {
    uint32_t a;
    asm("{ .reg .u64 t; cvta.to.shared.u64 t, %1; cvt.u32.u64 %0, t; }" : "=r"(a) : "l"(p));
    return a;
}
__device__ __forceinline__ void cp16(uint32_t saddr, const void* g) {
    asm volatile("cp.async.ca.shared.global [%0], [%1], 16;" :: "r"(saddr), "l"(g) : "memory");
}
__device__ __forceinline__ void cp_commit() {
    asm volatile("cp.async.commit_group;" ::: "memory");
}
__device__ __forceinline__ void cp_wait0() {
    asm volatile("cp.async.wait_group 0;" ::: "memory");
}
__device__ __forceinline__ void cp_wait1() {
    asm volatile("cp.async.wait_group 1;" ::: "memory");
}
__device__ __forceinline__ void ldm_x4(uint32_t* r, uint32_t saddr) {
    asm volatile("ldmatrix.sync.aligned.m8n8.x4.shared.b16 {%0,%1,%2,%3}, [%4];"
                 : "=r"(r[0]), "=r"(r[1]), "=r"(r[2]), "=r"(r[3]) : "r"(saddr));
}
__device__ __forceinline__ void mma_f16(float* c, const uint32_t* a,
                                        uint32_t b0, uint32_t b1) {
    asm volatile(
        "mma.sync.aligned.m16n8k16.row.col.f32.f16.f16.f32 "
        "{%0,%1,%2,%3}, {%4,%5,%6,%7}, {%8,%9}, {%0,%1,%2,%3};"
        : "+f"(c[0]), "+f"(c[1]), "+f"(c[2]), "+f"(c[3])
        : "r"(a[0]), "r"(a[1]), "r"(a[2]), "r"(a[3]), "r"(b0), "r"(b1));
}
// activation split: f -> fp16 hi + fp16 lo (residual), packed pairwise
__device__ __forceinline__ void split2h(float f0, float f1, uint32_t& hi, uint32_t& lo) {
    __half h0 = __float2half_rn(f0);
    __half h1 = __float2half_rn(f1);
    __half l0 = __float2half_rn(f0 - __half2float(h0));
    __half l1 = __float2half_rn(f1 - __half2float(h1));
    __half2 hp = __halves2half2(h0, h1);
    __half2 lp = __halves2half2(l0, l1);
    hi = *reinterpret_cast<uint32_t*>(&hp);
    lo = *reinterpret_cast<uint32_t*>(&lp);
}
// weight convert: single fp16 pair
__device__ __forceinline__ uint32_t cvt2h(float f0, float f1) {
    __half2 p = __halves2half2(__float2half_rn(f0), __float2half_rn(f1));
    return *reinterpret_cast<uint32_t*>(&p);
}

// ---------------- zero helpers ----------------------------------------------
__global__ void zero_f(float* __restrict__ p, size_t n) {
    size_t i = (size_t)blockIdx.x * blockDim.x + threadIdx.x;
    size_t st = (size_t)gridDim.x * blockDim.x;
    for (; i < n; i += st) p[i] = 0.f;
}
__global__ void zero_i(int* __restrict__ p, size_t n) {
    size_t i = (size_t)blockIdx.x * blockDim.x + threadIdx.x;
    size_t st = (size_t)gridDim.x * blockDim.x;
    for (; i < n; i += st) p[i] = 0;
}

// ---------------- bucket fill: per-dst neighbor lists ------------------------
__global__ void fill_bucket_kernel(const int* __restrict__ src,
                                   const int* __restrict__ dst) {
    int e = blockIdx.x * blockDim.x + threadIdx.x;
    if (e >= EE) return;
    int d = dst[e];
    int p = atomicAdd(&g_degi[d], 1);
    if (p < CAP) g_nbr[(size_t)d * CAP + p] = src[e];
}

// ---------------- weight cvt+transpose: Wt[n][kp] = h2(B[2kp][n], B[2kp+1][n])
__global__ void cvt_BT_kernel(const float* __restrict__ B,
                              uint32_t* __restrict__ Bp, int K2, int N) {
    int idx = blockIdx.x * blockDim.x + threadIdx.x;
    if (idx >= N * K2) return;
    int n = idx / K2, kp = idx - n * K2;
    Bp[idx] = cvt2h(B[(size_t)(2 * kp) * N + n], B[(size_t)(2 * kp + 1) * N + n]);
}

// ---------------- gather: x = h + mean nbr, write packed fp16 hi/lo ---------
__global__ void gather_x_kernel(const float* __restrict__ h) {
    int n = (blockIdx.x * blockDim.x + threadIdx.x) >> 5;
    int lane = threadIdx.x & 31;
    if (n >= NN) return;
    int dg = min(g_degi[n], CAP);
    const int* nb = g_nbr + (size_t)n * CAP;
    float a0 = 0.f, a1 = 0.f, a2 = 0.f, a3 = 0.f;
    for (int j = 0; j < dg; j++) {
        float4 v = ((const float4*)(h + (size_t)nb[j] * DD))[lane];
        a0 += v.x; a1 += v.y; a2 += v.z; a3 += v.w;
    }
    float inv = 1.f / fmaxf((float)dg, 1.f);
    float4 hn = ((const float4*)(h + (size_t)n * DD))[lane];
    float v0 = hn.x + a0 * inv;
    float v1 = hn.y + a1 * inv;
    float v2 = hn.z + a2 * inv;
    float v3 = hn.w + a3 * inv;
    uint32_t hi0, lo0, hi1, lo1;
    split2h(v0, v1, hi0, lo0);
    split2h(v2, v3, hi1, lo1);
    size_t base = (size_t)n * (DD / 2) + lane * 2;
    g_xh[base] = hi0; g_xh[base + 1] = hi1;
    g_xl[base] = lo0; g_xl[base + 1] = lo1;
}

// ================= FUSED pool1+pool2 (register x2, fp16 2-term) ==============
static constexpr int CW  = 64;            // chunk width
static constexpr int NCH = KK / CW;       // 25
static constexpr int S1  = 68;            // stride for 64-word rows
static constexpr int S2  = 36;            // stride for 32-word rows
static constexpr int XT_H    = 0;
static constexpr int XT_L    = 128 * S1;              // 8704
static constexpr int W1_BASE = 2 * 128 * S1;          // 17408
static constexpr int W1_BUF  = 64 * S1;               // 4352 (single fp16)
static constexpr int W2_BASE = W1_BASE + 2 * W1_BUF;  // 26112
static constexpr int W2_BUF  = 128 * S2;              // 4608
static constexpr int FUSED_W    = W2_BASE + 2 * W2_BUF;  // 35328 words
static constexpr int FUSED_SMEM = FUSED_W * 4;           // 141312 B

__global__ __launch_bounds__(256)
void fused_pool_kernel(const float* __restrict__ b1p, const float* __restrict__ b2p) {
    extern __shared__ uint32_t sm[];
    const uint32_t sb = smem_u32(sm);
    const int mt128 = blockIdx.x;       // m-tile within graph (0..15)
    const int gz    = blockIdx.y;       // graph
    const int tid = threadIdx.x, wid = tid >> 5, lane = tid & 31;
    const int g = lane >> 2, tig = lane & 3;
    const int lrow = (lane < 16) ? lane : (lane - 16);
    const int lsel = (lane >= 16) ? 4 : 0;

    // ---- prologue: X tile + W1[0] + W2[0], one group
#pragma unroll
    for (int i = 0; i < 8; i++) {
        int q = tid + i * 256;                 // 0..2047
        int row = q >> 4, w = (q & 15) * 4;
        int grow = gz * NPG + min(mt128 * 128 + row, NPG - 1);
        cp16(sb + (uint32_t)(XT_H + row * S1 + w) * 4, g_xh + (size_t)grow * 64 + w);
        cp16(sb + (uint32_t)(XT_L + row * S1 + w) * 4, g_xl + (size_t)grow * 64 + w);
    }
#pragma unroll
    for (int i = 0; i < 4; i++) {
        int q = tid + i * 256;                 // 0..1023
        int row = q >> 4, w = (q & 15) * 4;
        cp16(sb + (uint32_t)(W1_BASE + row * S1 + w) * 4, g_w1p + (size_t)row * 64 + w);
    }
#pragma unroll
    for (int i = 0; i < 4; i++) {
        int q = tid + i * 256;
        if (q < 800) {
            int row = q >> 3, w = (q & 7) * 4;
            cp16(sb + (uint32_t)(W2_BASE + row * S2 + w) * 4,
                 g_w2p + (size_t)(gz * 100 + row) * 800 + w);
        }
    }
    cp_commit();

    float c2[13][4];
#pragma unroll
    for (int nt = 0; nt < 13; nt++)
#pragma unroll
        for (int q = 0; q < 4; q++) c2[nt][q] = 0.f;

    for (int c = 0; c < NCH; c++) {
        cp_wait0();
        __syncthreads();      // chunk data arrived; all warps done with alt bufs

        // ---- prefetch next chunk into alternate buffers
        if (c + 1 < NCH) {
            const int nb = (c + 1) & 1;
#pragma unroll
            for (int i = 0; i < 4; i++) {
                int q = tid + i * 256;
                int row = q >> 4, w = (q & 15) * 4;
                cp16(sb + (uint32_t)(W1_BASE + nb * W1_BUF + row * S1 + w) * 4,
                     g_w1p + (size_t)((c + 1) * 64 + row) * 64 + w);
            }
#pragma unroll
            for (int i = 0; i < 4; i++) {
                int q = tid + i * 256;
                if (q < 800) {
                    int row = q >> 3, w = (q & 7) * 4;
                    cp16(sb + (uint32_t)(W2_BASE + nb * W2_BUF + row * S2 + w) * 4,
                         g_w2p + (size_t)(gz * 100 + row) * 800 + (c + 1) * 32 + w);
                }
            }
            cp_commit();
        }

        // ---- stage1: c1 = x @ W1p_chunk  (per warp m16 x 64, K=128)
        float c1[8][4];
#pragma unroll
        for (int nt = 0; nt < 8; nt++)
#pragma unroll
            for (int q = 0; q < 4; q++) c1[nt][q] = 0.f;

        const uint32_t w1b = (uint32_t)(W1_BASE + (c & 1) * W1_BUF);
        const uint32_t aRowOff = (uint32_t)((wid * 16 + lrow) * S1) * 4;
#pragma unroll
        for (int ks = 0; ks < 8; ks++) {
            const uint32_t ko = (uint32_t)(ks * 8 + lsel) * 4;
            uint32_t ah[4], al[4];
            ldm_x4(ah, sb + aRowOff + ko);
            ldm_x4(al, sb + (uint32_t)(XT_L * 4) + aRowOff + ko);
#pragma unroll
            for (int ng = 0; ng < 4; ng++) {
                uint32_t bb[4];
                const uint32_t ro = (uint32_t)((ng * 16 + lrow) * S1) * 4;
                ldm_x4(bb, sb + w1b * 4 + ro + ko);
#pragma unroll
                for (int sub = 0; sub < 2; sub++) {
                    const int nt = ng * 2 + sub;
                    mma_f16(c1[nt], ah, bb[sub], bb[2 + sub]);
                    mma_f16(c1[nt], al, bb[sub], bb[2 + sub]);
                }
            }
        }

        // ---- bias + relu in registers
#pragma unroll
        for (int nt = 0; nt < 8; nt++) {
            const int colG = c * 64 + nt * 8 + 2 * tig;
            const float b0 = b1p[colG];
            const float b1 = b1p[colG + 1];
            c1[nt][0] = fmaxf(c1[nt][0] + b0, 0.f);
            c1[nt][1] = fmaxf(c1[nt][1] + b1, 0.f);
            c1[nt][2] = fmaxf(c1[nt][2] + b0, 0.f);
            c1[nt][3] = fmaxf(c1[nt][3] + b1, 0.f);
        }

        // ---- stage2: c2 += x2c @ W2p_block (K=64 via 4 k16 steps)
        const uint32_t w2b = (uint32_t)(W2_BASE + (c & 1) * W2_BUF);
#pragma unroll
        for (int ks = 0; ks < 4; ks++) {
            uint32_t ah2[4], al2[4];
            split2h(c1[2 * ks][0],     c1[2 * ks][1],     ah2[0], al2[0]);
            split2h(c1[2 * ks][2],     c1[2 * ks][3],     ah2[1], al2[1]);
            split2h(c1[2 * ks + 1][0], c1[2 * ks + 1][1], ah2[2], al2[2]);
            split2h(c1[2 * ks + 1][2], c1[2 * ks + 1][3], ah2[3], al2[3]);
            const uint32_t ko = (uint32_t)(ks * 8 + lsel) * 4;
#pragma unroll
            for (int ng = 0; ng < 7; ng++) {            // cols 0..111
                uint32_t bb[4];
                const uint32_t ro = (uint32_t)((ng * 16 + lrow) * S2) * 4;
                ldm_x4(bb, sb + w2b * 4 + ro + ko);
#pragma unroll
                for (int sub = 0; sub < 2; sub++) {
                    const int nt = ng * 2 + sub;
                    if (nt > 12) continue;              // cols 104..111 masked
                    mma_f16(c2[nt], ah2, bb[sub], bb[2 + sub]);
                    mma_f16(c2[nt], al2, bb[sub], bb[2 + sub]);
                }
            }
        }
    }

    // ---- epilogue: bias + relu, write logits (compact [NPG][100] per graph)
    const int rL0 = mt128 * 128 + wid * 16 + g;
    const int rL1 = rL0 + 8;
#pragma unroll
    for (int nt = 0; nt < 13; nt++) {
        const int col = nt * 8 + 2 * tig;
        if (col >= KPG) continue;
        const float b0 = b2p[gz * KPG + col];
        const float b1 = b2p[gz * KPG + col + 1];
        if (rL0 < NPG) {
            float v0 = fmaxf(c2[nt][0] + b0, 0.f);
            float v1 = fmaxf(c2[nt][1] + b1, 0.f);
            *(float2*)(g_logits + (size_t)(gz * NPG + rL0) * KPG + col) = make_float2(v0, v1);
        }
        if (rL1 < NPG) {
            float v2 = fmaxf(c2[nt][2] + b0, 0.f);
            float v3 = fmaxf(c2[nt][3] + b1, 0.f);
            *(float2*)(g_logits + (size_t)(gz * NPG + rL1) * KPG + col) = make_float2(v2, v3);
        }
    }
}

// ---------------- tensor-core fp16 2-term GEMM (feat branch) -----------------
// A packed [M][K/2] hi/lo; B single fp16 packed [N][K/2].
static constexpr int AW = 20;               // smem row stride (words)
static constexpr int OFF_AL = 128 * AW;
static constexpr int OFF_B  = 2 * 128 * AW;
static constexpr int STAGEW = 3 * 128 * AW;       // 7680 words
static constexpr int GEMM_SMEM = 3 * STAGEW * 4;  // 92160 B

template<bool OUT_SPLIT>
__global__ __launch_bounds__(256)
void mma_gemm(const uint32_t* __restrict__ Ahg, const uint32_t* __restrict__ Alg,
              const uint32_t* __restrict__ Bg,
              const float* __restrict__ bias,
              float* __restrict__ C, uint32_t* __restrict__ Ch, uint32_t* __restrict__ Cl,
              int M, int N, int K, int ldaw, int ldbw, int ldc, int ldcw) {
    extern __shared__ uint32_t sm2[];
    const uint32_t sbase = smem_u32(sm2);

    const int tid  = threadIdx.x;
    const int wid  = tid >> 5;
    const int lane = tid & 31;
    const int wm   = wid & 3;
    const int wn   = wid >> 2;
    const int g    = lane >> 2;
    const int tig  = lane & 3;
    const int bm   = blockIdx.x * 128;
    const int bn   = blockIdx.y * 128;

    const int am = tid >> 1;
    const int aq = (tid & 1) * 8;
    const int arow = min(bm + am, M - 1);
    const int brow = min(bn + am, N - 1);
    const uint32_t* ApH = Ahg + (size_t)arow * ldaw + aq;
    const uint32_t* ApL = Alg + (size_t)arow * ldaw + aq;
    const uint32_t* Bp  = Bg  + (size_t)brow * ldbw + aq;
    const uint32_t aSm = (uint32_t)(am * AW + aq) * 4;

    const int lrow = (lane < 16) ? lane : (lane - 16);
    const int lsel = (lane >= 16) ? 4 : 0;

    float c[2][8][4];
#pragma unroll
    for (int mt = 0; mt < 2; mt++)
#pragma unroll
        for (int nt = 0; nt < 8; nt++)
#pragma unroll
            for (int q = 0; q < 4; q++) c[mt][nt][q] = 0.f;

    auto issue = [&](int t, int buf) {
        const int kpt = t * 16;
        const uint32_t sa = sbase + (uint32_t)(buf * STAGEW) * 4 + aSm;
        cp16(sa,                    ApH + kpt);
        cp16(sa + 16,               ApH + kpt + 4);
        cp16(sa + OFF_AL * 4,       ApL + kpt);
        cp16(sa + OFF_AL * 4 + 16,  ApL + kpt + 4);
        cp16(sa + OFF_B * 4,        Bp + kpt);
        cp16(sa + OFF_B * 4 + 16,   Bp + kpt + 4);
    };

    const int nT = K >> 5;
    issue(0, 0); cp_commit();
    if (nT > 1) { issue(1, 1); cp_commit(); }

    for (int t = 0; t < nT; t++) {
        if (t + 1 < nT) cp_wait1(); else cp_wait0();
        __syncthreads();

        const int buf = t % 3;
        const uint32_t stage = sbase + (uint32_t)(buf * STAGEW) * 4;
        const uint32_t aBase = stage + (uint32_t)((wm * 32 + lrow) * AW + lsel) * 4;
        const uint32_t bBase = stage + (uint32_t)(OFF_B + (wn * 64 + lrow) * AW + lsel) * 4;

#pragma unroll
        for (int ks = 0; ks < 2; ks++) {
            const uint32_t ko = (uint32_t)(ks * 8) * 4;
            uint32_t ah[2][4], al[2][4];
#pragma unroll
            for (int mt = 0; mt < 2; mt++) {
                const uint32_t ao = aBase + (uint32_t)(mt * 16 * AW) * 4 + ko;
                ldm_x4(ah[mt], ao);
                ldm_x4(al[mt], ao + OFF_AL * 4);
            }
#pragma unroll
            for (int ng = 0; ng < 4; ng++) {
                uint32_t bb[4];
                ldm_x4(bb, bBase + (uint32_t)(ng * 16 * AW) * 4 + ko);
#pragma unroll
                for (int sub = 0; sub < 2; sub++) {
                    const int nt = ng * 2 + sub;
#pragma unroll
                    for (int mt = 0; mt < 2; mt++) {
                        mma_f16(c[mt][nt], ah[mt], bb[sub], bb[2 + sub]);
                        mma_f16(c[mt][nt], al[mt], bb[sub], bb[2 + sub]);
                    }
                }
            }
        }
        if (t + 2 < nT) { issue(t + 2, (t + 2) % 3); cp_commit(); }
    }

#pragma unroll
    for (int mt = 0; mt < 2; mt++) {
        const int r0 = bm + wm * 32 + mt * 16 + g;
        const int r1 = r0 + 8;
#pragma unroll
        for (int nt = 0; nt < 8; nt++) {
            const int col = bn + wn * 64 + nt * 8 + 2 * tig;
            if (col >= N) continue;
            const bool pair = (col + 1 < N);
            const float b0 = bias[col];
            const float b1 = pair ? bias[col + 1] : 0.f;
            float v0 = fmaxf(c[mt][nt][0] + b0, 0.f);
            float v1 = fmaxf(c[mt][nt][1] + b1, 0.f);
            float v2 = fmaxf(c[mt][nt][2] + b0, 0.f);
            float v3 = fmaxf(c[mt][nt][3] + b1, 0.f);
            if (OUT_SPLIT) {
                uint32_t hi, lo;
                if (r0 < M) {
                    split2h(v0, v1, hi, lo);
                    Ch[(size_t)r0 * ldcw + (col >> 1)] = hi;
                    Cl[(size_t)r0 * ldcw + (col >> 1)] = lo;
                }
                if (r1 < M) {
                    split2h(v2, v3, hi, lo);
                    Ch[(size_t)r1 * ldcw + (col >> 1)] = hi;
                    Cl[(size_t)r1 * ldcw + (col >> 1)] = lo;
                }
            } else {
                if (r0 < M) {
                    if (pair) *(float2*)(C + (size_t)r0 * ldc + col) = make_float2(v0, v1);
                    else      C[(size_t)r0 * ldc + col] = v0;
                }
                if (r1 < M) {
                    if (pair) *(float2*)(C + (size_t)r1 * ldc + col) = make_float2(v2, v3);
                    else      C[(size_t)r1 * ldc + col] = v2;
                }
            }
        }
    }
}

// ---------------- per-node softmax over 100 compact logits ------------------
__global__ void softmax_kernel() {
    int node = (blockIdx.x * blockDim.x + threadIdx.x) >> 5;
    int lane = threadIdx.x & 31;
    if (node >= NN) return;
    const float* lp = g_logits + (size_t)node * KPG;
    float v[4];
    float mx = -1e30f;
#pragma unroll
    for (int i = 0; i < 4; i++) {
        int c = lane + 32 * i;
        v[i] = (c < KPG) ? lp[c] : -1e30f;
        mx = fmaxf(mx, v[i]);
    }
#pragma unroll
    for (int o = 16; o; o >>= 1) mx = fmaxf(mx, __shfl_xor_sync(0xFFFFFFFFu, mx, o));
    float sum = 0.f;
#pragma unroll
    for (int i = 0; i < 4; i++) {
        int c = lane + 32 * i;
        v[i] = (c < KPG) ? expf(v[i] - mx) : 0.f;
        sum += v[i];
    }
#pragma unroll
    for (int o = 16; o; o >>= 1) sum += __shfl_xor_sync(0xFFFFFFFFu, sum, o);
    float inv = 1.f / sum;
    float* ap = g_assign + (size_t)node * KPG;
#pragma unroll
    for (int i = 0; i < 4; i++) {
        int c = lane + 32 * i;
        if (c < KPG) ap[c] = v[i] * inv;
    }
}

// ---------------- gather: tmp[n] = sum_{s in N(n)} assign[s] ----------------
__global__ void gather_tmp_kernel() {
    int n = (blockIdx.x * blockDim.x + threadIdx.x) >> 5;
    int lane = threadIdx.x & 31;
    if (n >= NN) return;
    int dg = min(g_degi[n], CAP);
    const int* nb = g_nbr + (size_t)n * CAP;
    float a0 = 0.f, a1 = 0.f, a2 = 0.f, a3 = 0.f;
    for (int j = 0; j < dg; j++) {
        const float* ar = g_assign + (size_t)nb[j] * KPG;
        a0 += ar[lane];
        a1 += ar[lane + 32];
        a2 += ar[lane + 64];
        if (lane < 4) a3 += ar[lane + 96];
    }
    float* tp = g_tmp + (size_t)n * KPG;
    tp[lane]      = a0;
    tp[lane + 32] = a1;
    tp[lane + 64] = a2;
    if (lane < 4) tp[lane + 96] = a3;
}

// ---------------- h_pool: per graph, assign_b^T [2000x100] @ feat_b [2000x128]
__global__ __launch_bounds__(256)
void hpool_kernel(float* __restrict__ out) {   // out = d_out + ADJ_ELEMS
    const int g = blockIdx.y;
    const int split = blockIdx.x;
    const int kbeg = split * (NPG / 8);
    const int kend = kbeg + (NPG / 8);
    const float* A = g_assign + (size_t)g * NPG * KPG;
    const float* F = g_feat + (size_t)g * NPG * DD;

    __shared__ float As[8][KPG];
    __shared__ float Fs[8][DD];
    const int tx = threadIdx.x & 15;
    const int ty = threadIdx.x >> 4;

    float acc[7][8];
#pragma unroll
    for (int i = 0; i < 7; i++)
#pragma unroll
        for (int j = 0; j < 8; j++) acc[i][j] = 0.f;

    for (int k0 = kbeg; k0 < kend; k0 += 8) {
        int kc = min(8, kend - k0);
        for (int idx = threadIdx.x; idx < 8 * KPG; idx += 256) {
            int r = idx / KPG, c = idx % KPG;
            As[r][c] = (r < kc) ? A[(size_t)(k0 + r) * KPG + c] : 0.f;
        }
        for (int idx = threadIdx.x; idx < 8 * DD; idx += 256) {
            int r = idx >> 7, c = idx & 127;
            Fs[r][c] = (r < kc) ? F[(size_t)(k0 + r) * DD + c] : 0.f;
        }
        __syncthreads();
#pragma unroll
        for (int k = 0; k < 8; k++) {
            float a[7], f[8];
#pragma unroll
            for (int i = 0; i < 7; i++) {
                int c = ty + 16 * i;
                a[i] = (c < KPG) ? As[k][c] : 0.f;
            }
#pragma unroll
            for (int j = 0; j < 8; j++) f[j] = Fs[k][tx + 16 * j];
#pragma unroll
            for (int i = 0; i < 7; i++)
#pragma unroll
                for (int j = 0; j < 8; j++) acc[i][j] += a[i] * f[j];
        }
        __syncthreads();
    }
#pragma unroll
    for (int i = 0; i < 7; i++) {
        int c = ty + 16 * i;
        if (c >= KPG) continue;
#pragma unroll
        for (int j = 0; j < 8; j++) {
            int d = tx + 16 * j;
            atomicAdd(&out[(size_t)(g * KPG + c) * DD + d], acc[i][j]);
        }
    }
}

// ---------------- adj: per graph, assign_b^T [2000x100] @ tmp_b [2000x100] --
__global__ __launch_bounds__(256)
void adj_kernel(float* __restrict__ out) {
    const int g = blockIdx.y;
    const int split = blockIdx.x;
    const int kbeg = split * (NPG / 8);
    const int kend = kbeg + (NPG / 8);
    const float* A = g_assign + (size_t)g * NPG * KPG;
    const float* T = g_tmp + (size_t)g * NPG * KPG;

    __shared__ float As[8][KPG];
    __shared__ float Ts[8][KPG];
    const int tx = threadIdx.x & 15;
    const int ty = threadIdx.x >> 4;

    float acc[7][7];
#pragma unroll
    for (int i = 0; i < 7; i++)
#pragma unroll
        for (int j = 0; j < 7; j++) acc[i][j] = 0.f;

    for (int k0 = kbeg; k0 < kend; k0 += 8) {
        int kc = min(8, kend - k0);
        for (int idx = threadIdx.x; idx < 8 * KPG; idx += 256) {
            int r = idx / KPG, c = idx % KPG;
            As[r][c] = (r < kc) ? A[(size_t)(k0 + r) * KPG + c] : 0.f;
            Ts[r][c] = (r < kc) ? T[(size_t)(k0 + r) * KPG + c] : 0.f;
        }
        __syncthreads();
#pragma unroll
        for (int k = 0; k < 8; k++) {
            float a[7], b[7];
#pragma unroll
            for (int i = 0; i < 7; i++) {
                int c = ty + 16 * i;
                a[i] = (c < KPG) ? As[k][c] : 0.f;
            }
#pragma unroll
            for (int j = 0; j < 7; j++) {
                int c = tx + 16 * j;
                b[j] = (c < KPG) ? Ts[k][c] : 0.f;
            }
#pragma unroll
            for (int i = 0; i < 7; i++)
#pragma unroll
                for (int j = 0; j < 7; j++) acc[i][j] += a[i] * b[j];
        }
        __syncthreads();
    }
#pragma unroll
    for (int i = 0; i < 7; i++) {
        int c1 = ty + 16 * i;
        if (c1 >= KPG) continue;
#pragma unroll
        for (int j = 0; j < 7; j++) {
            int c2 = tx + 16 * j;
            if (c2 >= KPG) continue;
            atomicAdd(&out[(size_t)(g * KPG + c1) * KK + (g * KPG + c2)], acc[i][j]);
        }
    }
}

// ---------------- launch ----------------------------------------------------
extern "C" void kernel_launch(void* const* d_in, const int* in_sizes, int n_in,
                              void* d_out, int out_size) {
    const float* h   = (const float*)d_in[0];
    const int*   src = (const int*)d_in[1];
    const int*   dst = (const int*)d_in[2];
    const float* W1f = (const float*)d_in[3];
    const float* b1f = (const float*)d_in[4];
    const float* W2f = (const float*)d_in[5];
    const float* b2f = (const float*)d_in[6];
    const float* W1p = (const float*)d_in[7];
    const float* b1p = (const float*)d_in[8];
    const float* W2p = (const float*)d_in[9];
    const float* b2p = (const float*)d_in[10];
    float* out = (float*)d_out;

    uint32_t *xh, *xl, *t1h, *t1l, *w1f, *w2f, *w1p, *w2p;
    float *feat;
    int* degi;
    cudaGetSymbolAddress((void**)&xh,  g_xh);
    cudaGetSymbolAddress((void**)&xl,  g_xl);
    cudaGetSymbolAddress((void**)&t1h, g_t1h);
    cudaGetSymbolAddress((void**)&t1l, g_t1l);
    cudaGetSymbolAddress((void**)&w1f, g_w1f);
    cudaGetSymbolAddress((void**)&w2f, g_w2f);
    cudaGetSymbolAddress((void**)&w1p, g_w1p);
    cudaGetSymbolAddress((void**)&w2p, g_w2p);
    cudaGetSymbolAddress((void**)&feat, g_feat);
    cudaGetSymbolAddress((void**)&degi, g_degi);

    cudaFuncSetAttribute(mma_gemm<true>,  cudaFuncAttributeMaxDynamicSharedMemorySize, GEMM_SMEM);
    cudaFuncSetAttribute(mma_gemm<false>, cudaFuncAttributeMaxDynamicSharedMemorySize, GEMM_SMEM);
    cudaFuncSetAttribute(fused_pool_kernel, cudaFuncAttributeMaxDynamicSharedMemorySize, FUSED_SMEM);

    // 0-4: prep for fused pool
    zero_i<<<128, 256>>>(degi, (size_t)NN);
    fill_bucket_kernel<<<(EE + 255) / 256, 256>>>(src, dst);
    gather_x_kernel<<<(NN * 32 + 255) / 256, 256>>>(h);
    cvt_BT_kernel<<<((size_t)KK * DD / 2 + 255) / 256, 256>>>(W1p, w1p, DD / 2, KK);
    cvt_BT_kernel<<<((size_t)KK * KK / 2 + 255) / 256, 256>>>(W2p, w2p, KK / 2, KK);

    // 5: fused pool1+pool2 -> logits
    fused_pool_kernel<<<dim3(16, NB), 256, FUSED_SMEM>>>(b1p, b2p);

    // 6-10: output zero + feat branch
    zero_f<<<1024, 256>>>(out, (size_t)out_size);
    cvt_BT_kernel<<<(DD * DD / 2 + 255) / 256, 256>>>(W1f, w1f, DD / 2, DD);
    cvt_BT_kernel<<<(DD * DD / 2 + 255) / 256, 256>>>(W2f, w2f, DD / 2, DD);
    mma_gemm<true><<<dim3(250, 1, 1), 256, GEMM_SMEM>>>(
        xh, xl, w1f, b1f, nullptr, t1h, t1l,
        NN, DD, DD, DD / 2, DD / 2, 0, DD / 2);
    mma_gemm<false><<<dim3(250, 1, 1), 256, GEMM_SMEM>>>(
        t1h, t1l, w2f, b2f, feat, nullptr, nullptr,
        NN, DD, DD, DD / 2, DD / 2, DD, 0);

    // 11-14: softmax, tmp gather, output GEMMs
    softmax_kernel<<<(NN * 32 + 255) / 256, 256>>>();
    gather_tmp_kernel<<<(NN * 32 + 255) / 256, 256>>>();
    hpool_kernel<<<dim3(8, NB), 256>>>(out + ADJ_ELEMS);
    adj_kernel<<<dim3(8, NB), 256>>>(out);
}

// round 12
// speedup vs baseline: 3.1553x; 1.2597x over previous
#include <cuda_runtime.h>
#include <cuda_fp16.h>
#include <math.h>
#include <cstdint>
#include <cstddef>

// Problem constants
static constexpr int NN   = 32000;     // nodes
static constexpr int NB   = 16;        // graphs
static constexpr int NPG  = 2000;      // nodes per graph
static constexpr int KK   = 1600;      // clusters total
static constexpr int KPG  = 100;       // clusters per graph
static constexpr int DD   = 128;       // feature dim
static constexpr int EE   = 512000;    // edges
static constexpr int ADJ_ELEMS = KK * KK;
static constexpr int CAP  = 96;        // neighbor bucket capacity

// ---------------- scratch (__device__ globals) ------------------------------
// activations: packed fp16x2 single precision (A-format: [rows][K/2] words)
__device__ uint32_t g_x16[(size_t)NN * DD / 2];
__device__ uint32_t g_t116[(size_t)NN * DD / 2];
// weights: single fp16 packed, transposed A-format [N][K/2]
__device__ uint32_t g_w1f[DD * DD / 2];
__device__ uint32_t g_w2f[DD * DD / 2];
__device__ uint32_t g_w1p[(size_t)KK * DD / 2];
__device__ uint32_t g_w2p[(size_t)KK * KK / 2];
// fp32 buffers
__device__ float g_feat[(size_t)NN * DD];
__device__ float g_logits[(size_t)NN * KPG];
__device__ float g_assign[(size_t)NN * KPG];
__device__ float g_tmp[(size_t)NN * KPG];
__device__ int   g_degi[NN];
__device__ int   g_nbr[(size_t)NN * CAP];

// ---------------- helpers ----------------------------------------------------
__device__ __forceinline__ uint32_t smem_u32(const void* p) {
    uint32_t a;
    asm("{ .reg .u64 t; cvta.to.shared.u64 t, %1; cvt.u32.u64 %0, t; }" : "=r"(a) : "l"(p));
    return a;
}
__device__ __forceinline__ void cp16(uint32_t saddr, const void* g) {
    asm volatile("cp.async.ca.shared.global [%0], [%1], 16;" :: "r"(saddr), "l"(g) : "memory");
}
__device__ __forceinline__ void cp_commit() {
    asm volatile("cp.async.commit_group;" ::: "memory");
}
__device__ __forceinline__ void cp_wait0() {
    asm volatile("cp.async.wait_group 0;" ::: "memory");
}
__device__ __forceinline__ void cp_wait1() {
    asm volatile("cp.async.wait_group 1;" ::: "memory");
}
__device__ __forceinline__ void ldm_x4(uint32_t* r, uint32_t saddr) {
    asm volatile("ldmatrix.sync.aligned.m8n8.x4.shared.b16 {%0,%1,%2,%3}, [%4];"
                 : "=r"(r[0]), "=r"(r[1]), "=r"(r[2]), "=r"(r[3]) : "r"(saddr));
}
__device__ __forceinline__ void mma_f16(float* c, const uint32_t* a,
                                        uint32_t b0, uint32_t b1) {
    asm volatile(
        "mma.sync.aligned.m16n8k16.row.col.f32.f16.f16.f32 "
        "{%0,%1,%2,%3}, {%4,%5,%6,%7}, {%8,%9}, {%0,%1,%2,%3};"
        : "+f"(c[0]), "+f"(c[1]), "+f"(c[2]), "+f"(c[3])
        : "r"(a[0]), "r"(a[1]), "r"(a[2]), "r"(a[3]), "r"(b0), "r"(b1));
}
__device__ __forceinline__ uint32_t cvt2h(float f0, float f1) {
    __half2 p = __halves2half2(__float2half_rn(f0), __float2half_rn(f1));
    return *reinterpret_cast<uint32_t*>(&p);
}

// ---------------- zero helpers ----------------------------------------------
__global__ void zero_f(float* __restrict__ p, size_t n) {
    size_t i = (size_t)blockIdx.x * blockDim.x + threadIdx.x;
    size_t st = (size_t)gridDim.x * blockDim.x;
    for (; i < n; i += st) p[i] = 0.f;
}
__global__ void zero_i(int* __restrict__ p, size_t n) {
    size_t i = (size_t)blockIdx.x * blockDim.x + threadIdx.x;
    size_t st = (size_t)gridDim.x * blockDim.x;
    for (; i < n; i += st) p[i] = 0;
}

// ---------------- bucket fill: per-dst neighbor lists ------------------------
__global__ void fill_bucket_kernel(const int* __restrict__ src,
                                   const int* __restrict__ dst) {
    int e = blockIdx.x * blockDim.x + threadIdx.x;
    if (e >= EE) return;
    int d = dst[e];
    int p = atomicAdd(&g_degi[d], 1);
    if (p < CAP) g_nbr[(size_t)d * CAP + p] = src[e];
}

// ---------------- weight cvt+transpose: Wt[n][kp] = h2(B[2kp][n], B[2kp+1][n])
__global__ void cvt_BT_kernel(const float* __restrict__ B,
                              uint32_t* __restrict__ Bp, int K2, int N) {
    int idx = blockIdx.x * blockDim.x + threadIdx.x;
    if (idx >= N * K2) return;
    int n = idx / K2, kp = idx - n * K2;
    Bp[idx] = cvt2h(B[(size_t)(2 * kp) * N + n], B[(size_t)(2 * kp + 1) * N + n]);
}

// ---------------- gather: x = h + mean nbr, write packed fp16 ----------------
__global__ void gather_x_kernel(const float* __restrict__ h) {
    int n = (blockIdx.x * blockDim.x + threadIdx.x) >> 5;
    int lane = threadIdx.x & 31;
    if (n >= NN) return;
    int dg = min(g_degi[n], CAP);
    const int* nb = g_nbr + (size_t)n * CAP;
    float a0 = 0.f, a1 = 0.f, a2 = 0.f, a3 = 0.f;
    for (int j = 0; j < dg; j++) {
        float4 v = ((const float4*)(h + (size_t)nb[j] * DD))[lane];
        a0 += v.x; a1 += v.y; a2 += v.z; a3 += v.w;
    }
    float inv = 1.f / fmaxf((float)dg, 1.f);
    float4 hn = ((const float4*)(h + (size_t)n * DD))[lane];
    size_t base = (size_t)n * (DD / 2) + lane * 2;
    g_x16[base]     = cvt2h(hn.x + a0 * inv, hn.y + a1 * inv);
    g_x16[base + 1] = cvt2h(hn.z + a2 * inv, hn.w + a3 * inv);
}

// ================= FUSED pool1+pool2 (register x2, single fp16) ==============
static constexpr int CW  = 64;            // chunk width
static constexpr int NCH = KK / CW;       // 25
static constexpr int S1  = 68;            // stride for 64-word rows
static constexpr int S2  = 36;            // stride for 32-word rows
static constexpr int XT_0    = 0;                      // 128*S1 = 8704 words
static constexpr int W1_BASE = 128 * S1;               // 8704
static constexpr int W1_BUF  = 64 * S1;                // 4352
static constexpr int W2_BASE = W1_BASE + 2 * W1_BUF;   // 17408
static constexpr int W2_BUF  = 128 * S2;               // 4608
static constexpr int FUSED_W    = W2_BASE + 2 * W2_BUF;  // 26624 words
static constexpr int FUSED_SMEM = FUSED_W * 4;           // 106496 B (2 CTAs/SM)

__global__ __launch_bounds__(256, 2)
void fused_pool_kernel(const float* __restrict__ b1p, const float* __restrict__ b2p) {
    extern __shared__ uint32_t sm[];
    const uint32_t sb = smem_u32(sm);
    const int mt128 = blockIdx.x;       // m-tile within graph (0..15)
    const int gz    = blockIdx.y;       // graph
    const int tid = threadIdx.x, wid = tid >> 5, lane = tid & 31;
    const int g = lane >> 2, tig = lane & 3;
    const int lrow = (lane < 16) ? lane : (lane - 16);
    const int lsel = (lane >= 16) ? 4 : 0;

    // ---- prologue: X tile + W1[0] + W2[0], one group
#pragma unroll
    for (int i = 0; i < 8; i++) {
        int q = tid + i * 256;                 // 0..2047
        int row = q >> 4, w = (q & 15) * 4;
        int grow = gz * NPG + min(mt128 * 128 + row, NPG - 1);
        cp16(sb + (uint32_t)(XT_0 + row * S1 + w) * 4, g_x16 + (size_t)grow * 64 + w);
    }
#pragma unroll
    for (int i = 0; i < 4; i++) {
        int q = tid + i * 256;                 // 0..1023
        int row = q >> 4, w = (q & 15) * 4;
        cp16(sb + (uint32_t)(W1_BASE + row * S1 + w) * 4, g_w1p + (size_t)row * 64 + w);
    }
#pragma unroll
    for (int i = 0; i < 4; i++) {
        int q = tid + i * 256;
        if (q < 800) {
            int row = q >> 3, w = (q & 7) * 4;
            cp16(sb + (uint32_t)(W2_BASE + row * S2 + w) * 4,
                 g_w2p + (size_t)(gz * 100 + row) * 800 + w);
        }
    }
    cp_commit();

    float c2[13][4];
#pragma unroll
    for (int nt = 0; nt < 13; nt++)
#pragma unroll
        for (int q = 0; q < 4; q++) c2[nt][q] = 0.f;

    for (int c = 0; c < NCH; c++) {
        cp_wait0();
        __syncthreads();      // chunk data arrived; all warps done with alt bufs

        // ---- prefetch next chunk into alternate buffers
        if (c + 1 < NCH) {
            const int nb = (c + 1) & 1;
#pragma unroll
            for (int i = 0; i < 4; i++) {
                int q = tid + i * 256;
                int row = q >> 4, w = (q & 15) * 4;
                cp16(sb + (uint32_t)(W1_BASE + nb * W1_BUF + row * S1 + w) * 4,
                     g_w1p + (size_t)((c + 1) * 64 + row) * 64 + w);
            }
#pragma unroll
            for (int i = 0; i < 4; i++) {
                int q = tid + i * 256;
                if (q < 800) {
                    int row = q >> 3, w = (q & 7) * 4;
                    cp16(sb + (uint32_t)(W2_BASE + nb * W2_BUF + row * S2 + w) * 4,
                         g_w2p + (size_t)(gz * 100 + row) * 800 + (c + 1) * 32 + w);
                }
            }
            cp_commit();
        }

        // ---- stage1: c1 = x @ W1p_chunk  (per warp m16 x 64, K=128)
        float c1[8][4];
#pragma unroll
        for (int nt = 0; nt < 8; nt++)
#pragma unroll
            for (int q = 0; q < 4; q++) c1[nt][q] = 0.f;

        const uint32_t w1b = (uint32_t)(W1_BASE + (c & 1) * W1_BUF);
        const uint32_t aRowOff = (uint32_t)((wid * 16 + lrow) * S1) * 4;
#pragma unroll
        for (int ks = 0; ks < 8; ks++) {
            const uint32_t ko = (uint32_t)(ks * 8 + lsel) * 4;
            uint32_t aa[4];
            ldm_x4(aa, sb + aRowOff + ko);
#pragma unroll
            for (int ng = 0; ng < 4; ng++) {
                uint32_t bb[4];
                const uint32_t ro = (uint32_t)((ng * 16 + lrow) * S1) * 4;
                ldm_x4(bb, sb + w1b * 4 + ro + ko);
#pragma unroll
                for (int sub = 0; sub < 2; sub++)
                    mma_f16(c1[ng * 2 + sub], aa, bb[sub], bb[2 + sub]);
            }
        }

        // ---- bias + relu in registers
#pragma unroll
        for (int nt = 0; nt < 8; nt++) {
            const int colG = c * 64 + nt * 8 + 2 * tig;
            const float b0 = b1p[colG];
            const float b1 = b1p[colG + 1];
            c1[nt][0] = fmaxf(c1[nt][0] + b0, 0.f);
            c1[nt][1] = fmaxf(c1[nt][1] + b1, 0.f);
            c1[nt][2] = fmaxf(c1[nt][2] + b0, 0.f);
            c1[nt][3] = fmaxf(c1[nt][3] + b1, 0.f);
        }

        // ---- stage2: c2 += x2c @ W2p_block (K=64 via 4 k16 steps)
        const uint32_t w2b = (uint32_t)(W2_BASE + (c & 1) * W2_BUF);
#pragma unroll
        for (int ks = 0; ks < 4; ks++) {
            uint32_t a2[4];
            a2[0] = cvt2h(c1[2 * ks][0],     c1[2 * ks][1]);
            a2[1] = cvt2h(c1[2 * ks][2],     c1[2 * ks][3]);
            a2[2] = cvt2h(c1[2 * ks + 1][0], c1[2 * ks + 1][1]);
            a2[3] = cvt2h(c1[2 * ks + 1][2], c1[2 * ks + 1][3]);
            const uint32_t ko = (uint32_t)(ks * 8 + lsel) * 4;
#pragma unroll
            for (int ng = 0; ng < 7; ng++) {            // cols 0..111
                uint32_t bb[4];
                const uint32_t ro = (uint32_t)((ng * 16 + lrow) * S2) * 4;
                ldm_x4(bb, sb + w2b * 4 + ro + ko);
#pragma unroll
                for (int sub = 0; sub < 2; sub++) {
                    const int nt = ng * 2 + sub;
                    if (nt > 12) continue;              // cols 104..111 masked
                    mma_f16(c2[nt], a2, bb[sub], bb[2 + sub]);
                }
            }
        }
    }

    // ---- epilogue: bias + relu, write logits (compact [NPG][100] per graph)
    const int rL0 = mt128 * 128 + wid * 16 + g;
    const int rL1 = rL0 + 8;
#pragma unroll
    for (int nt = 0; nt < 13; nt++) {
        const int col = nt * 8 + 2 * tig;
        if (col >= KPG) continue;
        const float b0 = b2p[gz * KPG + col];
        const float b1 = b2p[gz * KPG + col + 1];
        if (rL0 < NPG) {
            float v0 = fmaxf(c2[nt][0] + b0, 0.f);
            float v1 = fmaxf(c2[nt][1] + b1, 0.f);
            *(float2*)(g_logits + (size_t)(gz * NPG + rL0) * KPG + col) = make_float2(v0, v1);
        }
        if (rL1 < NPG) {
            float v2 = fmaxf(c2[nt][2] + b0, 0.f);
            float v3 = fmaxf(c2[nt][3] + b1, 0.f);
            *(float2*)(g_logits + (size_t)(gz * NPG + rL1) * KPG + col) = make_float2(v2, v3);
        }
    }
}

// ---------------- tensor-core fp16 GEMM (feat branch) ------------------------
// A packed fp16 [M][K/2]; B packed fp16 [N][K/2].
static constexpr int AW = 20;               // smem row stride (words)
static constexpr int OFF_B  = 128 * AW;
static constexpr int STAGEW = 2 * 128 * AW;       // 5120 words
static constexpr int GEMM_SMEM = 3 * STAGEW * 4;  // 61440 B

template<bool OUT_FP16>
__global__ __launch_bounds__(256)
void mma_gemm(const uint32_t* __restrict__ Ag, const uint32_t* __restrict__ Bg,
              const float* __restrict__ bias,
              float* __restrict__ C, uint32_t* __restrict__ C16,
              int M, int N, int K, int ldaw, int ldbw, int ldc, int ldcw) {
    extern __shared__ uint32_t sm2[];
    const uint32_t sbase = smem_u32(sm2);

    const int tid  = threadIdx.x;
    const int wid  = tid >> 5;
    const int lane = tid & 31;
    const int wm   = wid & 3;
    const int wn   = wid >> 2;
    const int g    = lane >> 2;
    const int tig  = lane & 3;
    const int bm   = blockIdx.x * 128;
    const int bn   = blockIdx.y * 128;

    const int am = tid >> 1;
    const int aq = (tid & 1) * 8;
    const int arow = min(bm + am, M - 1);
    const int brow = min(bn + am, N - 1);
    const uint32_t* Ap = Ag + (size_t)arow * ldaw + aq;
    const uint32_t* Bp = Bg + (size_t)brow * ldbw + aq;
    const uint32_t aSm = (uint32_t)(am * AW + aq) * 4;

    const int lrow = (lane < 16) ? lane : (lane - 16);
    const int lsel = (lane >= 16) ? 4 : 0;

    float c[2][8][4];
#pragma unroll
    for (int mt = 0; mt < 2; mt++)
#pragma unroll
        for (int nt = 0; nt < 8; nt++)
#pragma unroll
            for (int q = 0; q < 4; q++) c[mt][nt][q] = 0.f;

    auto issue = [&](int t, int buf) {
        const int kpt = t * 16;
        const uint32_t sa = sbase + (uint32_t)(buf * STAGEW) * 4 + aSm;
        cp16(sa,                  Ap + kpt);
        cp16(sa + 16,             Ap + kpt + 4);
        cp16(sa + OFF_B * 4,      Bp + kpt);
        cp16(sa + OFF_B * 4 + 16, Bp + kpt + 4);
    };

    const int nT = K >> 5;
    issue(0, 0); cp_commit();
    if (nT > 1) { issue(1, 1); cp_commit(); }

    for (int t = 0; t < nT; t++) {
        if (t + 1 < nT) cp_wait1(); else cp_wait0();
        __syncthreads();

        const int buf = t % 3;
        const uint32_t stage = sbase + (uint32_t)(buf * STAGEW) * 4;
        const uint32_t aBase = stage + (uint32_t)((wm * 32 + lrow) * AW + lsel) * 4;
        const uint32_t bBase = stage + (uint32_t)(OFF_B + (wn * 64 + lrow) * AW + lsel) * 4;

#pragma unroll
        for (int ks = 0; ks < 2; ks++) {
            const uint32_t ko = (uint32_t)(ks * 8) * 4;
            uint32_t aa[2][4];
#pragma unroll
            for (int mt = 0; mt < 2; mt++)
                ldm_x4(aa[mt], aBase + (uint32_t)(mt * 16 * AW) * 4 + ko);
#pragma unroll
            for (int ng = 0; ng < 4; ng++) {
                uint32_t bb[4];
                ldm_x4(bb, bBase + (uint32_t)(ng * 16 * AW) * 4 + ko);
#pragma unroll
                for (int sub = 0; sub < 2; sub++) {
                    const int nt = ng * 2 + sub;
#pragma unroll
                    for (int mt = 0; mt < 2; mt++)
                        mma_f16(c[mt][nt], aa[mt], bb[sub], bb[2 + sub]);
                }
            }
        }
        if (t + 2 < nT) { issue(t + 2, (t + 2) % 3); cp_commit(); }
    }

#pragma unroll
    for (int mt = 0; mt < 2; mt++) {
        const int r0 = bm + wm * 32 + mt * 16 + g;
        const int r1 = r0 + 8;
#pragma unroll
        for (int nt = 0; nt < 8; nt++) {
            const int col = bn + wn * 64 + nt * 8 + 2 * tig;
            if (col >= N) continue;
            const bool pair = (col + 1 < N);
            const float b0 = bias[col];
            const float b1 = pair ? bias[col + 1] : 0.f;
            float v0 = fmaxf(c[mt][nt][0] + b0, 0.f);
            float v1 = fmaxf(c[mt][nt][1] + b1, 0.f);
            float v2 = fmaxf(c[mt][nt][2] + b0, 0.f);
            float v3 = fmaxf(c[mt][nt][3] + b1, 0.f);
            if (OUT_FP16) {
                if (r0 < M) C16[(size_t)r0 * ldcw + (col >> 1)] = cvt2h(v0, v1);
                if (r1 < M) C16[(size_t)r1 * ldcw + (col >> 1)] = cvt2h(v2, v3);
            } else {
                if (r0 < M) {
                    if (pair) *(float2*)(C + (size_t)r0 * ldc + col) = make_float2(v0, v1);
                    else      C[(size_t)r0 * ldc + col] = v0;
                }
                if (r1 < M) {
                    if (pair) *(float2*)(C + (size_t)r1 * ldc + col) = make_float2(v2, v3);
                    else      C[(size_t)r1 * ldc + col] = v2;
                }
            }
        }
    }
}

// ---------------- per-node softmax over 100 compact logits ------------------
__global__ void softmax_kernel() {
    int node = (blockIdx.x * blockDim.x + threadIdx.x) >> 5;
    int lane = threadIdx.x & 31;
    if (node >= NN) return;
    const float* lp = g_logits + (size_t)node * KPG;
    float v[4];
    float mx = -1e30f;
#pragma unroll
    for (int i = 0; i < 4; i++) {
        int c = lane + 32 * i;
        v[i] = (c < KPG) ? lp[c] : -1e30f;
        mx = fmaxf(mx, v[i]);
    }
#pragma unroll
    for (int o = 16; o; o >>= 1) mx = fmaxf(mx, __shfl_xor_sync(0xFFFFFFFFu, mx, o));
    float sum = 0.f;
#pragma unroll
    for (int i = 0; i < 4; i++) {
        int c = lane + 32 * i;
        v[i] = (c < KPG) ? expf(v[i] - mx) : 0.f;
        sum += v[i];
    }
#pragma unroll
    for (int o = 16; o; o >>= 1) sum += __shfl_xor_sync(0xFFFFFFFFu, sum, o);
    float inv = 1.f / sum;
    float* ap = g_assign + (size_t)node * KPG;
#pragma unroll
    for (int i = 0; i < 4; i++) {
        int c = lane + 32 * i;
        if (c < KPG) ap[c] = v[i] * inv;
    }
}

// ---------------- gather: tmp[n] = sum_{s in N(n)} assign[s] ----------------
__global__ void gather_tmp_kernel() {
    int n = (blockIdx.x * blockDim.x + threadIdx.x) >> 5;
    int lane = threadIdx.x & 31;
    if (n >= NN) return;
    int dg = min(g_degi[n], CAP);
    const int* nb = g_nbr + (size_t)n * CAP;
    float a0 = 0.f, a1 = 0.f, a2 = 0.f, a3 = 0.f;
    for (int j = 0; j < dg; j++) {
        const float* ar = g_assign + (size_t)nb[j] * KPG;
        a0 += ar[lane];
        a1 += ar[lane + 32];
        a2 += ar[lane + 64];
        if (lane < 4) a3 += ar[lane + 96];
    }
    float* tp = g_tmp + (size_t)n * KPG;
    tp[lane]      = a0;
    tp[lane + 32] = a1;
    tp[lane + 64] = a2;
    if (lane < 4) tp[lane + 96] = a3;
}

// ---------------- h_pool: per graph, assign_b^T [2000x100] @ feat_b [2000x128]
__global__ __launch_bounds__(256)
void hpool_kernel(float* __restrict__ out) {   // out = d_out + ADJ_ELEMS
    const int g = blockIdx.y;
    const int split = blockIdx.x;
    const int kbeg = split * (NPG / 8);
    const int kend = kbeg + (NPG / 8);
    const float* A = g_assign + (size_t)g * NPG * KPG;
    const float* F = g_feat + (size_t)g * NPG * DD;

    __shared__ float As[8][KPG];
    __shared__ float Fs[8][DD];
    const int tx = threadIdx.x & 15;
    const int ty = threadIdx.x >> 4;

    float acc[7][8];
#pragma unroll
    for (int i = 0; i < 7; i++)
#pragma unroll
        for (int j = 0; j < 8; j++) acc[i][j] = 0.f;

    for (int k0 = kbeg; k0 < kend; k0 += 8) {
        int kc = min(8, kend - k0);
        for (int idx = threadIdx.x; idx < 8 * KPG; idx += 256) {
            int r = idx / KPG, c = idx % KPG;
            As[r][c] = (r < kc) ? A[(size_t)(k0 + r) * KPG + c] : 0.f;
        }
        for (int idx = threadIdx.x; idx < 8 * DD; idx += 256) {
            int r = idx >> 7, c = idx & 127;
            Fs[r][c] = (r < kc) ? F[(size_t)(k0 + r) * DD + c] : 0.f;
        }
        __syncthreads();
#pragma unroll
        for (int k = 0; k < 8; k++) {
            float a[7], f[8];
#pragma unroll
            for (int i = 0; i < 7; i++) {
                int c = ty + 16 * i;
                a[i] = (c < KPG) ? As[k][c] : 0.f;
            }
#pragma unroll
            for (int j = 0; j < 8; j++) f[j] = Fs[k][tx + 16 * j];
#pragma unroll
            for (int i = 0; i < 7; i++)
#pragma unroll
                for (int j = 0; j < 8; j++) acc[i][j] += a[i] * f[j];
        }
        __syncthreads();
    }
#pragma unroll
    for (int i = 0; i < 7; i++) {
        int c = ty + 16 * i;
        if (c >= KPG) continue;
#pragma unroll
        for (int j = 0; j < 8; j++) {
            int d = tx + 16 * j;
            atomicAdd(&out[(size_t)(g * KPG + c) * DD + d], acc[i][j]);
        }
    }
}

// ---------------- adj: per graph, assign_b^T [2000x100] @ tmp_b [2000x100] --
__global__ __launch_bounds__(256)
void adj_kernel(float* __restrict__ out) {
    const int g = blockIdx.y;
    const int split = blockIdx.x;
    const int kbeg = split * (NPG / 8);
    const int kend = kbeg + (NPG / 8);
    const float* A = g_assign + (size_t)g * NPG * KPG;
    const float* T = g_tmp + (size_t)g * NPG * KPG;

    __shared__ float As[8][KPG];
    __shared__ float Ts[8][KPG];
    const int tx = threadIdx.x & 15;
    const int ty = threadIdx.x >> 4;

    float acc[7][7];
#pragma unroll
    for (int i = 0; i < 7; i++)
#pragma unroll
        for (int j = 0; j < 7; j++) acc[i][j] = 0.f;

    for (int k0 = kbeg; k0 < kend; k0 += 8) {
        int kc = min(8, kend - k0);
        for (int idx = threadIdx.x; idx < 8 * KPG; idx += 256) {
            int r = idx / KPG, c = idx % KPG;
            As[r][c] = (r < kc) ? A[(size_t)(k0 + r) * KPG + c] : 0.f;
            Ts[r][c] = (r < kc) ? T[(size_t)(k0 + r) * KPG + c] : 0.f;
        }
        __syncthreads();
#pragma unroll
        for (int k = 0; k < 8; k++) {
            float a[7], b[7];
#pragma unroll
            for (int i = 0; i < 7; i++) {
                int c = ty + 16 * i;
                a[i] = (c < KPG) ? As[k][c] : 0.f;
            }
#pragma unroll
            for (int j = 0; j < 7; j++) {
                int c = tx + 16 * j;
                b[j] = (c < KPG) ? Ts[k][c] : 0.f;
            }
#pragma unroll
            for (int i = 0; i < 7; i++)
#pragma unroll
                for (int j = 0; j < 7; j++) acc[i][j] += a[i] * b[j];
        }
        __syncthreads();
    }
#pragma unroll
    for (int i = 0; i < 7; i++) {
        int c1 = ty + 16 * i;
        if (c1 >= KPG) continue;
#pragma unroll
        for (int j = 0; j < 7; j++) {
            int c2 = tx + 16 * j;
            if (c2 >= KPG) continue;
            atomicAdd(&out[(size_t)(g * KPG + c1) * KK + (g * KPG + c2)], acc[i][j]);
        }
    }
}

// ---------------- launch ----------------------------------------------------
extern "C" void kernel_launch(void* const* d_in, const int* in_sizes, int n_in,
                              void* d_out, int out_size) {
    const float* h   = (const float*)d_in[0];
    const int*   src = (const int*)d_in[1];
    const int*   dst = (const int*)d_in[2];
    const float* W1f = (const float*)d_in[3];
    const float* b1f = (const float*)d_in[4];
    const float* W2f = (const float*)d_in[5];
    const float* b2f = (const float*)d_in[6];
    const float* W1p = (const float*)d_in[7];
    const float* b1p = (const float*)d_in[8];
    const float* W2p = (const float*)d_in[9];
    const float* b2p = (const float*)d_in[10];
    float* out = (float*)d_out;

    uint32_t *x16, *t116, *w1f, *w2f, *w1p, *w2p;
    float *feat;
    int* degi;
    cudaGetSymbolAddress((void**)&x16,  g_x16);
    cudaGetSymbolAddress((void**)&t116, g_t116);
    cudaGetSymbolAddress((void**)&w1f,  g_w1f);
    cudaGetSymbolAddress((void**)&w2f,  g_w2f);
    cudaGetSymbolAddress((void**)&w1p,  g_w1p);
    cudaGetSymbolAddress((void**)&w2p,  g_w2p);
    cudaGetSymbolAddress((void**)&feat, g_feat);
    cudaGetSymbolAddress((void**)&degi, g_degi);

    cudaFuncSetAttribute(mma_gemm<true>,  cudaFuncAttributeMaxDynamicSharedMemorySize, GEMM_SMEM);
    cudaFuncSetAttribute(mma_gemm<false>, cudaFuncAttributeMaxDynamicSharedMemorySize, GEMM_SMEM);
    cudaFuncSetAttribute(fused_pool_kernel, cudaFuncAttributeMaxDynamicSharedMemorySize, FUSED_SMEM);

    // 0-4: prep for fused pool
    zero_i<<<128, 256>>>(degi, (size_t)NN);
    fill_bucket_kernel<<<(EE + 255) / 256, 256>>>(src, dst);
    gather_x_kernel<<<(NN * 32 + 255) / 256, 256>>>(h);
    cvt_BT_kernel<<<((size_t)KK * DD / 2 + 255) / 256, 256>>>(W1p, w1p, DD / 2, KK);
    cvt_BT_kernel<<<((size_t)KK * KK / 2 + 255) / 256, 256>>>(W2p, w2p, KK / 2, KK);

    // 5: fused pool1+pool2 -> logits
    fused_pool_kernel<<<dim3(16, NB), 256, FUSED_SMEM>>>(b1p, b2p);

    // 6-10: output zero + feat branch
    zero_f<<<1024, 256>>>(out, (size_t)out_size);
    cvt_BT_kernel<<<(DD * DD / 2 + 255) / 256, 256>>>(W1f, w1f, DD / 2, DD);
    cvt_BT_kernel<<<(DD * DD / 2 + 255) / 256, 256>>>(W2f, w2f, DD / 2, DD);
    mma_gemm<true><<<dim3(250, 1, 1), 256, GEMM_SMEM>>>(
        x16, w1f, b1f, nullptr, t116,
        NN, DD, DD, DD / 2, DD / 2, 0, DD / 2);
    mma_gemm<false><<<dim3(250, 1, 1), 256, GEMM_SMEM>>>(
        t116, w2f, b2f, feat, nullptr,
        NN, DD, DD, DD / 2, DD / 2, DD, 0);

    // 11-14: softmax, tmp gather, output GEMMs
    softmax_kernel<<<(NN * 32 + 255) / 256, 256>>>();
    gather_tmp_kernel<<<(NN * 32 + 255) / 256, 256>>>();
    hpool_kernel<<<dim3(8, NB), 256>>>(out + ADJ_ELEMS);
    adj_kernel<<<dim3(8, NB), 256>>>(out);
}

// round 13
// speedup vs baseline: 3.7573x; 1.1908x over previous
#include <cuda_runtime.h>
#include <cuda_fp16.h>
#include <math.h>
#include <cstdint>
#include <cstddef>

// Problem constants
static constexpr int NN   = 32000;     // nodes
static constexpr int NB   = 16;        // graphs
static constexpr int NPG  = 2000;      // nodes per graph
static constexpr int KK   = 1600;      // clusters total
static constexpr int KPG  = 100;       // clusters per graph
static constexpr int DD   = 128;       // feature dim
static constexpr int EE   = 512000;    // edges
static constexpr int ADJ_ELEMS = KK * KK;
static constexpr int CAP  = 96;        // neighbor bucket capacity

// ---------------- scratch (__device__ globals) ------------------------------
__device__ uint32_t g_x16[(size_t)NN * DD / 2];      // packed fp16 activations
__device__ uint32_t g_w1f[DD * DD / 2];              // weights, [N][K/2] fp16
__device__ uint32_t g_w2f[DD * DD / 2];
__device__ uint32_t g_w1p[(size_t)KK * DD / 2];
__device__ uint32_t g_w2p[(size_t)KK * KK / 2];
__device__ float g_feat[(size_t)NN * DD];
__device__ float g_assign[(size_t)NN * KPG];
__device__ float g_tmp[(size_t)NN * KPG];
__device__ int   g_degi[NN];
__device__ int   g_nbr[(size_t)NN * CAP];

// ---------------- helpers ----------------------------------------------------
__device__ __forceinline__ uint32_t smem_u32(const void* p) {
    uint32_t a;
    asm("{ .reg .u64 t; cvta.to.shared.u64 t, %1; cvt.u32.u64 %0, t; }" : "=r"(a) : "l"(p));
    return a;
}
__device__ __forceinline__ void cp16(uint32_t saddr, const void* g) {
    asm volatile("cp.async.ca.shared.global [%0], [%1], 16;" :: "r"(saddr), "l"(g) : "memory");
}
__device__ __forceinline__ void cp_commit() {
    asm volatile("cp.async.commit_group;" ::: "memory");
}
__device__ __forceinline__ void cp_wait0() {
    asm volatile("cp.async.wait_group 0;" ::: "memory");
}
__device__ __forceinline__ void ldm_x4(uint32_t* r, uint32_t saddr) {
    asm volatile("ldmatrix.sync.aligned.m8n8.x4.shared.b16 {%0,%1,%2,%3}, [%4];"
                 : "=r"(r[0]), "=r"(r[1]), "=r"(r[2]), "=r"(r[3]) : "r"(saddr));
}
__device__ __forceinline__ void mma_f16(float* c, const uint32_t* a,
                                        uint32_t b0, uint32_t b1) {
    asm volatile(
        "mma.sync.aligned.m16n8k16.row.col.f32.f16.f16.f32 "
        "{%0,%1,%2,%3}, {%4,%5,%6,%7}, {%8,%9}, {%0,%1,%2,%3};"
        : "+f"(c[0]), "+f"(c[1]), "+f"(c[2]), "+f"(c[3])
        : "r"(a[0]), "r"(a[1]), "r"(a[2]), "r"(a[3]), "r"(b0), "r"(b1));
}
__device__ __forceinline__ uint32_t cvt2h(float f0, float f1) {
    __half2 p = __halves2half2(__float2half_rn(f0), __float2half_rn(f1));
    return *reinterpret_cast<uint32_t*>(&p);
}

// ---------------- zero helpers ----------------------------------------------
__global__ void zero_f(float* __restrict__ p, size_t n) {
    size_t i = (size_t)blockIdx.x * blockDim.x + threadIdx.x;
    size_t st = (size_t)gridDim.x * blockDim.x;
    for (; i < n; i += st) p[i] = 0.f;
}
__global__ void zero_i(int* __restrict__ p, size_t n) {
    size_t i = (size_t)blockIdx.x * blockDim.x + threadIdx.x;
    size_t st = (size_t)gridDim.x * blockDim.x;
    for (; i < n; i += st) p[i] = 0;
}

// ---------------- bucket fill: per-dst neighbor lists ------------------------
__global__ void fill_bucket_kernel(const int* __restrict__ src,
                                   const int* __restrict__ dst) {
    int e = blockIdx.x * blockDim.x + threadIdx.x;
    if (e >= EE) return;
    int d = dst[e];
    int p = atomicAdd(&g_degi[d], 1);
    if (p < CAP) g_nbr[(size_t)d * CAP + p] = src[e];
}

// ---------------- weight cvt+transpose: Wt[n][kp] = h2(B[2kp][n], B[2kp+1][n])
__global__ void cvt_BT_kernel(const float* __restrict__ B,
                              uint32_t* __restrict__ Bp, int K2, int N) {
    int idx = blockIdx.x * blockDim.x + threadIdx.x;
    if (idx >= N * K2) return;
    int n = idx / K2, kp = idx - n * K2;
    Bp[idx] = cvt2h(B[(size_t)(2 * kp) * N + n], B[(size_t)(2 * kp + 1) * N + n]);
}

// ---------------- gather: x = h + mean nbr, write packed fp16 ----------------
__global__ void gather_x_kernel(const float* __restrict__ h) {
    int n = (blockIdx.x * blockDim.x + threadIdx.x) >> 5;
    int lane = threadIdx.x & 31;
    if (n >= NN) return;
    int dg = min(g_degi[n], CAP);
    const int* nb = g_nbr + (size_t)n * CAP;
    float a0 = 0.f, a1 = 0.f, a2 = 0.f, a3 = 0.f;
    for (int j = 0; j < dg; j++) {
        float4 v = ((const float4*)(h + (size_t)nb[j] * DD))[lane];
        a0 += v.x; a1 += v.y; a2 += v.z; a3 += v.w;
    }
    float inv = 1.f / fmaxf((float)dg, 1.f);
    float4 hn = ((const float4*)(h + (size_t)n * DD))[lane];
    size_t base = (size_t)n * (DD / 2) + lane * 2;
    g_x16[base]     = cvt2h(hn.x + a0 * inv, hn.y + a1 * inv);
    g_x16[base + 1] = cvt2h(hn.z + a2 * inv, hn.w + a3 * inv);
}

// ================= FUSED pool1+pool2+softmax =================================
static constexpr int NCH = KK / 64;       // 25 chunks
static constexpr int S1  = 68;
static constexpr int S2  = 36;
static constexpr int XT_0    = 0;                      // 128*S1 words
static constexpr int W1_BASE = 128 * S1;               // 8704
static constexpr int W1_BUF  = 64 * S1;                // 4352
static constexpr int W2_BASE = W1_BASE + 2 * W1_BUF;   // 17408
static constexpr int W2_BUF  = 128 * S2;               // 4608
static constexpr int FUSED_W    = W2_BASE + 2 * W2_BUF;  // 26624 words
static constexpr int FUSED_SMEM = FUSED_W * 4;           // 106496 B

__global__ __launch_bounds__(256, 2)
void fused_pool_kernel(const float* __restrict__ b1p, const float* __restrict__ b2p) {
    extern __shared__ uint32_t sm[];
    const uint32_t sb = smem_u32(sm);
    const int mt128 = blockIdx.x;       // m-tile within graph (0..15)
    const int gz    = blockIdx.y;       // graph
    const int tid = threadIdx.x, wid = tid >> 5, lane = tid & 31;
    const int g = lane >> 2, tig = lane & 3;
    const int lrow = (lane < 16) ? lane : (lane - 16);
    const int lsel = (lane >= 16) ? 4 : 0;

    // ---- prologue: X tile + W1[0] + W2[0], one group
#pragma unroll
    for (int i = 0; i < 8; i++) {
        int q = tid + i * 256;
        int row = q >> 4, w = (q & 15) * 4;
        int grow = gz * NPG + min(mt128 * 128 + row, NPG - 1);
        cp16(sb + (uint32_t)(XT_0 + row * S1 + w) * 4, g_x16 + (size_t)grow * 64 + w);
    }
#pragma unroll
    for (int i = 0; i < 4; i++) {
        int q = tid + i * 256;
        int row = q >> 4, w = (q & 15) * 4;
        cp16(sb + (uint32_t)(W1_BASE + row * S1 + w) * 4, g_w1p + (size_t)row * 64 + w);
    }
#pragma unroll
    for (int i = 0; i < 4; i++) {
        int q = tid + i * 256;
        if (q < 800) {
            int row = q >> 3, w = (q & 7) * 4;
            cp16(sb + (uint32_t)(W2_BASE + row * S2 + w) * 4,
                 g_w2p + (size_t)(gz * 100 + row) * 800 + w);
        }
    }
    cp_commit();

    float c2[13][4];
#pragma unroll
    for (int nt = 0; nt < 13; nt++)
#pragma unroll
        for (int q = 0; q < 4; q++) c2[nt][q] = 0.f;

    for (int c = 0; c < NCH; c++) {
        cp_wait0();
        __syncthreads();

        if (c + 1 < NCH) {
            const int nb = (c + 1) & 1;
#pragma unroll
            for (int i = 0; i < 4; i++) {
                int q = tid + i * 256;
                int row = q >> 4, w = (q & 15) * 4;
                cp16(sb + (uint32_t)(W1_BASE + nb * W1_BUF + row * S1 + w) * 4,
                     g_w1p + (size_t)((c + 1) * 64 + row) * 64 + w);
            }
#pragma unroll
            for (int i = 0; i < 4; i++) {
                int q = tid + i * 256;
                if (q < 800) {
                    int row = q >> 3, w = (q & 7) * 4;
                    cp16(sb + (uint32_t)(W2_BASE + nb * W2_BUF + row * S2 + w) * 4,
                         g_w2p + (size_t)(gz * 100 + row) * 800 + (c + 1) * 32 + w);
                }
            }
            cp_commit();
        }

        // ---- stage1
        float c1[8][4];
#pragma unroll
        for (int nt = 0; nt < 8; nt++)
#pragma unroll
            for (int q = 0; q < 4; q++) c1[nt][q] = 0.f;

        const uint32_t w1b = (uint32_t)(W1_BASE + (c & 1) * W1_BUF);
        const uint32_t aRowOff = (uint32_t)((wid * 16 + lrow) * S1) * 4;
#pragma unroll
        for (int ks = 0; ks < 8; ks++) {
            const uint32_t ko = (uint32_t)(ks * 8 + lsel) * 4;
            uint32_t aa[4];
            ldm_x4(aa, sb + aRowOff + ko);
#pragma unroll
            for (int ng = 0; ng < 4; ng++) {
                uint32_t bb[4];
                const uint32_t ro = (uint32_t)((ng * 16 + lrow) * S1) * 4;
                ldm_x4(bb, sb + w1b * 4 + ro + ko);
#pragma unroll
                for (int sub = 0; sub < 2; sub++)
                    mma_f16(c1[ng * 2 + sub], aa, bb[sub], bb[2 + sub]);
            }
        }

        // ---- bias + relu
#pragma unroll
        for (int nt = 0; nt < 8; nt++) {
            const int colG = c * 64 + nt * 8 + 2 * tig;
            const float b0 = b1p[colG];
            const float b1 = b1p[colG + 1];
            c1[nt][0] = fmaxf(c1[nt][0] + b0, 0.f);
            c1[nt][1] = fmaxf(c1[nt][1] + b1, 0.f);
            c1[nt][2] = fmaxf(c1[nt][2] + b0, 0.f);
            c1[nt][3] = fmaxf(c1[nt][3] + b1, 0.f);
        }

        // ---- stage2
        const uint32_t w2b = (uint32_t)(W2_BASE + (c & 1) * W2_BUF);
#pragma unroll
        for (int ks = 0; ks < 4; ks++) {
            uint32_t a2[4];
            a2[0] = cvt2h(c1[2 * ks][0],     c1[2 * ks][1]);
            a2[1] = cvt2h(c1[2 * ks][2],     c1[2 * ks][3]);
            a2[2] = cvt2h(c1[2 * ks + 1][0], c1[2 * ks + 1][1]);
            a2[3] = cvt2h(c1[2 * ks + 1][2], c1[2 * ks + 1][3]);
            const uint32_t ko = (uint32_t)(ks * 8 + lsel) * 4;
#pragma unroll
            for (int ng = 0; ng < 7; ng++) {
                uint32_t bb[4];
                const uint32_t ro = (uint32_t)((ng * 16 + lrow) * S2) * 4;
                ldm_x4(bb, sb + w2b * 4 + ro + ko);
#pragma unroll
                for (int sub = 0; sub < 2; sub++) {
                    const int nt = ng * 2 + sub;
                    if (nt > 12) continue;
                    mma_f16(c2[nt], a2, bb[sub], bb[2 + sub]);
                }
            }
        }
    }

    // ---- fused epilogue: bias + relu + SOFTMAX (rows rL0, rL1), write assign
    const int rL0 = mt128 * 128 + wid * 16 + g;
    const int rL1 = rL0 + 8;
    float e[13][4];
    float mx0 = -1e30f, mx1 = -1e30f;
#pragma unroll
    for (int nt = 0; nt < 13; nt++) {
        const int col = nt * 8 + 2 * tig;
        if (col < KPG) {
            const float b0 = b2p[gz * KPG + col];
            const float b1 = b2p[gz * KPG + col + 1];
            e[nt][0] = fmaxf(c2[nt][0] + b0, 0.f);
            e[nt][1] = fmaxf(c2[nt][1] + b1, 0.f);
            e[nt][2] = fmaxf(c2[nt][2] + b0, 0.f);
            e[nt][3] = fmaxf(c2[nt][3] + b1, 0.f);
            mx0 = fmaxf(mx0, fmaxf(e[nt][0], e[nt][1]));
            mx1 = fmaxf(mx1, fmaxf(e[nt][2], e[nt][3]));
        } else {
            e[nt][0] = e[nt][1] = e[nt][2] = e[nt][3] = -1e30f;
        }
    }
    mx0 = fmaxf(mx0, __shfl_xor_sync(0xFFFFFFFFu, mx0, 1));
    mx0 = fmaxf(mx0, __shfl_xor_sync(0xFFFFFFFFu, mx0, 2));
    mx1 = fmaxf(mx1, __shfl_xor_sync(0xFFFFFFFFu, mx1, 1));
    mx1 = fmaxf(mx1, __shfl_xor_sync(0xFFFFFFFFu, mx1, 2));
    float s0 = 0.f, s1 = 0.f;
#pragma unroll
    for (int nt = 0; nt < 13; nt++) {
        e[nt][0] = expf(e[nt][0] - mx0);
        e[nt][1] = expf(e[nt][1] - mx0);
        e[nt][2] = expf(e[nt][2] - mx1);
        e[nt][3] = expf(e[nt][3] - mx1);
        const int col = nt * 8 + 2 * tig;
        if (col < KPG) { s0 += e[nt][0] + e[nt][1]; s1 += e[nt][2] + e[nt][3]; }
    }
    s0 += __shfl_xor_sync(0xFFFFFFFFu, s0, 1);
    s0 += __shfl_xor_sync(0xFFFFFFFFu, s0, 2);
    s1 += __shfl_xor_sync(0xFFFFFFFFu, s1, 1);
    s1 += __shfl_xor_sync(0xFFFFFFFFu, s1, 2);
    const float inv0 = 1.f / (s0 + 1e-13f);
    const float inv1 = 1.f / (s1 + 1e-13f);
#pragma unroll
    for (int nt = 0; nt < 13; nt++) {
        const int col = nt * 8 + 2 * tig;
        if (col >= KPG) continue;
        if (rL0 < NPG)
            *(float2*)(g_assign + (size_t)(gz * NPG + rL0) * KPG + col) =
                make_float2(e[nt][0] * inv0, e[nt][1] * inv0);
        if (rL1 < NPG)
            *(float2*)(g_assign + (size_t)(gz * NPG + rL1) * KPG + col) =
                make_float2(e[nt][2] * inv1, e[nt][3] * inv1);
    }
}

// ================= FUSED feat branch (both layers, t1 in registers) ==========
static constexpr int FS  = 68;
static constexpr int FX  = 0;
static constexpr int FW1 = 128 * FS;        // 8704
static constexpr int FW2 = 2 * 128 * FS;    // 17408
static constexpr int FEAT_SMEM = 3 * 128 * FS * 4;   // 104448 B

__global__ __launch_bounds__(256, 2)
void feat_fused_kernel(const float* __restrict__ b1f, const float* __restrict__ b2f) {
    extern __shared__ uint32_t smf[];
    const uint32_t sb = smem_u32(smf);
    const int bm = blockIdx.x * 128;
    const int tid = threadIdx.x, wid = tid >> 5, lane = tid & 31;
    const int g = lane >> 2, tig = lane & 3;
    const int lrow = (lane < 16) ? lane : (lane - 16);
    const int lsel = (lane >= 16) ? 4 : 0;

    // ---- prologue: X tile + both weight tiles
#pragma unroll
    for (int i = 0; i < 8; i++) {
        int q = tid + i * 256;
        int row = q >> 4, w = (q & 15) * 4;
        cp16(sb + (uint32_t)(FX + row * FS + w) * 4,  g_x16 + (size_t)(bm + row) * 64 + w);
        cp16(sb + (uint32_t)(FW1 + row * FS + w) * 4, g_w1f + (size_t)row * 64 + w);
        cp16(sb + (uint32_t)(FW2 + row * FS + w) * 4, g_w2f + (size_t)row * 64 + w);
    }
    cp_commit();
    cp_wait0();
    __syncthreads();

    // ---- stage1: t1 = relu(x @ W1f + b1f)  (per warp m16 x 128, K=128)
    float c1[16][4];
#pragma unroll
    for (int nt = 0; nt < 16; nt++)
#pragma unroll
        for (int q = 0; q < 4; q++) c1[nt][q] = 0.f;

    const uint32_t aRowOff = (uint32_t)((wid * 16 + lrow) * FS) * 4;
#pragma unroll
    for (int ks = 0; ks < 8; ks++) {
        const uint32_t ko = (uint32_t)(ks * 8 + lsel) * 4;
        uint32_t aa[4];
        ldm_x4(aa, sb + aRowOff + ko);
#pragma unroll
        for (int ng = 0; ng < 8; ng++) {
            uint32_t bb[4];
            ldm_x4(bb, sb + (uint32_t)(FW1 * 4) + (uint32_t)((ng * 16 + lrow) * FS) * 4 + ko);
#pragma unroll
            for (int sub = 0; sub < 2; sub++)
                mma_f16(c1[ng * 2 + sub], aa, bb[sub], bb[2 + sub]);
        }
    }
#pragma unroll
    for (int nt = 0; nt < 16; nt++) {
        const int col = nt * 8 + 2 * tig;
        const float b0 = b1f[col];
        const float b1 = b1f[col + 1];
        c1[nt][0] = fmaxf(c1[nt][0] + b0, 0.f);
        c1[nt][1] = fmaxf(c1[nt][1] + b1, 0.f);
        c1[nt][2] = fmaxf(c1[nt][2] + b0, 0.f);
        c1[nt][3] = fmaxf(c1[nt][3] + b1, 0.f);
    }
    // pack t1 C-fragments directly as stage-2 A-fragments
    uint32_t a2[8][4];
#pragma unroll
    for (int ks = 0; ks < 8; ks++) {
        a2[ks][0] = cvt2h(c1[2 * ks][0],     c1[2 * ks][1]);
        a2[ks][1] = cvt2h(c1[2 * ks][2],     c1[2 * ks][3]);
        a2[ks][2] = cvt2h(c1[2 * ks + 1][0], c1[2 * ks + 1][1]);
        a2[ks][3] = cvt2h(c1[2 * ks + 1][2], c1[2 * ks + 1][3]);
    }

    // ---- stage2: feat = relu(t1 @ W2f + b2f)
    float c2[16][4];
#pragma unroll
    for (int nt = 0; nt < 16; nt++)
#pragma unroll
        for (int q = 0; q < 4; q++) c2[nt][q] = 0.f;
#pragma unroll
    for (int ks = 0; ks < 8; ks++) {
        const uint32_t ko = (uint32_t)(ks * 8 + lsel) * 4;
#pragma unroll
        for (int ng = 0; ng < 8; ng++) {
            uint32_t bb[4];
            ldm_x4(bb, sb + (uint32_t)(FW2 * 4) + (uint32_t)((ng * 16 + lrow) * FS) * 4 + ko);
#pragma unroll
            for (int sub = 0; sub < 2; sub++)
                mma_f16(c2[ng * 2 + sub], a2[ks], bb[sub], bb[2 + sub]);
        }
    }

    // ---- epilogue
    const int r0 = bm + wid * 16 + g;
    const int r1 = r0 + 8;
#pragma unroll
    for (int nt = 0; nt < 16; nt++) {
        const int col = nt * 8 + 2 * tig;
        const float b0 = b2f[col];
        const float b1 = b2f[col + 1];
        *(float2*)(g_feat + (size_t)r0 * DD + col) =
            make_float2(fmaxf(c2[nt][0] + b0, 0.f), fmaxf(c2[nt][1] + b1, 0.f));
        *(float2*)(g_feat + (size_t)r1 * DD + col) =
            make_float2(fmaxf(c2[nt][2] + b0, 0.f), fmaxf(c2[nt][3] + b1, 0.f));
    }
}

// ---------------- gather: tmp[n] = sum_{s in N(n)} assign[s] ----------------
__global__ void gather_tmp_kernel() {
    int n = (blockIdx.x * blockDim.x + threadIdx.x) >> 5;
    int lane = threadIdx.x & 31;
    if (n >= NN) return;
    int dg = min(g_degi[n], CAP);
    const int* nb = g_nbr + (size_t)n * CAP;
    float a0 = 0.f, a1 = 0.f, a2 = 0.f, a3 = 0.f;
    for (int j = 0; j < dg; j++) {
        const float* ar = g_assign + (size_t)nb[j] * KPG;
        a0 += ar[lane];
        a1 += ar[lane + 32];
        a2 += ar[lane + 64];
        if (lane < 4) a3 += ar[lane + 96];
    }
    float* tp = g_tmp + (size_t)n * KPG;
    tp[lane]      = a0;
    tp[lane + 32] = a1;
    tp[lane + 64] = a2;
    if (lane < 4) tp[lane + 96] = a3;
}

// ---------------- merged hpool + adj: share assign tiles --------------------
__global__ __launch_bounds__(256)
void hpool_adj_kernel(float* __restrict__ out) {
    const int g = blockIdx.y;
    const int split = blockIdx.x;          // 8 splits
    const int kbeg = split * (NPG / 8);
    const int kend = kbeg + (NPG / 8);
    const float* A = g_assign + (size_t)g * NPG * KPG;
    const float* T = g_tmp + (size_t)g * NPG * KPG;
    const float* F = g_feat + (size_t)g * NPG * DD;
    float* outAdj = out;
    float* outHp  = out + ADJ_ELEMS;

    __shared__ float As[8][KPG];
    __shared__ float Ts[8][KPG];
    __shared__ float Fs[8][DD];
    const int tx = threadIdx.x & 15;
    const int ty = threadIdx.x >> 4;

    float accH[7][8];
    float accA[7][7];
#pragma unroll
    for (int i = 0; i < 7; i++) {
#pragma unroll
        for (int j = 0; j < 8; j++) accH[i][j] = 0.f;
#pragma unroll
        for (int j = 0; j < 7; j++) accA[i][j] = 0.f;
    }

    for (int k0 = kbeg; k0 < kend; k0 += 8) {
        int kc = min(8, kend - k0);
        for (int idx = threadIdx.x; idx < 8 * KPG; idx += 256) {
            int r = idx / KPG, c = idx % KPG;
            As[r][c] = (r < kc) ? A[(size_t)(k0 + r) * KPG + c] : 0.f;
            Ts[r][c] = (r < kc) ? T[(size_t)(k0 + r) * KPG + c] : 0.f;
        }
        for (int idx = threadIdx.x; idx < 8 * DD; idx += 256) {
            int r = idx >> 7, c = idx & 127;
            Fs[r][c] = (r < kc) ? F[(size_t)(k0 + r) * DD + c] : 0.f;
        }
        __syncthreads();
#pragma unroll
        for (int k = 0; k < 8; k++) {
            float a[7], f[8], b[7];
#pragma unroll
            for (int i = 0; i < 7; i++) {
                int c = ty + 16 * i;
                a[i] = (c < KPG) ? As[k][c] : 0.f;
            }
#pragma unroll
            for (int j = 0; j < 8; j++) f[j] = Fs[k][tx + 16 * j];
#pragma unroll
            for (int j = 0; j < 7; j++) {
                int c = tx + 16 * j;
                b[j] = (c < KPG) ? Ts[k][c] : 0.f;
            }
#pragma unroll
            for (int i = 0; i < 7; i++) {
#pragma unroll
                for (int j = 0; j < 8; j++) accH[i][j] += a[i] * f[j];
#pragma unroll
                for (int j = 0; j < 7; j++) accA[i][j] += a[i] * b[j];
            }
        }
        __syncthreads();
    }
#pragma unroll
    for (int i = 0; i < 7; i++) {
        int c1 = ty + 16 * i;
        if (c1 >= KPG) continue;
#pragma unroll
        for (int j = 0; j < 8; j++) {
            int d = tx + 16 * j;
            atomicAdd(&outHp[(size_t)(g * KPG + c1) * DD + d], accH[i][j]);
        }
#pragma unroll
        for (int j = 0; j < 7; j++) {
            int c2 = tx + 16 * j;
            if (c2 >= KPG) continue;
            atomicAdd(&outAdj[(size_t)(g * KPG + c1) * KK + (g * KPG + c2)], accA[i][j]);
        }
    }
}

// ---------------- launch ----------------------------------------------------
extern "C" void kernel_launch(void* const* d_in, const int* in_sizes, int n_in,
                              void* d_out, int out_size) {
    const float* h   = (const float*)d_in[0];
    const int*   src = (const int*)d_in[1];
    const int*   dst = (const int*)d_in[2];
    const float* W1f = (const float*)d_in[3];
    const float* b1f = (const float*)d_in[4];
    const float* W2f = (const float*)d_in[5];
    const float* b2f = (const float*)d_in[6];
    const float* W1p = (const float*)d_in[7];
    const float* b1p = (const float*)d_in[8];
    const float* W2p = (const float*)d_in[9];
    const float* b2p = (const float*)d_in[10];
    float* out = (float*)d_out;

    uint32_t *w1f, *w2f, *w1p, *w2p;
    int* degi;
    cudaGetSymbolAddress((void**)&w1f,  g_w1f);
    cudaGetSymbolAddress((void**)&w2f,  g_w2f);
    cudaGetSymbolAddress((void**)&w1p,  g_w1p);
    cudaGetSymbolAddress((void**)&w2p,  g_w2p);
    cudaGetSymbolAddress((void**)&degi, g_degi);

    cudaFuncSetAttribute(fused_pool_kernel, cudaFuncAttributeMaxDynamicSharedMemorySize, FUSED_SMEM);
    cudaFuncSetAttribute(feat_fused_kernel, cudaFuncAttributeMaxDynamicSharedMemorySize, FEAT_SMEM);

    // prep
    zero_i<<<128, 256>>>(degi, (size_t)NN);
    fill_bucket_kernel<<<(EE + 255) / 256, 256>>>(src, dst);
    gather_x_kernel<<<(NN * 32 + 255) / 256, 256>>>(h);
    cvt_BT_kernel<<<((size_t)KK * DD / 2 + 255) / 256, 256>>>(W1p, w1p, DD / 2, KK);
    cvt_BT_kernel<<<((size_t)KK * KK / 2 + 255) / 256, 256>>>(W2p, w2p, KK / 2, KK);

    // fused pool1+pool2+softmax -> assign
    fused_pool_kernel<<<dim3(16, NB), 256, FUSED_SMEM>>>(b1p, b2p);

    // feat branch (both layers fused)
    zero_f<<<1024, 256>>>(out, (size_t)out_size);
    cvt_BT_kernel<<<(DD * DD / 2 + 255) / 256, 256>>>(W1f, w1f, DD / 2, DD);
    cvt_BT_kernel<<<(DD * DD / 2 + 255) / 256, 256>>>(W2f, w2f, DD / 2, DD);
    feat_fused_kernel<<<250, 256, FEAT_SMEM>>>(b1f, b2f);

    // tmp gather, merged output GEMMs
    gather_tmp_kernel<<<(NN * 32 + 255) / 256, 256>>>();
    hpool_adj_kernel<<<dim3(8, NB), 256>>>(out);
}